// round 1
// baseline (speedup 1.0000x reference)
#include <cuda_runtime.h>

#define E_NUM   100000
#define N_NODES 40000
#define R_NUM   400
#define RH      200     // R/2 = number of used edge types / segments
#define DIN     200
#define NH      4       // 2*NHEADS
#define CAP     1024
#define SPLIT   4

// ---------------- device scratch (no allocs allowed) ----------------
__device__ float  g_u[NH][DIN];
__device__ float  g_v[NH][DIN];
__device__ float  g_t[NH][RH];
__device__ float4 g_s[N_NODES];          // s[n][h], h=0..3
__device__ int    g_count[RH];
__device__ int    g_offs[RH + 1];
__device__ int    g_cursor[RH];
__device__ int2   g_edges[E_NUM];        // sorted by type: (src, tail)
__device__ float  g_agg[NH][RH][DIN];    // sum(ex * emb)/denom per head/relation
__device__ float  g_relrep[R_NUM * 400];

// ---------------- helpers ----------------
__device__ __forceinline__ float lrelu(float x) { return x >= 0.f ? x : 0.2f * x; }
__device__ __forceinline__ float elu(float x)   { return x > 0.f ? x : expm1f(x); }

__device__ __forceinline__ float warp_sum(float v) {
    #pragma unroll
    for (int o = 16; o; o >>= 1) v += __shfl_down_sync(0xffffffffu, v, o);
    return v;
}

__device__ __forceinline__ void fma2(unsigned long long &d, unsigned long long a,
                                     unsigned long long b) {
    asm("fma.rn.f32x2 %0, %1, %2, %0;" : "+l"(d) : "l"(a), "l"(b));
}
__device__ __forceinline__ unsigned long long dup2(float x) {
    unsigned long long r;
    asm("mov.b64 %0, {%1, %1};" : "=l"(r) : "f"(x));
    return r;
}
__device__ __forceinline__ float2 unpk(unsigned long long v) {
    float2 f;
    asm("mov.b64 {%0, %1}, %2;" : "=f"(f.x), "=f"(f.y) : "l"(v));
    return f;
}

// ---------------- kernels ----------------

// zero g_agg and g_count each launch (graph replay!)
__global__ void k_zero() {
    int i = blockIdx.x * 256 + threadIdx.x;
    if (i < NH * RH * DIN) ((float*)g_agg)[i] = 0.f;
    if (i < RH) g_count[i] = 0;
}

// u[h] = W_src[h] @ a_vec[h,:200] ; v[h] = W_dst[h] @ a_vec[h,200:]
__global__ void k_uv(const float* __restrict__ Wsrc, const float* __restrict__ Wdst,
                     const float* __restrict__ avec) {
    int w = blockIdx.x * 8 + (threadIdx.x >> 5);   // 1600 warps
    int lane = threadIdx.x & 31;
    int side = w / 800;            // 0: u (src), 1: v (dst)
    int h = (w / 200) % 4;
    int i = w % 200;
    const float* W = (side == 0 ? Wsrc : Wdst) + h * DIN * DIN + i * DIN;
    const float* a = avec + h * 400 + side * 200;
    float acc = 0.f;
    for (int j = lane; j < DIN; j += 32) acc += W[j] * a[j];
    acc = warp_sum(acc);
    if (lane == 0) {
        if (side == 0) g_u[h][i] = acc; else g_v[h][i] = acc;
    }
}

// t[h][r] = relation_emb[r + (h<2 ? RH : 0)] . v[h],  r < RH
__global__ void k_t(const float* __restrict__ rel) {
    int w = blockIdx.x * 8 + (threadIdx.x >> 5);   // 800 warps
    int lane = threadIdx.x & 31;
    int h = w / RH;
    int r = w % RH;
    const float* row = rel + (r + (h < 2 ? RH : 0)) * DIN;
    float acc = 0.f;
    for (int j = lane; j < DIN; j += 32) acc += row[j] * g_v[h][j];
    acc = warp_sum(acc);
    if (lane == 0) g_t[h][r] = acc;
}

// s[n][h] = emb[n] . u[h]
__global__ void k_s(const float* __restrict__ emb) {
    __shared__ float su[NH][DIN];
    for (int i = threadIdx.x; i < NH * DIN; i += 256)
        ((float*)su)[i] = ((const float*)g_u)[i];
    __syncthreads();
    int n = blockIdx.x * 8 + (threadIdx.x >> 5);
    int lane = threadIdx.x & 31;
    const float* row = emb + (long)n * DIN;
    float a0 = 0.f, a1 = 0.f, a2 = 0.f, a3 = 0.f;
    for (int j = lane; j < DIN; j += 32) {
        float x = row[j];
        a0 += x * su[0][j]; a1 += x * su[1][j];
        a2 += x * su[2][j]; a3 += x * su[3][j];
    }
    a0 = warp_sum(a0); a1 = warp_sum(a1); a2 = warp_sum(a2); a3 = warp_sum(a3);
    if (lane == 0) g_s[n] = make_float4(a0, a1, a2, a3);
}

__global__ void k_hist(const int* __restrict__ etype) {
    __shared__ int hh[RH];
    for (int i = threadIdx.x; i < RH; i += 256) hh[i] = 0;
    __syncthreads();
    int base = blockIdx.x * 1024;
    for (int i = threadIdx.x; i < 1024; i += 256) {
        int e = base + i;
        if (e < E_NUM) atomicAdd(&hh[etype[e]], 1);
    }
    __syncthreads();
    for (int i = threadIdx.x; i < RH; i += 256)
        if (hh[i]) atomicAdd(&g_count[i], hh[i]);
}

__global__ void k_scan() {
    __shared__ int sc[256];
    int t = threadIdx.x;
    int c = (t < RH) ? g_count[t] : 0;
    sc[t] = c;
    __syncthreads();
    for (int o = 1; o < 256; o <<= 1) {
        int v = (t >= o) ? sc[t - o] : 0;
        __syncthreads();
        sc[t] += v;
        __syncthreads();
    }
    if (t < RH) {
        int excl = sc[t] - c;
        g_offs[t] = excl;
        g_cursor[t] = excl;
        if (t == RH - 1) g_offs[RH] = sc[t];
    }
}

__global__ void k_scatter(const int* __restrict__ el, const int* __restrict__ etype) {
    int e = blockIdx.x * 256 + threadIdx.x;
    if (e >= E_NUM) return;
    int p = atomicAdd(&g_cursor[etype[e]], 1);
    g_edges[p] = make_int2(el[e], el[E_NUM + e]);
}

// per-segment softmax + weighted aggregation of raw embeddings
__global__ void k_seg(const float* __restrict__ emb) {
    __shared__ float4 sw[CAP];
    __shared__ int2   sed[CAP];
    __shared__ float4 red[256];
    int r = blockIdx.x;
    int t = threadIdx.x;
    int start = g_offs[r], end = g_offs[r + 1];
    int cnt = end - start;
    if (cnt == 0) return;
    float4 tr = make_float4(g_t[0][r], g_t[1][r], g_t[2][r], g_t[3][r]);

    for (int i = t; i < cnt && i < CAP; i += 256) sed[i] = g_edges[start + i];
    __syncthreads();

    // pass 1: per-head max
    float4 mx = make_float4(-1e30f, -1e30f, -1e30f, -1e30f);
    for (int i = t; i < cnt; i += 256) {
        int2 ed = (i < CAP) ? sed[i] : g_edges[start + i];
        float4 ss = g_s[ed.x], st = g_s[ed.y];
        mx.x = fmaxf(mx.x, lrelu(ss.x + tr.x));
        mx.y = fmaxf(mx.y, lrelu(ss.y + tr.y));
        mx.z = fmaxf(mx.z, lrelu(st.z + tr.z));
        mx.w = fmaxf(mx.w, lrelu(st.w + tr.w));
    }
    red[t] = mx; __syncthreads();
    for (int s = 128; s > 0; s >>= 1) {
        if (t < s) {
            float4 o = red[t + s];
            red[t].x = fmaxf(red[t].x, o.x); red[t].y = fmaxf(red[t].y, o.y);
            red[t].z = fmaxf(red[t].z, o.z); red[t].w = fmaxf(red[t].w, o.w);
        }
        __syncthreads();
    }
    float4 m = red[0]; __syncthreads();

    // pass 2: denominators, cache exp weights
    float4 sm = make_float4(0.f, 0.f, 0.f, 0.f);
    for (int i = t; i < cnt; i += 256) {
        int2 ed = (i < CAP) ? sed[i] : g_edges[start + i];
        float4 ss = g_s[ed.x], st = g_s[ed.y];
        float4 ex;
        ex.x = expf(lrelu(ss.x + tr.x) - m.x);
        ex.y = expf(lrelu(ss.y + tr.y) - m.y);
        ex.z = expf(lrelu(st.z + tr.z) - m.z);
        ex.w = expf(lrelu(st.w + tr.w) - m.w);
        if (i < CAP) sw[i] = ex;
        sm.x += ex.x; sm.y += ex.y; sm.z += ex.z; sm.w += ex.w;
    }
    red[t] = sm; __syncthreads();
    for (int s = 128; s > 0; s >>= 1) {
        if (t < s) {
            float4 o = red[t + s];
            red[t].x += o.x; red[t].y += o.y; red[t].z += o.z; red[t].w += o.w;
        }
        __syncthreads();
    }
    float4 dn = red[0];
    float4 sc = make_float4(1.f / (dn.x + 1e-16f), 1.f / (dn.y + 1e-16f),
                            1.f / (dn.z + 1e-16f), 1.f / (dn.w + 1e-16f));
    __syncthreads();

    // pass 3: this CTA's slice of edges, thread t owns dim t (t < DIN)
    int chunk = (cnt + SPLIT - 1) / SPLIT;
    int lo = blockIdx.y * chunk;
    int hi = min(lo + chunk, cnt);
    bool act = (t < DIN);
    float a0 = 0.f, a1 = 0.f, a2 = 0.f, a3 = 0.f;
    if (hi <= CAP) {
        #pragma unroll 4
        for (int i = lo; i < hi; i++) {
            float4 w = sw[i];
            int2 ed = sed[i];
            if (act) {
                float x = emb[(long)ed.x * DIN + t];
                float y = emb[(long)ed.y * DIN + t];
                a0 += w.x * x; a1 += w.y * x; a2 += w.z * y; a3 += w.w * y;
            }
        }
    } else {
        for (int i = lo; i < hi; i++) {
            float4 w;
            int2 ed;
            if (i < CAP) { w = sw[i]; ed = sed[i]; }
            else {
                ed = g_edges[start + i];
                float4 ss = g_s[ed.x], st = g_s[ed.y];
                w.x = expf(lrelu(ss.x + tr.x) - m.x);
                w.y = expf(lrelu(ss.y + tr.y) - m.y);
                w.z = expf(lrelu(st.z + tr.z) - m.z);
                w.w = expf(lrelu(st.w + tr.w) - m.w);
            }
            if (act) {
                float x = emb[(long)ed.x * DIN + t];
                float y = emb[(long)ed.y * DIN + t];
                a0 += w.x * x; a1 += w.y * x; a2 += w.z * y; a3 += w.w * y;
            }
        }
    }
    if (act) {
        atomicAdd(&g_agg[0][r][t], a0 * sc.x);
        atomicAdd(&g_agg[1][r][t], a1 * sc.y);
        atomicAdd(&g_agg[2][r][t], a2 * sc.z);
        atomicAdd(&g_agg[3][r][t], a3 * sc.w);
    }
}

// rel_rep[r][h*200+j] = elu(agg[h][r] @ Wsrc[h][:,j]) + elu(agg[h+2][r] @ Wsrc[h+2][:,j])
__global__ void k_relrep(const float* __restrict__ Wsrc) {
    int r = blockIdx.x;
    int t = threadIdx.x;
    if (r >= RH) {
        for (int o = t; o < 400; o += 256) g_relrep[r * 400 + o] = 0.f;
        return;
    }
    __shared__ float sa[NH][DIN];
    for (int i = t; i < NH * DIN; i += 256) {
        int h = i / DIN, k = i % DIN;
        sa[h][k] = g_agg[h][r][k];
    }
    __syncthreads();
    for (int o = t; o < 400; o += 256) {
        int h = o / DIN, j = o % DIN;
        const float* W1 = Wsrc + h * (DIN * DIN) + j;
        const float* W2 = Wsrc + (h + 2) * (DIN * DIN) + j;
        float d1 = 0.f, d2 = 0.f;
        #pragma unroll 4
        for (int k = 0; k < DIN; k++) {
            d1 += sa[h][k] * W1[k * DIN];
            d2 += sa[h + 2][k] * W2[k * DIN];
        }
        g_relrep[r * 400 + o] = elu(d1) + elu(d2);
    }
}

// rel_final = [rel_rep | relation_emb] @ w_rel ; 4 rows per CTA, 400 threads = cols
__global__ void k_relfinal(const float* __restrict__ rel, const float* __restrict__ wrel,
                           float* __restrict__ out_rel) {
    __shared__ float sin_[4][600];
    int r0 = blockIdx.x * 4;
    int t = threadIdx.x;
    for (int i = t; i < 4 * 600; i += 400) {
        int rr = i / 600, k = i % 600;
        sin_[rr][k] = (k < 400) ? g_relrep[(r0 + rr) * 400 + k]
                                : rel[(r0 + rr) * DIN + (k - 400)];
    }
    __syncthreads();
    float acc0 = 0.f, acc1 = 0.f, acc2 = 0.f, acc3 = 0.f;
    #pragma unroll 4
    for (int k = 0; k < 600; k++) {
        float w = wrel[k * 400 + t];
        acc0 += sin_[0][k] * w; acc1 += sin_[1][k] * w;
        acc2 += sin_[2][k] * w; acc3 += sin_[3][k] * w;
    }
    out_rel[(r0 + 0) * 400 + t] = acc0;
    out_rel[(r0 + 1) * 400 + t] = acc1;
    out_rel[(r0 + 2) * 400 + t] = acc2;
    out_rel[(r0 + 3) * 400 + t] = acc3;
}

// ent = entity_emb @ W_rel_proj  [40000,200]@[200,400], fp32 with fma.rn.f32x2
// BM=128, BN=64, BK=40, thread tile 8(M)x4(N), 256 threads
__global__ __launch_bounds__(256) void k_ent(const float* __restrict__ A,
                                             const float* __restrict__ B,
                                             float* __restrict__ C) {
    __shared__ float As[40][132];   // [k][m], padded stride
    __shared__ float Bs[40][64];    // [k][n]
    const int bm = blockIdx.y * 128;
    const int bn = blockIdx.x * 64;
    const int tid = threadIdx.x;
    const int tx = tid & 15;        // N dir
    const int ty = tid >> 4;        // M dir
    unsigned long long acc[4][4];   // [row-pair][col], packed (row 2p, 2p+1)
    #pragma unroll
    for (int p = 0; p < 4; p++)
        #pragma unroll
        for (int c = 0; c < 4; c++) acc[p][c] = 0ull;

    for (int kc = 0; kc < 200; kc += 40) {
        // load A tile: 128x40 = 1280 float4, 5 per thread
        #pragma unroll
        for (int i = 0; i < 5; i++) {
            int idx = tid + i * 256;
            int m = idx / 10;
            int k4 = (idx % 10) * 4;
            int gm_ = bm + m;
            float4 v = make_float4(0.f, 0.f, 0.f, 0.f);
            if (gm_ < N_NODES)
                v = *(const float4*)&A[(long)gm_ * 200 + kc + k4];
            As[k4 + 0][m] = v.x; As[k4 + 1][m] = v.y;
            As[k4 + 2][m] = v.z; As[k4 + 3][m] = v.w;
        }
        // load B tile: 40x64 = 1280 float2, 5 per thread
        #pragma unroll
        for (int i = 0; i < 5; i++) {
            int idx = tid + i * 256;
            int k = idx / 32;
            int c = (idx & 31) * 2;
            int gc = bn + c;
            float2 v = make_float2(0.f, 0.f);
            if (gc < 400) v = *(const float2*)&B[(kc + k) * 400 + gc];
            Bs[k][c] = v.x; Bs[k][c + 1] = v.y;
        }
        __syncthreads();
        #pragma unroll
        for (int k = 0; k < 40; k++) {
            ulonglong2 av0 = *(const ulonglong2*)&As[k][ty * 8];
            ulonglong2 av1 = *(const ulonglong2*)&As[k][ty * 8 + 4];
            float4 bv = *(const float4*)&Bs[k][tx * 4];
            unsigned long long b0 = dup2(bv.x), b1 = dup2(bv.y);
            unsigned long long b2 = dup2(bv.z), b3 = dup2(bv.w);
            fma2(acc[0][0], av0.x, b0); fma2(acc[0][1], av0.x, b1);
            fma2(acc[0][2], av0.x, b2); fma2(acc[0][3], av0.x, b3);
            fma2(acc[1][0], av0.y, b0); fma2(acc[1][1], av0.y, b1);
            fma2(acc[1][2], av0.y, b2); fma2(acc[1][3], av0.y, b3);
            fma2(acc[2][0], av1.x, b0); fma2(acc[2][1], av1.x, b1);
            fma2(acc[2][2], av1.x, b2); fma2(acc[2][3], av1.x, b3);
            fma2(acc[3][0], av1.y, b0); fma2(acc[3][1], av1.y, b1);
            fma2(acc[3][2], av1.y, b2); fma2(acc[3][3], av1.y, b3);
        }
        __syncthreads();
    }
    // store: 8 rows x 4 cols per thread
    int c0 = bn + tx * 4;
    if (c0 >= 400) return;
    #pragma unroll
    for (int p = 0; p < 4; p++) {
        float2 f0 = unpk(acc[p][0]);
        float2 f1 = unpk(acc[p][1]);
        float2 f2 = unpk(acc[p][2]);
        float2 f3 = unpk(acc[p][3]);
        int row0 = bm + ty * 8 + 2 * p;
        if (row0 < N_NODES)
            *(float4*)&C[(long)row0 * 400 + c0] = make_float4(f0.x, f1.x, f2.x, f3.x);
        if (row0 + 1 < N_NODES)
            *(float4*)&C[(long)(row0 + 1) * 400 + c0] = make_float4(f0.y, f1.y, f2.y, f3.y);
    }
}

// ---------------- launch ----------------
extern "C" void kernel_launch(void* const* d_in, const int* in_sizes, int n_in,
                              void* d_out, int out_size) {
    const int*   el    = (const int*)d_in[0];
    const int*   et    = (const int*)d_in[1];
    const float* emb   = (const float*)d_in[2];
    const float* rel   = (const float*)d_in[3];
    const float* Wsrc  = (const float*)d_in[4];
    const float* Wdst  = (const float*)d_in[5];
    const float* avec  = (const float*)d_in[6];
    const float* wrel  = (const float*)d_in[7];
    const float* Wproj = (const float*)d_in[8];
    float* out     = (float*)d_out;
    float* out_ent = out;                        // [40000, 400]
    float* out_rel = out + (long)N_NODES * 400;  // [400, 400]

    k_zero<<<625, 256>>>();
    k_uv<<<200, 256>>>(Wsrc, Wdst, avec);
    k_t<<<100, 256>>>(rel);
    k_s<<<5000, 256>>>(emb);
    k_hist<<<98, 256>>>(et);
    k_scan<<<1, 256>>>();
    k_scatter<<<391, 256>>>(el, et);
    k_seg<<<dim3(RH, SPLIT), 256>>>(emb);
    k_relrep<<<R_NUM, 256>>>(Wsrc);
    k_relfinal<<<100, 400>>>(rel, wrel, out_rel);
    k_ent<<<dim3(7, 313), 256>>>(emb, Wproj, out_ent);
}

// round 3
// speedup vs baseline: 1.1242x; 1.1242x over previous
#include <cuda_runtime.h>
#include <cuda_bf16.h>
#include <cstdint>

#define E_NUM   100000
#define N_NODES 40000
#define R_NUM   400
#define RH      200
#define DIN     200
#define NH      4
#define CAP     1024
#define SPLIT   4
#define KPAD    256

// ---------------- device scratch ----------------
__device__ float  g_u[NH][DIN];
__device__ float  g_v[NH][DIN];
__device__ float  g_t[NH][RH];
__device__ float4 g_s[N_NODES];
__device__ int    g_count[RH];
__device__ int    g_offs[RH + 1];
__device__ int    g_cursor[RH];
__device__ int2   g_edges[E_NUM];
__device__ float  g_agg[NH][RH][DIN];
__device__ float  g_relrep[R_NUM * 400];
__device__ __align__(16) __nv_bfloat16 g_Ah[(size_t)N_NODES * KPAD];
__device__ __align__(16) __nv_bfloat16 g_Al[(size_t)N_NODES * KPAD];
__device__ __align__(16) __nv_bfloat16 g_Bh[400 * KPAD];
__device__ __align__(16) __nv_bfloat16 g_Bl[400 * KPAD];

// ---------------- helpers ----------------
__device__ __forceinline__ float lrelu(float x) { return x >= 0.f ? x : 0.2f * x; }
__device__ __forceinline__ float elu(float x)   { return x > 0.f ? x : expm1f(x); }

__device__ __forceinline__ float warp_sum(float v) {
    #pragma unroll
    for (int o = 16; o; o >>= 1) v += __shfl_down_sync(0xffffffffu, v, o);
    return v;
}

__device__ __forceinline__ uint32_t smem_u32(const void* p) {
    uint32_t a;
    asm("{ .reg .u64 t; cvta.to.shared.u64 t, %1; cvt.u32.u64 %0, t; }" : "=r"(a) : "l"(p));
    return a;
}

__device__ __forceinline__ void ldm_x4(uint32_t* r, uint32_t addr) {
    asm volatile("ldmatrix.sync.aligned.m8n8.x4.shared.b16 {%0,%1,%2,%3}, [%4];"
                 : "=r"(r[0]), "=r"(r[1]), "=r"(r[2]), "=r"(r[3]) : "r"(addr));
}
__device__ __forceinline__ void ldm_x2(uint32_t* r, uint32_t addr) {
    asm volatile("ldmatrix.sync.aligned.m8n8.x2.shared.b16 {%0,%1}, [%2];"
                 : "=r"(r[0]), "=r"(r[1]) : "r"(addr));
}
__device__ __forceinline__ void mma16816(float* d, const uint32_t* a, const uint32_t* b) {
    asm volatile("mma.sync.aligned.m16n8k16.row.col.f32.bf16.bf16.f32 "
                 "{%0,%1,%2,%3}, {%4,%5,%6,%7}, {%8,%9}, {%0,%1,%2,%3};"
                 : "+f"(d[0]), "+f"(d[1]), "+f"(d[2]), "+f"(d[3])
                 : "r"(a[0]), "r"(a[1]), "r"(a[2]), "r"(a[3]), "r"(b[0]), "r"(b[1]));
}

// ---------------- pipeline kernels ----------------
__global__ void k_zero() {
    int i = blockIdx.x * 256 + threadIdx.x;
    if (i < NH * RH * DIN) ((float*)g_agg)[i] = 0.f;
    if (i < RH) g_count[i] = 0;
}

__global__ void k_uv(const float* __restrict__ Wsrc, const float* __restrict__ Wdst,
                     const float* __restrict__ avec) {
    int w = blockIdx.x * 8 + (threadIdx.x >> 5);
    int lane = threadIdx.x & 31;
    int side = w / 800;
    int h = (w / 200) % 4;
    int i = w % 200;
    const float* W = (side == 0 ? Wsrc : Wdst) + h * DIN * DIN + i * DIN;
    const float* a = avec + h * 400 + side * 200;
    float acc = 0.f;
    for (int j = lane; j < DIN; j += 32) acc += W[j] * a[j];
    acc = warp_sum(acc);
    if (lane == 0) {
        if (side == 0) g_u[h][i] = acc; else g_v[h][i] = acc;
    }
}

__global__ void k_t(const float* __restrict__ rel) {
    int w = blockIdx.x * 8 + (threadIdx.x >> 5);
    int lane = threadIdx.x & 31;
    int h = w / RH;
    int r = w % RH;
    const float* row = rel + (r + (h < 2 ? RH : 0)) * DIN;
    float acc = 0.f;
    for (int j = lane; j < DIN; j += 32) acc += row[j] * g_v[h][j];
    acc = warp_sum(acc);
    if (lane == 0) g_t[h][r] = acc;
}

__global__ void k_s(const float* __restrict__ emb) {
    __shared__ float4 su4[NH * 50];
    for (int i = threadIdx.x; i < NH * 50; i += 256)
        su4[i] = ((const float4*)g_u)[i];
    __syncthreads();
    int n = blockIdx.x * 8 + (threadIdx.x >> 5);
    int l = threadIdx.x & 31;
    const float4* row4 = (const float4*)(emb + (long)n * DIN);
    float4 x = row4[l];
    float4 u0 = su4[0 * 50 + l], u1 = su4[1 * 50 + l];
    float4 u2 = su4[2 * 50 + l], u3 = su4[3 * 50 + l];
    float a0 = x.x * u0.x + x.y * u0.y + x.z * u0.z + x.w * u0.w;
    float a1 = x.x * u1.x + x.y * u1.y + x.z * u1.z + x.w * u1.w;
    float a2 = x.x * u2.x + x.y * u2.y + x.z * u2.z + x.w * u2.w;
    float a3 = x.x * u3.x + x.y * u3.y + x.z * u3.z + x.w * u3.w;
    if (l < 18) {
        float4 y = row4[l + 32];
        float4 v0 = su4[0 * 50 + l + 32], v1 = su4[1 * 50 + l + 32];
        float4 v2 = su4[2 * 50 + l + 32], v3 = su4[3 * 50 + l + 32];
        a0 += y.x * v0.x + y.y * v0.y + y.z * v0.z + y.w * v0.w;
        a1 += y.x * v1.x + y.y * v1.y + y.z * v1.z + y.w * v1.w;
        a2 += y.x * v2.x + y.y * v2.y + y.z * v2.z + y.w * v2.w;
        a3 += y.x * v3.x + y.y * v3.y + y.z * v3.z + y.w * v3.w;
    }
    a0 = warp_sum(a0); a1 = warp_sum(a1); a2 = warp_sum(a2); a3 = warp_sum(a3);
    if (l == 0) g_s[n] = make_float4(a0, a1, a2, a3);
}

__global__ void k_hist(const int* __restrict__ etype) {
    __shared__ int hh[RH];
    for (int i = threadIdx.x; i < RH; i += 256) hh[i] = 0;
    __syncthreads();
    int base = blockIdx.x * 1024;
    for (int i = threadIdx.x; i < 1024; i += 256) {
        int e = base + i;
        if (e < E_NUM) atomicAdd(&hh[etype[e]], 1);
    }
    __syncthreads();
    for (int i = threadIdx.x; i < RH; i += 256)
        if (hh[i]) atomicAdd(&g_count[i], hh[i]);
}

__global__ void k_scan() {
    __shared__ int sc[256];
    int t = threadIdx.x;
    int c = (t < RH) ? g_count[t] : 0;
    sc[t] = c;
    __syncthreads();
    for (int o = 1; o < 256; o <<= 1) {
        int v = (t >= o) ? sc[t - o] : 0;
        __syncthreads();
        sc[t] += v;
        __syncthreads();
    }
    if (t < RH) {
        int excl = sc[t] - c;
        g_offs[t] = excl;
        g_cursor[t] = excl;
        if (t == RH - 1) g_offs[RH] = sc[t];
    }
}

__global__ void k_scatter(const int* __restrict__ el, const int* __restrict__ etype) {
    int e = blockIdx.x * 256 + threadIdx.x;
    if (e >= E_NUM) return;
    int p = atomicAdd(&g_cursor[etype[e]], 1);
    g_edges[p] = make_int2(el[e], el[E_NUM + e]);
}

__global__ void k_seg(const float* __restrict__ emb) {
    __shared__ float4 sw[CAP];
    __shared__ int2   sed[CAP];
    __shared__ float4 red[256];
    int r = blockIdx.x;
    int t = threadIdx.x;
    int start = g_offs[r], end = g_offs[r + 1];
    int cnt = end - start;
    if (cnt == 0) return;
    float4 tr = make_float4(g_t[0][r], g_t[1][r], g_t[2][r], g_t[3][r]);

    for (int i = t; i < cnt && i < CAP; i += 256) sed[i] = g_edges[start + i];
    __syncthreads();

    float4 mx = make_float4(-1e30f, -1e30f, -1e30f, -1e30f);
    for (int i = t; i < cnt; i += 256) {
        int2 ed = (i < CAP) ? sed[i] : g_edges[start + i];
        float4 ss = g_s[ed.x], st = g_s[ed.y];
        mx.x = fmaxf(mx.x, lrelu(ss.x + tr.x));
        mx.y = fmaxf(mx.y, lrelu(ss.y + tr.y));
        mx.z = fmaxf(mx.z, lrelu(st.z + tr.z));
        mx.w = fmaxf(mx.w, lrelu(st.w + tr.w));
    }
    red[t] = mx; __syncthreads();
    for (int s = 128; s > 0; s >>= 1) {
        if (t < s) {
            float4 o = red[t + s];
            red[t].x = fmaxf(red[t].x, o.x); red[t].y = fmaxf(red[t].y, o.y);
            red[t].z = fmaxf(red[t].z, o.z); red[t].w = fmaxf(red[t].w, o.w);
        }
        __syncthreads();
    }
    float4 m = red[0]; __syncthreads();

    float4 sm = make_float4(0.f, 0.f, 0.f, 0.f);
    for (int i = t; i < cnt; i += 256) {
        int2 ed = (i < CAP) ? sed[i] : g_edges[start + i];
        float4 ss = g_s[ed.x], st = g_s[ed.y];
        float4 ex;
        ex.x = expf(lrelu(ss.x + tr.x) - m.x);
        ex.y = expf(lrelu(ss.y + tr.y) - m.y);
        ex.z = expf(lrelu(st.z + tr.z) - m.z);
        ex.w = expf(lrelu(st.w + tr.w) - m.w);
        if (i < CAP) sw[i] = ex;
        sm.x += ex.x; sm.y += ex.y; sm.z += ex.z; sm.w += ex.w;
    }
    red[t] = sm; __syncthreads();
    for (int s = 128; s > 0; s >>= 1) {
        if (t < s) {
            float4 o = red[t + s];
            red[t].x += o.x; red[t].y += o.y; red[t].z += o.z; red[t].w += o.w;
        }
        __syncthreads();
    }
    float4 dn = red[0];
    float4 sc = make_float4(1.f / (dn.x + 1e-16f), 1.f / (dn.y + 1e-16f),
                            1.f / (dn.z + 1e-16f), 1.f / (dn.w + 1e-16f));
    __syncthreads();

    int chunk = (cnt + SPLIT - 1) / SPLIT;
    int lo = blockIdx.y * chunk;
    int hi = min(lo + chunk, cnt);
    bool act = (t < DIN);
    float a0 = 0.f, a1 = 0.f, a2 = 0.f, a3 = 0.f;
    if (hi <= CAP) {
        #pragma unroll 4
        for (int i = lo; i < hi; i++) {
            float4 w = sw[i];
            int2 ed = sed[i];
            if (act) {
                float x = emb[(long)ed.x * DIN + t];
                float y = emb[(long)ed.y * DIN + t];
                a0 += w.x * x; a1 += w.y * x; a2 += w.z * y; a3 += w.w * y;
            }
        }
    } else {
        for (int i = lo; i < hi; i++) {
            float4 w;
            int2 ed;
            if (i < CAP) { w = sw[i]; ed = sed[i]; }
            else {
                ed = g_edges[start + i];
                float4 ss = g_s[ed.x], st = g_s[ed.y];
                w.x = expf(lrelu(ss.x + tr.x) - m.x);
                w.y = expf(lrelu(ss.y + tr.y) - m.y);
                w.z = expf(lrelu(st.z + tr.z) - m.z);
                w.w = expf(lrelu(st.w + tr.w) - m.w);
            }
            if (act) {
                float x = emb[(long)ed.x * DIN + t];
                float y = emb[(long)ed.y * DIN + t];
                a0 += w.x * x; a1 += w.y * x; a2 += w.z * y; a3 += w.w * y;
            }
        }
    }
    if (act) {
        atomicAdd(&g_agg[0][r][t], a0 * sc.x);
        atomicAdd(&g_agg[1][r][t], a1 * sc.y);
        atomicAdd(&g_agg[2][r][t], a2 * sc.z);
        atomicAdd(&g_agg[3][r][t], a3 * sc.w);
    }
}

__global__ void k_relrep(const float* __restrict__ Wsrc) {
    int r = blockIdx.x;
    int t = threadIdx.x;
    if (r >= RH) {
        for (int o = t; o < 400; o += 256) g_relrep[r * 400 + o] = 0.f;
        return;
    }
    __shared__ float sa[NH][DIN];
    for (int i = t; i < NH * DIN; i += 256) {
        int h = i / DIN, k = i % DIN;
        sa[h][k] = g_agg[h][r][k];
    }
    __syncthreads();
    for (int o = t; o < 400; o += 256) {
        int h = o / DIN, j = o % DIN;
        const float* W1 = Wsrc + h * (DIN * DIN) + j;
        const float* W2 = Wsrc + (h + 2) * (DIN * DIN) + j;
        float d1 = 0.f, d2 = 0.f;
        #pragma unroll 4
        for (int k = 0; k < DIN; k++) {
            d1 += sa[h][k] * W1[k * DIN];
            d2 += sa[h + 2][k] * W2[k * DIN];
        }
        g_relrep[r * 400 + o] = elu(d1) + elu(d2);
    }
}

__global__ void k_relfinal(const float* __restrict__ rel, const float* __restrict__ wrel,
                           float* __restrict__ out_rel) {
    __shared__ float sin_[4][600];
    int r0 = blockIdx.x * 4;
    int t = threadIdx.x;
    for (int i = t; i < 4 * 600; i += 400) {
        int rr = i / 600, k = i % 600;
        sin_[rr][k] = (k < 400) ? g_relrep[(r0 + rr) * 400 + k]
                                : rel[(r0 + rr) * DIN + (k - 400)];
    }
    __syncthreads();
    float acc0 = 0.f, acc1 = 0.f, acc2 = 0.f, acc3 = 0.f;
    #pragma unroll 4
    for (int k = 0; k < 600; k++) {
        float w = wrel[k * 400 + t];
        acc0 += sin_[0][k] * w; acc1 += sin_[1][k] * w;
        acc2 += sin_[2][k] * w; acc3 += sin_[3][k] * w;
    }
    out_rel[(r0 + 0) * 400 + t] = acc0;
    out_rel[(r0 + 1) * 400 + t] = acc1;
    out_rel[(r0 + 2) * 400 + t] = acc2;
    out_rel[(r0 + 3) * 400 + t] = acc3;
}

// ---------------- split-bf16 conversion ----------------
__global__ void k_cvtA(const float* __restrict__ emb) {
    int i = blockIdx.x * 256 + threadIdx.x;        // over 40000*128
    int n = i >> 7;
    int c = (i & 127) << 1;
    float2 x = make_float2(0.f, 0.f);
    if (c < 200) x = *(const float2*)&emb[(long)n * 200 + c];
    __nv_bfloat16 h0 = __float2bfloat16(x.x);
    __nv_bfloat16 h1 = __float2bfloat16(x.y);
    __nv_bfloat16 l0 = __float2bfloat16(x.x - __bfloat162float(h0));
    __nv_bfloat16 l1 = __float2bfloat16(x.y - __bfloat162float(h1));
    *(__nv_bfloat162*)&g_Ah[(long)n * KPAD + c] = __nv_bfloat162(h0, h1);
    *(__nv_bfloat162*)&g_Al[(long)n * KPAD + c] = __nv_bfloat162(l0, l1);
}

__global__ void k_cvtB(const float* __restrict__ W) {
    int n = blockIdx.x;            // 0..399 (output col)
    int k = threadIdx.x;           // 0..255
    float x = (k < 200) ? W[k * 400 + n] : 0.f;
    __nv_bfloat16 h = __float2bfloat16(x);
    g_Bh[n * KPAD + k] = h;
    g_Bl[n * KPAD + k] = __float2bfloat16(x - __bfloat162float(h));
}

// ---------------- HMMA GEMM: C[40000,400] = A @ B (split-bf16, 3 passes) ----------------
// BM=128, BN=80, KC=64 chunks; 8 warps in 4(M)x2(N); warp tile 32x40 =
// 2 m-frags x 5 n-frags of m16n8k16. fp32 accum persists across all passes.
#define BM 128
#define BN 80
#define KC 64
#define AST 72   // smem row stride (bf16) = 144B -> conflict-free ldmatrix
#define BST 72

__global__ __launch_bounds__(256) void k_entmm(float* __restrict__ C) {
    __shared__ __align__(16) __nv_bfloat16 sA[BM * AST];
    __shared__ __align__(16) __nv_bfloat16 sB[BN * BST];
    const int tid = threadIdx.x;
    const int warp = tid >> 5, lane = tid & 31;
    const int wm = warp & 3;        // 0..3 (M)
    const int wn = warp >> 2;       // 0..1 (N)
    const int bm = blockIdx.y * BM;
    const int bn = blockIdx.x * BN;

    float acc[2][5][4];
    #pragma unroll
    for (int i = 0; i < 2; i++)
        #pragma unroll
        for (int j = 0; j < 5; j++)
            #pragma unroll
            for (int c = 0; c < 4; c++) acc[i][j][c] = 0.f;

    // precompute ldmatrix shared addresses
    const uint32_t sA32 = smem_u32(sA);
    const uint32_t sB32 = smem_u32(sB);
    // A: rows (wm*32 + mf*16 + lane&15), col offset (lane>>4)*8
    const int a_row = wm * 32 + (lane & 15);
    const int a_koff = (lane >> 4) * 8;
    // B: rows (wn*40 + nf*8 + lane&7), col offset ((lane>>3)&1)*8
    const int b_row = wn * 40 + (lane & 7);
    const int b_koff = ((lane >> 3) & 1) * 8;

    #pragma unroll 1
    for (int pass = 0; pass < 3; pass++) {
        const __nv_bfloat16* Ap = (pass == 1) ? g_Al : g_Ah;
        const __nv_bfloat16* Bp = (pass == 2) ? g_Bl : g_Bh;
        #pragma unroll 1
        for (int kc = 0; kc < KPAD; kc += KC) {
            // load A tile 128x64: 1024 int4, 4 per thread
            #pragma unroll
            for (int i = 0; i < 4; i++) {
                int idx = tid + i * 256;
                int row = idx >> 3, j = idx & 7;
                int grow = bm + row;
                int4 v = make_int4(0, 0, 0, 0);
                if (grow < N_NODES)
                    v = *(const int4*)(Ap + (long)grow * KPAD + kc + j * 8);
                *(int4*)(sA + row * AST + j * 8) = v;
            }
            // load B tile 80x64: 640 int4
            for (int idx = tid; idx < 640; idx += 256) {
                int row = idx >> 3, j = idx & 7;
                int4 v = *(const int4*)(Bp + (long)(bn + row) * KPAD + kc + j * 8);
                *(int4*)(sB + row * BST + j * 8) = v;
            }
            __syncthreads();

            int nks = (kc == 192) ? 1 : 4;  // cols >= 208 are zero padding
            for (int ks = 0; ks < nks; ks++) {
                int k0 = ks * 16;
                uint32_t af[2][4], bf[5][2];
                #pragma unroll
                for (int mf = 0; mf < 2; mf++)
                    ldm_x4(af[mf], sA32 + ((a_row + mf * 16) * AST + k0 + a_koff) * 2);
                #pragma unroll
                for (int nf = 0; nf < 5; nf++)
                    ldm_x2(bf[nf], sB32 + ((b_row + nf * 8) * BST + k0 + b_koff) * 2);
                #pragma unroll
                for (int mf = 0; mf < 2; mf++)
                    #pragma unroll
                    for (int nf = 0; nf < 5; nf++)
                        mma16816(acc[mf][nf], af[mf], bf[nf]);
            }
            __syncthreads();
        }
    }

    // store: frag c0,c1 -> (m=lane/4, n=(lane%4)*2), c2,c3 -> m+8
    const int m_base = bm + wm * 32 + (lane >> 2);
    const int n_base = bn + wn * 40 + (lane & 3) * 2;
    #pragma unroll
    for (int mf = 0; mf < 2; mf++) {
        #pragma unroll
        for (int nf = 0; nf < 5; nf++) {
            int n = n_base + nf * 8;
            int m0 = m_base + mf * 16;
            if (m0 < N_NODES)
                *(float2*)&C[(long)m0 * 400 + n] = make_float2(acc[mf][nf][0], acc[mf][nf][1]);
            if (m0 + 8 < N_NODES)
                *(float2*)&C[(long)(m0 + 8) * 400 + n] = make_float2(acc[mf][nf][2], acc[mf][nf][3]);
        }
    }
}

// ---------------- launch ----------------
extern "C" void kernel_launch(void* const* d_in, const int* in_sizes, int n_in,
                              void* d_out, int out_size) {
    const int*   el    = (const int*)d_in[0];
    const int*   et    = (const int*)d_in[1];
    const float* emb   = (const float*)d_in[2];
    const float* rel   = (const float*)d_in[3];
    const float* Wsrc  = (const float*)d_in[4];
    const float* Wdst  = (const float*)d_in[5];
    const float* avec  = (const float*)d_in[6];
    const float* wrel  = (const float*)d_in[7];
    const float* Wproj = (const float*)d_in[8];
    float* out     = (float*)d_out;
    float* out_ent = out;
    float* out_rel = out + (long)N_NODES * 400;

    k_zero<<<625, 256>>>();
    k_uv<<<200, 256>>>(Wsrc, Wdst, avec);
    k_t<<<100, 256>>>(rel);
    k_s<<<5000, 256>>>(emb);
    k_hist<<<98, 256>>>(et);
    k_scan<<<1, 256>>>();
    k_scatter<<<391, 256>>>(el, et);
    k_seg<<<dim3(RH, SPLIT), 256>>>(emb);
    k_relrep<<<R_NUM, 256>>>(Wsrc);
    k_relfinal<<<100, 400>>>(rel, wrel, out_rel);
    k_cvtA<<<20000, 256>>>(emb);
    k_cvtB<<<400, 256>>>(Wproj);
    k_entmm<<<dim3(5, 313), 256>>>(out_ent);
}

// round 6
// speedup vs baseline: 1.1753x; 1.0455x over previous
#include <cuda_runtime.h>
#include <cuda_bf16.h>
#include <cstdint>

#define E_NUM   100000
#define N_NODES 40000
#define R_NUM   400
#define RH      200
#define DIN     200
#define NH      4
#define CAP     1024
#define SPLIT   8
#define SLICE_MAX 256
#define KPAD    256

// ---------------- device scratch ----------------
__device__ float  g_u[NH][DIN];
__device__ float  g_v[NH][DIN];
__device__ float  g_t[NH][RH];
__device__ float4 g_s[N_NODES];
__device__ int    g_count[RH];
__device__ int    g_offs[RH + 1];
__device__ int    g_cursor[RH];
__device__ int2   g_edges[E_NUM];
__device__ float4 g_w[E_NUM];            // per-edge un-normalized exp weights
__device__ float4 g_sc[RH];              // per-relation 1/denom
__device__ float  g_agg[NH][RH][DIN];
__device__ float  g_relrep[R_NUM * 400];
__device__ __align__(16) __nv_bfloat16 g_Ah[(size_t)N_NODES * KPAD];
__device__ __align__(16) __nv_bfloat16 g_Al[(size_t)N_NODES * KPAD];
__device__ __align__(16) __nv_bfloat16 g_Bh[400 * KPAD];
__device__ __align__(16) __nv_bfloat16 g_Bl[400 * KPAD];

// ---------------- helpers ----------------
__device__ __forceinline__ float lrelu(float x) { return x >= 0.f ? x : 0.2f * x; }
__device__ __forceinline__ float elu(float x)   { return x > 0.f ? x : expm1f(x); }

__device__ __forceinline__ float warp_sum(float v) {
    #pragma unroll
    for (int o = 16; o; o >>= 1) v += __shfl_down_sync(0xffffffffu, v, o);
    return v;
}

__device__ __forceinline__ uint32_t smem_u32(const void* p) {
    uint32_t a;
    asm("{ .reg .u64 t; cvta.to.shared.u64 t, %1; cvt.u32.u64 %0, t; }" : "=r"(a) : "l"(p));
    return a;
}

__device__ __forceinline__ uint32_t pack_bf2(float a, float b) {
    __nv_bfloat162 t(__float2bfloat16(a), __float2bfloat16(b));
    return *(uint32_t*)&t;
}

__device__ __forceinline__ void ldm_x4(uint32_t* r, uint32_t addr) {
    asm volatile("ldmatrix.sync.aligned.m8n8.x4.shared.b16 {%0,%1,%2,%3}, [%4];"
                 : "=r"(r[0]), "=r"(r[1]), "=r"(r[2]), "=r"(r[3]) : "r"(addr));
}
__device__ __forceinline__ void ldm_x2(uint32_t* r, uint32_t addr) {
    asm volatile("ldmatrix.sync.aligned.m8n8.x2.shared.b16 {%0,%1}, [%2];"
                 : "=r"(r[0]), "=r"(r[1]) : "r"(addr));
}
__device__ __forceinline__ void mma16816(float* d, const uint32_t* a, const uint32_t* b) {
    asm volatile("mma.sync.aligned.m16n8k16.row.col.f32.bf16.bf16.f32 "
                 "{%0,%1,%2,%3}, {%4,%5,%6,%7}, {%8,%9}, {%0,%1,%2,%3};"
                 : "+f"(d[0]), "+f"(d[1]), "+f"(d[2]), "+f"(d[3])
                 : "r"(a[0]), "r"(a[1]), "r"(a[2]), "r"(a[3]), "r"(b[0]), "r"(b[1]));
}

// ---------------- k_init: uv + zero(agg,count) + cvtB ----------------
__global__ void k_init(const float* __restrict__ Wsrc, const float* __restrict__ Wdst,
                       const float* __restrict__ avec, const float* __restrict__ Wproj) {
    int b = blockIdx.x;
    if (b < 200) {
        int w = b * 8 + (threadIdx.x >> 5);
        int lane = threadIdx.x & 31;
        int side = w / 800;
        int h = (w / 200) % 4;
        int i = w % 200;
        const float* W = (side == 0 ? Wsrc : Wdst) + h * DIN * DIN + i * DIN;
        const float* a = avec + h * 400 + side * 200;
        float acc = 0.f;
        for (int j = lane; j < DIN; j += 32) acc += W[j] * a[j];
        acc = warp_sum(acc);
        if (lane == 0) {
            if (side == 0) g_u[h][i] = acc; else g_v[h][i] = acc;
        }
    } else if (b < 825) {
        int i = (b - 200) * 256 + threadIdx.x;
        if (i < NH * RH * DIN) ((float*)g_agg)[i] = 0.f;
        if (b == 200 && threadIdx.x < RH) g_count[threadIdx.x] = 0;
    } else {
        int n = b - 825;
        int k = threadIdx.x;
        float x = (k < 200) ? Wproj[k * 400 + n] : 0.f;
        __nv_bfloat16 h = __float2bfloat16(x);
        g_Bh[n * KPAD + k] = h;
        g_Bl[n * KPAD + k] = __float2bfloat16(x - __bfloat162float(h));
    }
}

// ---------------- k_stcvt: s-scores + cvtA (one emb read) + t + hist ----------------
__global__ void k_stcvt(const float* __restrict__ emb, const float* __restrict__ rel,
                        const int* __restrict__ etype) {
    __shared__ float4 su4[NH * 50];
    __shared__ int hh[RH];
    int b = blockIdx.x;
    if (b < 5000) {
        for (int i = threadIdx.x; i < NH * 50; i += 256)
            su4[i] = ((const float4*)g_u)[i];
        __syncthreads();
        int n = b * 8 + (threadIdx.x >> 5);
        int l = threadIdx.x & 31;
        const float4* row4 = (const float4*)(emb + (long)n * DIN);
        float4 x = row4[l];
        float4 u0 = su4[0 * 50 + l], u1 = su4[1 * 50 + l];
        float4 u2 = su4[2 * 50 + l], u3 = su4[3 * 50 + l];
        float a0 = x.x * u0.x + x.y * u0.y + x.z * u0.z + x.w * u0.w;
        float a1 = x.x * u1.x + x.y * u1.y + x.z * u1.z + x.w * u1.w;
        float a2 = x.x * u2.x + x.y * u2.y + x.z * u2.z + x.w * u2.w;
        float a3 = x.x * u3.x + x.y * u3.y + x.z * u3.z + x.w * u3.w;
        {
            uint2 vh, vl;
            vh.x = pack_bf2(x.x, x.y); vh.y = pack_bf2(x.z, x.w);
            float rx = x.x - __bfloat162float(__float2bfloat16(x.x));
            float ry = x.y - __bfloat162float(__float2bfloat16(x.y));
            float rz = x.z - __bfloat162float(__float2bfloat16(x.z));
            float rw = x.w - __bfloat162float(__float2bfloat16(x.w));
            vl.x = pack_bf2(rx, ry); vl.y = pack_bf2(rz, rw);
            *(uint2*)&g_Ah[(long)n * KPAD + 4 * l] = vh;
            *(uint2*)&g_Al[(long)n * KPAD + 4 * l] = vl;
        }
        if (l < 18) {
            float4 y = row4[l + 32];
            float4 v0 = su4[0 * 50 + l + 32], v1 = su4[1 * 50 + l + 32];
            float4 v2 = su4[2 * 50 + l + 32], v3 = su4[3 * 50 + l + 32];
            a0 += y.x * v0.x + y.y * v0.y + y.z * v0.z + y.w * v0.w;
            a1 += y.x * v1.x + y.y * v1.y + y.z * v1.z + y.w * v1.w;
            a2 += y.x * v2.x + y.y * v2.y + y.z * v2.z + y.w * v2.w;
            a3 += y.x * v3.x + y.y * v3.y + y.z * v3.z + y.w * v3.w;
            uint2 vh, vl;
            vh.x = pack_bf2(y.x, y.y); vh.y = pack_bf2(y.z, y.w);
            float rx = y.x - __bfloat162float(__float2bfloat16(y.x));
            float ry = y.y - __bfloat162float(__float2bfloat16(y.y));
            float rz = y.z - __bfloat162float(__float2bfloat16(y.z));
            float rw = y.w - __bfloat162float(__float2bfloat16(y.w));
            vl.x = pack_bf2(rx, ry); vl.y = pack_bf2(rz, rw);
            *(uint2*)&g_Ah[(long)n * KPAD + 128 + 4 * l] = vh;
            *(uint2*)&g_Al[(long)n * KPAD + 128 + 4 * l] = vl;
        } else {
            uint2 z = make_uint2(0u, 0u);
            *(uint2*)&g_Ah[(long)n * KPAD + 128 + 4 * l] = z;
            *(uint2*)&g_Al[(long)n * KPAD + 128 + 4 * l] = z;
        }
        a0 = warp_sum(a0); a1 = warp_sum(a1); a2 = warp_sum(a2); a3 = warp_sum(a3);
        if (l == 0) g_s[n] = make_float4(a0, a1, a2, a3);
    } else if (b < 5100) {
        int w = (b - 5000) * 8 + (threadIdx.x >> 5);
        int lane = threadIdx.x & 31;
        int h = w / RH;
        int r = w % RH;
        const float* row = rel + (r + (h < 2 ? RH : 0)) * DIN;
        float acc = 0.f;
        for (int j = lane; j < DIN; j += 32) acc += row[j] * g_v[h][j];
        acc = warp_sum(acc);
        if (lane == 0) g_t[h][r] = acc;
    } else {
        for (int i = threadIdx.x; i < RH; i += 256) hh[i] = 0;
        __syncthreads();
        int base = (b - 5100) * 1024;
        for (int i = threadIdx.x; i < 1024; i += 256) {
            int e = base + i;
            if (e < E_NUM) atomicAdd(&hh[etype[e]], 1);
        }
        __syncthreads();
        for (int i = threadIdx.x; i < RH; i += 256)
            if (hh[i]) atomicAdd(&g_count[i], hh[i]);
    }
}

__global__ void k_scan() {
    __shared__ int sc[256];
    int t = threadIdx.x;
    int c = (t < RH) ? g_count[t] : 0;
    sc[t] = c;
    __syncthreads();
    for (int o = 1; o < 256; o <<= 1) {
        int v = (t >= o) ? sc[t - o] : 0;
        __syncthreads();
        sc[t] += v;
        __syncthreads();
    }
    if (t < RH) {
        int excl = sc[t] - c;
        g_offs[t] = excl;
        g_cursor[t] = excl;
        if (t == RH - 1) g_offs[RH] = sc[t];
    }
}

__global__ void k_scatter(const int* __restrict__ el, const int* __restrict__ etype) {
    int e = blockIdx.x * 256 + threadIdx.x;
    if (e >= E_NUM) return;
    int p = atomicAdd(&g_cursor[etype[e]], 1);
    g_edges[p] = make_int2(el[e], el[E_NUM + e]);
}

// ---------------- k_w: per-relation softmax stats + per-edge weights ----------------
__global__ void k_w() {
    __shared__ int2   sed[CAP];
    __shared__ float4 red[256];
    int r = blockIdx.x;
    int t = threadIdx.x;
    int start = g_offs[r], end = g_offs[r + 1];
    int cnt = end - start;
    if (cnt == 0) return;
    float4 tr = make_float4(g_t[0][r], g_t[1][r], g_t[2][r], g_t[3][r]);

    for (int i = t; i < cnt && i < CAP; i += 256) sed[i] = g_edges[start + i];
    __syncthreads();

    float4 mx = make_float4(-1e30f, -1e30f, -1e30f, -1e30f);
    for (int i = t; i < cnt; i += 256) {
        int2 ed = (i < CAP) ? sed[i] : g_edges[start + i];
        float4 ss = g_s[ed.x], st = g_s[ed.y];
        mx.x = fmaxf(mx.x, lrelu(ss.x + tr.x));
        mx.y = fmaxf(mx.y, lrelu(ss.y + tr.y));
        mx.z = fmaxf(mx.z, lrelu(st.z + tr.z));
        mx.w = fmaxf(mx.w, lrelu(st.w + tr.w));
    }
    red[t] = mx; __syncthreads();
    for (int s = 128; s > 0; s >>= 1) {
        if (t < s) {
            float4 o = red[t + s];
            red[t].x = fmaxf(red[t].x, o.x); red[t].y = fmaxf(red[t].y, o.y);
            red[t].z = fmaxf(red[t].z, o.z); red[t].w = fmaxf(red[t].w, o.w);
        }
        __syncthreads();
    }
    float4 m = red[0]; __syncthreads();

    float4 sm = make_float4(0.f, 0.f, 0.f, 0.f);
    for (int i = t; i < cnt; i += 256) {
        int2 ed = (i < CAP) ? sed[i] : g_edges[start + i];
        float4 ss = g_s[ed.x], st = g_s[ed.y];
        float4 ex;
        ex.x = expf(lrelu(ss.x + tr.x) - m.x);
        ex.y = expf(lrelu(ss.y + tr.y) - m.y);
        ex.z = expf(lrelu(st.z + tr.z) - m.z);
        ex.w = expf(lrelu(st.w + tr.w) - m.w);
        g_w[start + i] = ex;
        sm.x += ex.x; sm.y += ex.y; sm.z += ex.z; sm.w += ex.w;
    }
    red[t] = sm; __syncthreads();
    for (int s = 128; s > 0; s >>= 1) {
        if (t < s) {
            float4 o = red[t + s];
            red[t].x += o.x; red[t].y += o.y; red[t].z += o.z; red[t].w += o.w;
        }
        __syncthreads();
    }
    if (t == 0) {
        float4 dn = red[0];
        g_sc[r] = make_float4(1.f / (dn.x + 1e-16f), 1.f / (dn.y + 1e-16f),
                              1.f / (dn.z + 1e-16f), 1.f / (dn.w + 1e-16f));
    }
}

// ---------------- k_agg: gather-aggregate with precomputed weights ----------------
__global__ void k_agg(const float* __restrict__ emb) {
    __shared__ int2   sed[SLICE_MAX];
    __shared__ float4 sw[SLICE_MAX];
    int r = blockIdx.x;
    int t = threadIdx.x;
    int start = g_offs[r], end = g_offs[r + 1];
    int cnt = end - start;
    if (cnt == 0) return;
    int chunk = (cnt + SPLIT - 1) / SPLIT;
    int lo = blockIdx.y * chunk;
    int hi = min(lo + chunk, cnt);
    if (lo >= hi) return;
    int len = hi - lo;
    bool fits = (len <= SLICE_MAX);
    if (fits) {
        for (int i = t; i < len; i += 256) {
            sed[i] = g_edges[start + lo + i];
            sw[i]  = g_w[start + lo + i];
        }
        __syncthreads();
    }
    float4 sc = g_sc[r];
    bool act = (t < DIN);
    float a0 = 0.f, a1 = 0.f, a2 = 0.f, a3 = 0.f;
    #pragma unroll 4
    for (int j = 0; j < len; j++) {
        float4 w = fits ? sw[j] : g_w[start + lo + j];
        int2 ed  = fits ? sed[j] : g_edges[start + lo + j];
        if (act) {
            float x = emb[(long)ed.x * DIN + t];
            float y = emb[(long)ed.y * DIN + t];
            a0 += w.x * x; a1 += w.y * x; a2 += w.z * y; a3 += w.w * y;
        }
    }
    if (act) {
        atomicAdd(&g_agg[0][r][t], a0 * sc.x);
        atomicAdd(&g_agg[1][r][t], a1 * sc.y);
        atomicAdd(&g_agg[2][r][t], a2 * sc.z);
        atomicAdd(&g_agg[3][r][t], a3 * sc.w);
    }
}

__global__ void k_relrep(const float* __restrict__ Wsrc) {
    int r = blockIdx.x;
    int t = threadIdx.x;
    if (r >= RH) {
        for (int o = t; o < 400; o += 256) g_relrep[r * 400 + o] = 0.f;
        return;
    }
    __shared__ float sa[NH][DIN];
    for (int i = t; i < NH * DIN; i += 256) {
        int h = i / DIN, k = i % DIN;
        sa[h][k] = g_agg[h][r][k];
    }
    __syncthreads();
    for (int o = t; o < 400; o += 256) {
        int h = o / DIN, j = o % DIN;
        const float* W1 = Wsrc + h * (DIN * DIN) + j;
        const float* W2 = Wsrc + (h + 2) * (DIN * DIN) + j;
        float d1 = 0.f, d2 = 0.f;
        #pragma unroll 4
        for (int k = 0; k < DIN; k++) {
            d1 += sa[h][k] * W1[k * DIN];
            d2 += sa[h + 2][k] * W2[k * DIN];
        }
        g_relrep[r * 400 + o] = elu(d1) + elu(d2);
    }
}

__global__ void k_relfinal(const float* __restrict__ rel, const float* __restrict__ wrel,
                           float* __restrict__ out_rel) {
    __shared__ float sin_[4][600];
    int r0 = blockIdx.x * 4;
    int t = threadIdx.x;
    for (int i = t; i < 4 * 600; i += 400) {
        int rr = i / 600, k = i % 600;
        sin_[rr][k] = (k < 400) ? g_relrep[(r0 + rr) * 400 + k]
                                : rel[(r0 + rr) * DIN + (k - 400)];
    }
    __syncthreads();
    float acc0 = 0.f, acc1 = 0.f, acc2 = 0.f, acc3 = 0.f;
    #pragma unroll 4
    for (int k = 0; k < 600; k++) {
        float w = wrel[k * 400 + t];
        acc0 += sin_[0][k] * w; acc1 += sin_[1][k] * w;
        acc2 += sin_[2][k] * w; acc3 += sin_[3][k] * w;
    }
    out_rel[(r0 + 0) * 400 + t] = acc0;
    out_rel[(r0 + 1) * 400 + t] = acc1;
    out_rel[(r0 + 2) * 400 + t] = acc2;
    out_rel[(r0 + 3) * 400 + t] = acc3;
}

// ---------------- fused split-bf16 HMMA GEMM (KC=32, smem 33.3KB) ----------------
#define BM 128
#define BN 80
#define KC 32
#define AST 40
#define BST 40

__global__ __launch_bounds__(256) void k_entmm(float* __restrict__ C) {
    __shared__ __align__(16) __nv_bfloat16 sAh[BM * AST];
    __shared__ __align__(16) __nv_bfloat16 sAl[BM * AST];
    __shared__ __align__(16) __nv_bfloat16 sBh[BN * BST];
    __shared__ __align__(16) __nv_bfloat16 sBl[BN * BST];
    const int tid = threadIdx.x;
    const int warp = tid >> 5, lane = tid & 31;
    const int wm = warp & 3;
    const int wn = warp >> 2;
    const int bm = blockIdx.y * BM;
    const int bn = blockIdx.x * BN;

    float acc[2][5][4];
    #pragma unroll
    for (int i = 0; i < 2; i++)
        #pragma unroll
        for (int j = 0; j < 5; j++)
            #pragma unroll
            for (int c = 0; c < 4; c++) acc[i][j][c] = 0.f;

    const uint32_t sAh32 = smem_u32(sAh), sAl32 = smem_u32(sAl);
    const uint32_t sBh32 = smem_u32(sBh), sBl32 = smem_u32(sBl);
    const int a_row = wm * 32 + (lane & 15);
    const int a_koff = (lane >> 4) * 8;
    const int b_row = wn * 40 + (lane & 7);
    const int b_koff = ((lane >> 3) & 1) * 8;

    #pragma unroll 1
    for (int kc = 0; kc < 224; kc += KC) {
        // A tiles: 128 rows x 32 cols = 512 int4 each; 2 per thread
        #pragma unroll
        for (int i = 0; i < 2; i++) {
            int idx = tid + i * 256;
            int row = idx >> 2, j = idx & 3;
            int grow = bm + row;
            int4 vh = make_int4(0, 0, 0, 0), vl = make_int4(0, 0, 0, 0);
            if (grow < N_NODES) {
                vh = *(const int4*)(g_Ah + (long)grow * KPAD + kc + j * 8);
                vl = *(const int4*)(g_Al + (long)grow * KPAD + kc + j * 8);
            }
            *(int4*)(sAh + row * AST + j * 8) = vh;
            *(int4*)(sAl + row * AST + j * 8) = vl;
        }
        // B tiles: 80 rows x 32 cols = 320 int4 each
        for (int idx = tid; idx < 320; idx += 256) {
            int row = idx >> 2, j = idx & 3;
            *(int4*)(sBh + row * BST + j * 8) =
                *(const int4*)(g_Bh + (long)(bn + row) * KPAD + kc + j * 8);
            *(int4*)(sBl + row * BST + j * 8) =
                *(const int4*)(g_Bl + (long)(bn + row) * KPAD + kc + j * 8);
        }
        __syncthreads();

        int nks = (kc == 192) ? 1 : 2;
        for (int ks = 0; ks < nks; ks++) {
            int k0 = ks * 16;
            uint32_t afh[2][4], afl[2][4], bfh[5][2], bfl[5][2];
            #pragma unroll
            for (int mf = 0; mf < 2; mf++) {
                ldm_x4(afh[mf], sAh32 + ((a_row + mf * 16) * AST + k0 + a_koff) * 2);
                ldm_x4(afl[mf], sAl32 + ((a_row + mf * 16) * AST + k0 + a_koff) * 2);
            }
            #pragma unroll
            for (int nf = 0; nf < 5; nf++) {
                ldm_x2(bfh[nf], sBh32 + ((b_row + nf * 8) * BST + k0 + b_koff) * 2);
                ldm_x2(bfl[nf], sBl32 + ((b_row + nf * 8) * BST + k0 + b_koff) * 2);
            }
            #pragma unroll
            for (int mf = 0; mf < 2; mf++)
                #pragma unroll
                for (int nf = 0; nf < 5; nf++) {
                    mma16816(acc[mf][nf], afh[mf], bfh[nf]);
                    mma16816(acc[mf][nf], afl[mf], bfh[nf]);
                    mma16816(acc[mf][nf], afh[mf], bfl[nf]);
                }
        }
        __syncthreads();
    }

    const int m_base = bm + wm * 32 + (lane >> 2);
    const int n_base = bn + wn * 40 + (lane & 3) * 2;
    #pragma unroll
    for (int mf = 0; mf < 2; mf++) {
        #pragma unroll
        for (int nf = 0; nf < 5; nf++) {
            int n = n_base + nf * 8;
            int m0 = m_base + mf * 16;
            if (m0 < N_NODES)
                *(float2*)&C[(long)m0 * 400 + n] = make_float2(acc[mf][nf][0], acc[mf][nf][1]);
            if (m0 + 8 < N_NODES)
                *(float2*)&C[(long)(m0 + 8) * 400 + n] = make_float2(acc[mf][nf][2], acc[mf][nf][3]);
        }
    }
}

// ---------------- launch ----------------
extern "C" void kernel_launch(void* const* d_in, const int* in_sizes, int n_in,
                              void* d_out, int out_size) {
    const int*   el    = (const int*)d_in[0];
    const int*   et    = (const int*)d_in[1];
    const float* emb   = (const float*)d_in[2];
    const float* rel   = (const float*)d_in[3];
    const float* Wsrc  = (const float*)d_in[4];
    const float* Wdst  = (const float*)d_in[5];
    const float* avec  = (const float*)d_in[6];
    const float* wrel  = (const float*)d_in[7];
    const float* Wproj = (const float*)d_in[8];
    float* out     = (float*)d_out;
    float* out_ent = out;
    float* out_rel = out + (long)N_NODES * 400;

    k_init<<<1225, 256>>>(Wsrc, Wdst, avec, Wproj);
    k_stcvt<<<5198, 256>>>(emb, rel, et);
    k_scan<<<1, 256>>>();
    k_scatter<<<391, 256>>>(el, et);
    k_w<<<RH, 256>>>();
    k_agg<<<dim3(RH, SPLIT), 256>>>(emb);
    k_relrep<<<R_NUM, 256>>>(Wsrc);
    k_relfinal<<<100, 400>>>(rel, wrel, out_rel);
    k_entmm<<<dim3(5, 313), 256>>>(out_ent);
}

// round 7
// speedup vs baseline: 1.2396x; 1.0547x over previous
#include <cuda_runtime.h>
#include <cuda_bf16.h>
#include <cstdint>

#define E_NUM   100000
#define N_NODES 40000
#define R_NUM   400
#define RH      200
#define DIN     200
#define NH      4
#define CAP     1024
#define SPLIT   8
#define SLICE_MAX 256
#define KPAD    224

// ---------------- device scratch ----------------
__device__ float  g_u[NH][DIN];
__device__ float  g_v[NH][DIN];
__device__ float  g_t[NH][RH];
__device__ float4 g_s[N_NODES];
__device__ int    g_count[RH];
__device__ int    g_offs[RH + 1];
__device__ int    g_cursor[RH];
__device__ int2   g_edges[E_NUM];
__device__ float4 g_w[E_NUM];            // per-edge un-normalized exp weights
__device__ float4 g_sc[RH];              // per-relation 1/denom
__device__ float  g_agg[NH][RH][DIN];
__device__ float  g_relrep[R_NUM * 400];
__device__ __align__(16) __nv_bfloat16 g_Ah[(size_t)N_NODES * KPAD];
__device__ __align__(16) __nv_bfloat16 g_Al[(size_t)N_NODES * KPAD];
__device__ __align__(16) __nv_bfloat16 g_Bh[400 * KPAD];
__device__ __align__(16) __nv_bfloat16 g_Bl[400 * KPAD];

// ---------------- helpers ----------------
__device__ __forceinline__ float lrelu(float x) { return x >= 0.f ? x : 0.2f * x; }
__device__ __forceinline__ float elu(float x)   { return x > 0.f ? x : expm1f(x); }

__device__ __forceinline__ float warp_sum(float v) {
    #pragma unroll
    for (int o = 16; o; o >>= 1) v += __shfl_down_sync(0xffffffffu, v, o);
    return v;
}

__device__ __forceinline__ uint32_t smem_u32(const void* p) {
    uint32_t a;
    asm("{ .reg .u64 t; cvta.to.shared.u64 t, %1; cvt.u32.u64 %0, t; }" : "=r"(a) : "l"(p));
    return a;
}

__device__ __forceinline__ uint32_t pack_bf2(float a, float b) {
    __nv_bfloat162 t(__float2bfloat16(a), __float2bfloat16(b));
    return *(uint32_t*)&t;
}

__device__ __forceinline__ void ldm_x4(uint32_t* r, uint32_t addr) {
    asm volatile("ldmatrix.sync.aligned.m8n8.x4.shared.b16 {%0,%1,%2,%3}, [%4];"
                 : "=r"(r[0]), "=r"(r[1]), "=r"(r[2]), "=r"(r[3]) : "r"(addr));
}
__device__ __forceinline__ void ldm_x2(uint32_t* r, uint32_t addr) {
    asm volatile("ldmatrix.sync.aligned.m8n8.x2.shared.b16 {%0,%1}, [%2];"
                 : "=r"(r[0]), "=r"(r[1]) : "r"(addr));
}
__device__ __forceinline__ void mma16816(float* d, const uint32_t* a, const uint32_t* b) {
    asm volatile("mma.sync.aligned.m16n8k16.row.col.f32.bf16.bf16.f32 "
                 "{%0,%1,%2,%3}, {%4,%5,%6,%7}, {%8,%9}, {%0,%1,%2,%3};"
                 : "+f"(d[0]), "+f"(d[1]), "+f"(d[2]), "+f"(d[3])
                 : "r"(a[0]), "r"(a[1]), "r"(a[2]), "r"(a[3]), "r"(b[0]), "r"(b[1]));
}

// ---------------- k_init: uv + zero(agg,count) + cvtB ----------------
__global__ void k_init(const float* __restrict__ Wsrc, const float* __restrict__ Wdst,
                       const float* __restrict__ avec, const float* __restrict__ Wproj) {
    int b = blockIdx.x;
    if (b < 200) {
        int w = b * 8 + (threadIdx.x >> 5);
        int lane = threadIdx.x & 31;
        int side = w / 800;
        int h = (w / 200) % 4;
        int i = w % 200;
        const float* W = (side == 0 ? Wsrc : Wdst) + h * DIN * DIN + i * DIN;
        const float* a = avec + h * 400 + side * 200;
        float acc = 0.f;
        for (int j = lane; j < DIN; j += 32) acc += W[j] * a[j];
        acc = warp_sum(acc);
        if (lane == 0) {
            if (side == 0) g_u[h][i] = acc; else g_v[h][i] = acc;
        }
    } else if (b < 825) {
        int i = (b - 200) * 256 + threadIdx.x;
        if (i < NH * RH * DIN) ((float*)g_agg)[i] = 0.f;
        if (b == 200 && threadIdx.x < RH) g_count[threadIdx.x] = 0;
    } else {
        int n = b - 825;
        int k = threadIdx.x;
        if (k < KPAD) {
            float x = (k < 200) ? Wproj[k * 400 + n] : 0.f;
            __nv_bfloat16 h = __float2bfloat16(x);
            g_Bh[n * KPAD + k] = h;
            g_Bl[n * KPAD + k] = __float2bfloat16(x - __bfloat162float(h));
        }
    }
}

// ---------------- k_stcvt: s-scores + cvtA (one emb read) + t + hist ----------------
__global__ void k_stcvt(const float* __restrict__ emb, const float* __restrict__ rel,
                        const int* __restrict__ etype) {
    __shared__ float4 su4[NH * 50];
    __shared__ int hh[RH];
    int b = blockIdx.x;
    if (b < 5000) {
        for (int i = threadIdx.x; i < NH * 50; i += 256)
            su4[i] = ((const float4*)g_u)[i];
        __syncthreads();
        int n = b * 8 + (threadIdx.x >> 5);
        int l = threadIdx.x & 31;
        const float4* row4 = (const float4*)(emb + (long)n * DIN);
        float4 x = row4[l];
        float4 u0 = su4[0 * 50 + l], u1 = su4[1 * 50 + l];
        float4 u2 = su4[2 * 50 + l], u3 = su4[3 * 50 + l];
        float a0 = x.x * u0.x + x.y * u0.y + x.z * u0.z + x.w * u0.w;
        float a1 = x.x * u1.x + x.y * u1.y + x.z * u1.z + x.w * u1.w;
        float a2 = x.x * u2.x + x.y * u2.y + x.z * u2.z + x.w * u2.w;
        float a3 = x.x * u3.x + x.y * u3.y + x.z * u3.z + x.w * u3.w;
        {
            uint2 vh, vl;
            vh.x = pack_bf2(x.x, x.y); vh.y = pack_bf2(x.z, x.w);
            float rx = x.x - __bfloat162float(__float2bfloat16(x.x));
            float ry = x.y - __bfloat162float(__float2bfloat16(x.y));
            float rz = x.z - __bfloat162float(__float2bfloat16(x.z));
            float rw = x.w - __bfloat162float(__float2bfloat16(x.w));
            vl.x = pack_bf2(rx, ry); vl.y = pack_bf2(rz, rw);
            *(uint2*)&g_Ah[(long)n * KPAD + 4 * l] = vh;
            *(uint2*)&g_Al[(long)n * KPAD + 4 * l] = vl;
        }
        if (l < 18) {
            float4 y = row4[l + 32];
            float4 v0 = su4[0 * 50 + l + 32], v1 = su4[1 * 50 + l + 32];
            float4 v2 = su4[2 * 50 + l + 32], v3 = su4[3 * 50 + l + 32];
            a0 += y.x * v0.x + y.y * v0.y + y.z * v0.z + y.w * v0.w;
            a1 += y.x * v1.x + y.y * v1.y + y.z * v1.z + y.w * v1.w;
            a2 += y.x * v2.x + y.y * v2.y + y.z * v2.z + y.w * v2.w;
            a3 += y.x * v3.x + y.y * v3.y + y.z * v3.z + y.w * v3.w;
            uint2 vh, vl;
            vh.x = pack_bf2(y.x, y.y); vh.y = pack_bf2(y.z, y.w);
            float rx = y.x - __bfloat162float(__float2bfloat16(y.x));
            float ry = y.y - __bfloat162float(__float2bfloat16(y.y));
            float rz = y.z - __bfloat162float(__float2bfloat16(y.z));
            float rw = y.w - __bfloat162float(__float2bfloat16(y.w));
            vl.x = pack_bf2(rx, ry); vl.y = pack_bf2(rz, rw);
            *(uint2*)&g_Ah[(long)n * KPAD + 128 + 4 * l] = vh;
            *(uint2*)&g_Al[(long)n * KPAD + 128 + 4 * l] = vl;
        } else if (l < 24) {
            uint2 z = make_uint2(0u, 0u);
            *(uint2*)&g_Ah[(long)n * KPAD + 128 + 4 * l] = z;
            *(uint2*)&g_Al[(long)n * KPAD + 128 + 4 * l] = z;
        }
        a0 = warp_sum(a0); a1 = warp_sum(a1); a2 = warp_sum(a2); a3 = warp_sum(a3);
        if (l == 0) g_s[n] = make_float4(a0, a1, a2, a3);
    } else if (b < 5100) {
        int w = (b - 5000) * 8 + (threadIdx.x >> 5);
        int lane = threadIdx.x & 31;
        int h = w / RH;
        int r = w % RH;
        const float* row = rel + (r + (h < 2 ? RH : 0)) * DIN;
        float acc = 0.f;
        for (int j = lane; j < DIN; j += 32) acc += row[j] * g_v[h][j];
        acc = warp_sum(acc);
        if (lane == 0) g_t[h][r] = acc;
    } else {
        for (int i = threadIdx.x; i < RH; i += 256) hh[i] = 0;
        __syncthreads();
        int base = (b - 5100) * 1024;
        for (int i = threadIdx.x; i < 1024; i += 256) {
            int e = base + i;
            if (e < E_NUM) atomicAdd(&hh[etype[e]], 1);
        }
        __syncthreads();
        for (int i = threadIdx.x; i < RH; i += 256)
            if (hh[i]) atomicAdd(&g_count[i], hh[i]);
    }
}

__global__ void k_scan() {
    __shared__ int sc[256];
    int t = threadIdx.x;
    int c = (t < RH) ? g_count[t] : 0;
    sc[t] = c;
    __syncthreads();
    for (int o = 1; o < 256; o <<= 1) {
        int v = (t >= o) ? sc[t - o] : 0;
        __syncthreads();
        sc[t] += v;
        __syncthreads();
    }
    if (t < RH) {
        int excl = sc[t] - c;
        g_offs[t] = excl;
        g_cursor[t] = excl;
        if (t == RH - 1) g_offs[RH] = sc[t];
    }
}

// ---------------- k_scatter: block-aggregated counting sort ----------------
// 98 blocks x 256 threads x 4 edges; smem histogram+rank, <=200 global atomics/block
__global__ void k_scatter(const int* __restrict__ el, const int* __restrict__ etype) {
    __shared__ int hh[RH];
    __shared__ int bb[RH];
    int t = threadIdx.x;
    int e0 = blockIdx.x * 1024;
    for (int i = t; i < RH; i += 256) hh[i] = 0;
    __syncthreads();
    int myrel[4], myrank[4];
    #pragma unroll
    for (int j = 0; j < 4; j++) {
        int e = e0 + t + j * 256;
        if (e < E_NUM) {
            myrel[j] = etype[e];
            myrank[j] = atomicAdd(&hh[myrel[j]], 1);
        } else myrel[j] = -1;
    }
    __syncthreads();
    for (int i = t; i < RH; i += 256)
        if (hh[i]) bb[i] = atomicAdd(&g_cursor[i], hh[i]);
    __syncthreads();
    #pragma unroll
    for (int j = 0; j < 4; j++) {
        int e = e0 + t + j * 256;
        if (myrel[j] >= 0)
            g_edges[bb[myrel[j]] + myrank[j]] = make_int2(el[e], el[E_NUM + e]);
    }
}

// ---------------- k_w: softmax stats + per-edge weights (scores cached in smem) ----------------
__global__ void k_w() {
    __shared__ int2   sed[CAP];
    __shared__ float4 s_e[CAP];
    __shared__ float4 red[256];
    int r = blockIdx.x;
    int t = threadIdx.x;
    int start = g_offs[r], end = g_offs[r + 1];
    int cnt = end - start;
    if (cnt == 0) return;
    float4 tr = make_float4(g_t[0][r], g_t[1][r], g_t[2][r], g_t[3][r]);

    for (int i = t; i < cnt && i < CAP; i += 256) sed[i] = g_edges[start + i];
    __syncthreads();

    // pass 1: compute scores, cache, track max
    float4 mx = make_float4(-1e30f, -1e30f, -1e30f, -1e30f);
    for (int i = t; i < cnt; i += 256) {
        int2 ed = (i < CAP) ? sed[i] : g_edges[start + i];
        float4 ss = g_s[ed.x], st = g_s[ed.y];
        float4 e;
        e.x = lrelu(ss.x + tr.x);
        e.y = lrelu(ss.y + tr.y);
        e.z = lrelu(st.z + tr.z);
        e.w = lrelu(st.w + tr.w);
        if (i < CAP) s_e[i] = e;
        mx.x = fmaxf(mx.x, e.x); mx.y = fmaxf(mx.y, e.y);
        mx.z = fmaxf(mx.z, e.z); mx.w = fmaxf(mx.w, e.w);
    }
    red[t] = mx; __syncthreads();
    for (int s = 128; s > 0; s >>= 1) {
        if (t < s) {
            float4 o = red[t + s];
            red[t].x = fmaxf(red[t].x, o.x); red[t].y = fmaxf(red[t].y, o.y);
            red[t].z = fmaxf(red[t].z, o.z); red[t].w = fmaxf(red[t].w, o.w);
        }
        __syncthreads();
    }
    float4 m = red[0]; __syncthreads();

    // pass 2: exp from cached scores, write weights, sum
    float4 sm = make_float4(0.f, 0.f, 0.f, 0.f);
    for (int i = t; i < cnt; i += 256) {
        float4 e;
        if (i < CAP) e = s_e[i];
        else {
            int2 ed = g_edges[start + i];
            float4 ss = g_s[ed.x], st = g_s[ed.y];
            e.x = lrelu(ss.x + tr.x); e.y = lrelu(ss.y + tr.y);
            e.z = lrelu(st.z + tr.z); e.w = lrelu(st.w + tr.w);
        }
        float4 ex;
        ex.x = expf(e.x - m.x); ex.y = expf(e.y - m.y);
        ex.z = expf(e.z - m.z); ex.w = expf(e.w - m.w);
        g_w[start + i] = ex;
        sm.x += ex.x; sm.y += ex.y; sm.z += ex.z; sm.w += ex.w;
    }
    red[t] = sm; __syncthreads();
    for (int s = 128; s > 0; s >>= 1) {
        if (t < s) {
            float4 o = red[t + s];
            red[t].x += o.x; red[t].y += o.y; red[t].z += o.z; red[t].w += o.w;
        }
        __syncthreads();
    }
    if (t == 0) {
        float4 dn = red[0];
        g_sc[r] = make_float4(1.f / (dn.x + 1e-16f), 1.f / (dn.y + 1e-16f),
                              1.f / (dn.z + 1e-16f), 1.f / (dn.w + 1e-16f));
    }
}

// ---------------- k_agg ----------------
__global__ void k_agg(const float* __restrict__ emb) {
    __shared__ int2   sed[SLICE_MAX];
    __shared__ float4 sw[SLICE_MAX];
    int r = blockIdx.x;
    int t = threadIdx.x;
    int start = g_offs[r], end = g_offs[r + 1];
    int cnt = end - start;
    if (cnt == 0) return;
    int chunk = (cnt + SPLIT - 1) / SPLIT;
    int lo = blockIdx.y * chunk;
    int hi = min(lo + chunk, cnt);
    if (lo >= hi) return;
    int len = hi - lo;
    bool fits = (len <= SLICE_MAX);
    if (fits) {
        for (int i = t; i < len; i += 256) {
            sed[i] = g_edges[start + lo + i];
            sw[i]  = g_w[start + lo + i];
        }
        __syncthreads();
    }
    float4 sc = g_sc[r];
    bool act = (t < DIN);
    float a0 = 0.f, a1 = 0.f, a2 = 0.f, a3 = 0.f;
    #pragma unroll 4
    for (int j = 0; j < len; j++) {
        float4 w = fits ? sw[j] : g_w[start + lo + j];
        int2 ed  = fits ? sed[j] : g_edges[start + lo + j];
        if (act) {
            float x = emb[(long)ed.x * DIN + t];
            float y = emb[(long)ed.y * DIN + t];
            a0 += w.x * x; a1 += w.y * x; a2 += w.z * y; a3 += w.w * y;
        }
    }
    if (act) {
        atomicAdd(&g_agg[0][r][t], a0 * sc.x);
        atomicAdd(&g_agg[1][r][t], a1 * sc.y);
        atomicAdd(&g_agg[2][r][t], a2 * sc.z);
        atomicAdd(&g_agg[3][r][t], a3 * sc.w);
    }
}

__global__ void k_relrep(const float* __restrict__ Wsrc) {
    int r = blockIdx.x;
    int t = threadIdx.x;
    if (r >= RH) {
        for (int o = t; o < 400; o += 256) g_relrep[r * 400 + o] = 0.f;
        return;
    }
    __shared__ float sa[NH][DIN];
    for (int i = t; i < NH * DIN; i += 256) {
        int h = i / DIN, k = i % DIN;
        sa[h][k] = g_agg[h][r][k];
    }
    __syncthreads();
    for (int o = t; o < 400; o += 256) {
        int h = o / DIN, j = o % DIN;
        const float* W1 = Wsrc + h * (DIN * DIN) + j;
        const float* W2 = Wsrc + (h + 2) * (DIN * DIN) + j;
        float d1 = 0.f, d2 = 0.f;
        #pragma unroll 4
        for (int k = 0; k < DIN; k++) {
            d1 += sa[h][k] * W1[k * DIN];
            d2 += sa[h + 2][k] * W2[k * DIN];
        }
        g_relrep[r * 400 + o] = elu(d1) + elu(d2);
    }
}

__global__ void k_relfinal(const float* __restrict__ rel, const float* __restrict__ wrel,
                           float* __restrict__ out_rel) {
    __shared__ float sin_[4][600];
    int r0 = blockIdx.x * 4;
    int t = threadIdx.x;
    for (int i = t; i < 4 * 600; i += 400) {
        int rr = i / 600, k = i % 600;
        sin_[rr][k] = (k < 400) ? g_relrep[(r0 + rr) * 400 + k]
                                : rel[(r0 + rr) * DIN + (k - 400)];
    }
    __syncthreads();
    float acc0 = 0.f, acc1 = 0.f, acc2 = 0.f, acc3 = 0.f;
    #pragma unroll 4
    for (int k = 0; k < 600; k++) {
        float w = wrel[k * 400 + t];
        acc0 += sin_[0][k] * w; acc1 += sin_[1][k] * w;
        acc2 += sin_[2][k] * w; acc3 += sin_[3][k] * w;
    }
    out_rel[(r0 + 0) * 400 + t] = acc0;
    out_rel[(r0 + 1) * 400 + t] = acc1;
    out_rel[(r0 + 2) * 400 + t] = acc2;
    out_rel[(r0 + 3) * 400 + t] = acc3;
}

// ---------------- fused split-bf16 HMMA GEMM (KC=32) ----------------
#define BM 128
#define BN 80
#define KC 32
#define AST 40
#define BST 40

__global__ __launch_bounds__(256) void k_entmm(float* __restrict__ C) {
    __shared__ __align__(16) __nv_bfloat16 sAh[BM * AST];
    __shared__ __align__(16) __nv_bfloat16 sAl[BM * AST];
    __shared__ __align__(16) __nv_bfloat16 sBh[BN * BST];
    __shared__ __align__(16) __nv_bfloat16 sBl[BN * BST];
    const int tid = threadIdx.x;
    const int warp = tid >> 5, lane = tid & 31;
    const int wm = warp & 3;
    const int wn = warp >> 2;
    const int bm = blockIdx.y * BM;
    const int bn = blockIdx.x * BN;

    float acc[2][5][4];
    #pragma unroll
    for (int i = 0; i < 2; i++)
        #pragma unroll
        for (int j = 0; j < 5; j++)
            #pragma unroll
            for (int c = 0; c < 4; c++) acc[i][j][c] = 0.f;

    const uint32_t sAh32 = smem_u32(sAh), sAl32 = smem_u32(sAl);
    const uint32_t sBh32 = smem_u32(sBh), sBl32 = smem_u32(sBl);
    const int a_row = wm * 32 + (lane & 15);
    const int a_koff = (lane >> 4) * 8;
    const int b_row = wn * 40 + (lane & 7);
    const int b_koff = ((lane >> 3) & 1) * 8;

    #pragma unroll 1
    for (int kc = 0; kc < 224; kc += KC) {
        #pragma unroll
        for (int i = 0; i < 2; i++) {
            int idx = tid + i * 256;
            int row = idx >> 2, j = idx & 3;
            int grow = bm + row;
            int4 vh = make_int4(0, 0, 0, 0), vl = make_int4(0, 0, 0, 0);
            if (grow < N_NODES) {
                vh = *(const int4*)(g_Ah + (long)grow * KPAD + kc + j * 8);
                vl = *(const int4*)(g_Al + (long)grow * KPAD + kc + j * 8);
            }
            *(int4*)(sAh + row * AST + j * 8) = vh;
            *(int4*)(sAl + row * AST + j * 8) = vl;
        }
        for (int idx = tid; idx < 320; idx += 256) {
            int row = idx >> 2, j = idx & 3;
            *(int4*)(sBh + row * BST + j * 8) =
                *(const int4*)(g_Bh + (long)(bn + row) * KPAD + kc + j * 8);
            *(int4*)(sBl + row * BST + j * 8) =
                *(const int4*)(g_Bl + (long)(bn + row) * KPAD + kc + j * 8);
        }
        __syncthreads();

        int nks = (kc == 192) ? 1 : 2;
        for (int ks = 0; ks < nks; ks++) {
            int k0 = ks * 16;
            uint32_t afh[2][4], afl[2][4], bfh[5][2], bfl[5][2];
            #pragma unroll
            for (int mf = 0; mf < 2; mf++) {
                ldm_x4(afh[mf], sAh32 + ((a_row + mf * 16) * AST + k0 + a_koff) * 2);
                ldm_x4(afl[mf], sAl32 + ((a_row + mf * 16) * AST + k0 + a_koff) * 2);
            }
            #pragma unroll
            for (int nf = 0; nf < 5; nf++) {
                ldm_x2(bfh[nf], sBh32 + ((b_row + nf * 8) * BST + k0 + b_koff) * 2);
                ldm_x2(bfl[nf], sBl32 + ((b_row + nf * 8) * BST + k0 + b_koff) * 2);
            }
            #pragma unroll
            for (int mf = 0; mf < 2; mf++)
                #pragma unroll
                for (int nf = 0; nf < 5; nf++) {
                    mma16816(acc[mf][nf], afh[mf], bfh[nf]);
                    mma16816(acc[mf][nf], afl[mf], bfh[nf]);
                    mma16816(acc[mf][nf], afh[mf], bfl[nf]);
                }
        }
        __syncthreads();
    }

    const int m_base = bm + wm * 32 + (lane >> 2);
    const int n_base = bn + wn * 40 + (lane & 3) * 2;
    #pragma unroll
    for (int mf = 0; mf < 2; mf++) {
        #pragma unroll
        for (int nf = 0; nf < 5; nf++) {
            int n = n_base + nf * 8;
            int m0 = m_base + mf * 16;
            if (m0 < N_NODES)
                *(float2*)&C[(long)m0 * 400 + n] = make_float2(acc[mf][nf][0], acc[mf][nf][1]);
            if (m0 + 8 < N_NODES)
                *(float2*)&C[(long)(m0 + 8) * 400 + n] = make_float2(acc[mf][nf][2], acc[mf][nf][3]);
        }
    }
}

// ---------------- launch: fork k_entmm onto a side stream ----------------
extern "C" void kernel_launch(void* const* d_in, const int* in_sizes, int n_in,
                              void* d_out, int out_size) {
    const int*   el    = (const int*)d_in[0];
    const int*   et    = (const int*)d_in[1];
    const float* emb   = (const float*)d_in[2];
    const float* rel   = (const float*)d_in[3];
    const float* Wsrc  = (const float*)d_in[4];
    const float* Wdst  = (const float*)d_in[5];
    const float* avec  = (const float*)d_in[6];
    const float* wrel  = (const float*)d_in[7];
    const float* Wproj = (const float*)d_in[8];
    float* out     = (float*)d_out;
    float* out_ent = out;
    float* out_rel = out + (long)N_NODES * 400;

    cudaStream_t s2;
    cudaEvent_t ev_fork, ev_join;
    cudaStreamCreateWithFlags(&s2, cudaStreamNonBlocking);
    cudaEventCreateWithFlags(&ev_fork, cudaEventDisableTiming);
    cudaEventCreateWithFlags(&ev_join, cudaEventDisableTiming);

    k_init<<<1225, 256>>>(Wsrc, Wdst, avec, Wproj);
    k_stcvt<<<5198, 256>>>(emb, rel, et);

    // fork: GEMM depends only on k_init/k_stcvt outputs
    cudaEventRecord(ev_fork, 0);
    cudaStreamWaitEvent(s2, ev_fork, 0);
    k_entmm<<<dim3(5, 313), 256, 0, s2>>>(out_ent);
    cudaEventRecord(ev_join, s2);

    // edge pipeline on main stream, overlapped with GEMM
    k_scan<<<1, 256>>>();
    k_scatter<<<98, 256>>>(el, et);
    k_w<<<RH, 256>>>();
    k_agg<<<dim3(RH, SPLIT), 256>>>(emb);
    k_relrep<<<R_NUM, 256>>>(Wsrc);
    k_relfinal<<<100, 400>>>(rel, wrel, out_rel);

    cudaStreamWaitEvent(0, ev_join, 0);
}

// round 9
// speedup vs baseline: 1.4363x; 1.1587x over previous
#include <cuda_runtime.h>
#include <cuda_bf16.h>
#include <cstdint>

#define E_NUM   100000
#define N_NODES 40000
#define R_NUM   400
#define RH      200
#define DIN     200
#define NH      4
#define CAP     1024
#define SPLIT   8
#define SLICE_MAX 256
#define KPAD    224

// ---------------- device scratch ----------------
__device__ float  g_u[NH][DIN];
__device__ float  g_v[NH][DIN];
__device__ float  g_t[NH][RH];
__device__ float4 g_s[N_NODES];
__device__ int    g_count[RH];
__device__ int    g_offs[RH + 1];
__device__ int    g_cursor[RH];
__device__ int2   g_edges[E_NUM];
__device__ float4 g_w[E_NUM];
__device__ float4 g_sc[RH];
__device__ float  g_agg[NH][RH][DIN];
__device__ __align__(16) __nv_bfloat16 g_Ah[(size_t)N_NODES * KPAD];
__device__ __align__(16) __nv_bfloat16 g_Al[(size_t)N_NODES * KPAD];
__device__ __align__(16) __nv_bfloat16 g_Bh[400 * KPAD];
__device__ __align__(16) __nv_bfloat16 g_Bl[400 * KPAD];

// ---------------- helpers ----------------
__device__ __forceinline__ float lrelu(float x) { return x >= 0.f ? x : 0.2f * x; }
__device__ __forceinline__ float elu(float x)   { return x > 0.f ? x : expm1f(x); }

__device__ __forceinline__ float warp_sum(float v) {
    #pragma unroll
    for (int o = 16; o; o >>= 1) v += __shfl_down_sync(0xffffffffu, v, o);
    return v;
}

__device__ __forceinline__ uint32_t smem_u32(const void* p) {
    uint32_t a;
    asm("{ .reg .u64 t; cvta.to.shared.u64 t, %1; cvt.u32.u64 %0, t; }" : "=r"(a) : "l"(p));
    return a;
}

__device__ __forceinline__ uint32_t pack_bf2(float a, float b) {
    __nv_bfloat162 t(__float2bfloat16(a), __float2bfloat16(b));
    return *(uint32_t*)&t;
}

__device__ __forceinline__ void ldm_x4(uint32_t* r, uint32_t addr) {
    asm volatile("ldmatrix.sync.aligned.m8n8.x4.shared.b16 {%0,%1,%2,%3}, [%4];"
                 : "=r"(r[0]), "=r"(r[1]), "=r"(r[2]), "=r"(r[3]) : "r"(addr));
}
__device__ __forceinline__ void ldm_x2(uint32_t* r, uint32_t addr) {
    asm volatile("ldmatrix.sync.aligned.m8n8.x2.shared.b16 {%0,%1}, [%2];"
                 : "=r"(r[0]), "=r"(r[1]) : "r"(addr));
}
__device__ __forceinline__ void mma16816(float* d, const uint32_t* a, const uint32_t* b) {
    asm volatile("mma.sync.aligned.m16n8k16.row.col.f32.bf16.bf16.f32 "
                 "{%0,%1,%2,%3}, {%4,%5,%6,%7}, {%8,%9}, {%0,%1,%2,%3};"
                 : "+f"(d[0]), "+f"(d[1]), "+f"(d[2]), "+f"(d[3])
                 : "r"(a[0]), "r"(a[1]), "r"(a[2]), "r"(a[3]), "r"(b[0]), "r"(b[1]));
}

// ---------------- k_init: uv + zero(agg,count,cursor) + cvtB ----------------
__global__ void k_init(const float* __restrict__ Wsrc, const float* __restrict__ Wdst,
                       const float* __restrict__ avec, const float* __restrict__ Wproj) {
    int b = blockIdx.x;
    if (b < 200) {
        int w = b * 8 + (threadIdx.x >> 5);
        int lane = threadIdx.x & 31;
        int side = w / 800;
        int h = (w / 200) % 4;
        int i = w % 200;
        const float* W = (side == 0 ? Wsrc : Wdst) + h * DIN * DIN + i * DIN;
        const float* a = avec + h * 400 + side * 200;
        float acc = 0.f;
        for (int j = lane; j < DIN; j += 32) acc += W[j] * a[j];
        acc = warp_sum(acc);
        if (lane == 0) {
            if (side == 0) g_u[h][i] = acc; else g_v[h][i] = acc;
        }
    } else if (b < 825) {
        int i = (b - 200) * 256 + threadIdx.x;
        if (i < NH * RH * DIN) ((float*)g_agg)[i] = 0.f;
        if (b == 200 && threadIdx.x < RH) {
            g_count[threadIdx.x] = 0;
            g_cursor[threadIdx.x] = 0;
        }
    } else {
        int n = b - 825;
        int k = threadIdx.x;
        if (k < KPAD) {
            float x = (k < 200) ? Wproj[k * 400 + n] : 0.f;
            __nv_bfloat16 h = __float2bfloat16(x);
            g_Bh[n * KPAD + k] = h;
            g_Bl[n * KPAD + k] = __float2bfloat16(x - __bfloat162float(h));
        }
    }
}

// ---------------- k_stcvt: s-scores + cvtA (one emb read) + t + hist ----------------
__global__ void k_stcvt(const float* __restrict__ emb, const float* __restrict__ rel,
                        const int* __restrict__ etype) {
    __shared__ float4 su4[NH * 50];
    __shared__ int hh[RH];
    int b = blockIdx.x;
    if (b < 5000) {
        for (int i = threadIdx.x; i < NH * 50; i += 256)
            su4[i] = ((const float4*)g_u)[i];
        __syncthreads();
        int n = b * 8 + (threadIdx.x >> 5);
        int l = threadIdx.x & 31;
        const float4* row4 = (const float4*)(emb + (long)n * DIN);
        float4 x = row4[l];
        float4 u0 = su4[0 * 50 + l], u1 = su4[1 * 50 + l];
        float4 u2 = su4[2 * 50 + l], u3 = su4[3 * 50 + l];
        float a0 = x.x * u0.x + x.y * u0.y + x.z * u0.z + x.w * u0.w;
        float a1 = x.x * u1.x + x.y * u1.y + x.z * u1.z + x.w * u1.w;
        float a2 = x.x * u2.x + x.y * u2.y + x.z * u2.z + x.w * u2.w;
        float a3 = x.x * u3.x + x.y * u3.y + x.z * u3.z + x.w * u3.w;
        {
            uint2 vh, vl;
            vh.x = pack_bf2(x.x, x.y); vh.y = pack_bf2(x.z, x.w);
            float rx = x.x - __bfloat162float(__float2bfloat16(x.x));
            float ry = x.y - __bfloat162float(__float2bfloat16(x.y));
            float rz = x.z - __bfloat162float(__float2bfloat16(x.z));
            float rw = x.w - __bfloat162float(__float2bfloat16(x.w));
            vl.x = pack_bf2(rx, ry); vl.y = pack_bf2(rz, rw);
            *(uint2*)&g_Ah[(long)n * KPAD + 4 * l] = vh;
            *(uint2*)&g_Al[(long)n * KPAD + 4 * l] = vl;
        }
        if (l < 18) {
            float4 y = row4[l + 32];
            float4 v0 = su4[0 * 50 + l + 32], v1 = su4[1 * 50 + l + 32];
            float4 v2 = su4[2 * 50 + l + 32], v3 = su4[3 * 50 + l + 32];
            a0 += y.x * v0.x + y.y * v0.y + y.z * v0.z + y.w * v0.w;
            a1 += y.x * v1.x + y.y * v1.y + y.z * v1.z + y.w * v1.w;
            a2 += y.x * v2.x + y.y * v2.y + y.z * v2.z + y.w * v2.w;
            a3 += y.x * v3.x + y.y * v3.y + y.z * v3.z + y.w * v3.w;
            uint2 vh, vl;
            vh.x = pack_bf2(y.x, y.y); vh.y = pack_bf2(y.z, y.w);
            float rx = y.x - __bfloat162float(__float2bfloat16(y.x));
            float ry = y.y - __bfloat162float(__float2bfloat16(y.y));
            float rz = y.z - __bfloat162float(__float2bfloat16(y.z));
            float rw = y.w - __bfloat162float(__float2bfloat16(y.w));
            vl.x = pack_bf2(rx, ry); vl.y = pack_bf2(rz, rw);
            *(uint2*)&g_Ah[(long)n * KPAD + 128 + 4 * l] = vh;
            *(uint2*)&g_Al[(long)n * KPAD + 128 + 4 * l] = vl;
        } else if (l < 24) {
            uint2 z = make_uint2(0u, 0u);
            *(uint2*)&g_Ah[(long)n * KPAD + 128 + 4 * l] = z;
            *(uint2*)&g_Al[(long)n * KPAD + 128 + 4 * l] = z;
        }
        a0 = warp_sum(a0); a1 = warp_sum(a1); a2 = warp_sum(a2); a3 = warp_sum(a3);
        if (l == 0) g_s[n] = make_float4(a0, a1, a2, a3);
    } else if (b < 5100) {
        int w = (b - 5000) * 8 + (threadIdx.x >> 5);
        int lane = threadIdx.x & 31;
        int h = w / RH;
        int r = w % RH;
        const float* row = rel + (r + (h < 2 ? RH : 0)) * DIN;
        float acc = 0.f;
        for (int j = lane; j < DIN; j += 32) acc += row[j] * g_v[h][j];
        acc = warp_sum(acc);
        if (lane == 0) g_t[h][r] = acc;
    } else {
        for (int i = threadIdx.x; i < RH; i += 256) hh[i] = 0;
        __syncthreads();
        int base = (b - 5100) * 1024;
        for (int i = threadIdx.x; i < 1024; i += 256) {
            int e = base + i;
            if (e < E_NUM) atomicAdd(&hh[etype[e]], 1);
        }
        __syncthreads();
        for (int i = threadIdx.x; i < RH; i += 256)
            if (hh[i]) atomicAdd(&g_count[i], hh[i]);
    }
}

// ---------------- k_scatter: local scan + block-aggregated counting sort ----------------
__global__ void k_scatter(const int* __restrict__ el, const int* __restrict__ etype) {
    __shared__ int sc[256];
    __shared__ int hh[RH];
    __shared__ int bb[RH];
    int t = threadIdx.x;
    int c = (t < RH) ? g_count[t] : 0;
    sc[t] = c;
    __syncthreads();
    for (int o = 1; o < 256; o <<= 1) {
        int v = (t >= o) ? sc[t - o] : 0;
        __syncthreads();
        sc[t] += v;
        __syncthreads();
    }
    int offs_t = sc[t] - c;
    if (blockIdx.x == 0 && t < RH) {
        g_offs[t] = offs_t;
        if (t == RH - 1) g_offs[RH] = sc[t];
    }
    if (t < RH) hh[t] = 0;
    __syncthreads();
    int e0 = blockIdx.x * 1024;
    int myrel[4], myrank[4];
    #pragma unroll
    for (int j = 0; j < 4; j++) {
        int e = e0 + t + j * 256;
        if (e < E_NUM) {
            myrel[j] = etype[e];
            myrank[j] = atomicAdd(&hh[myrel[j]], 1);
        } else myrel[j] = -1;
    }
    __syncthreads();
    if (t < RH) {
        int cnt = hh[t];
        if (cnt) bb[t] = offs_t + atomicAdd(&g_cursor[t], cnt);
    }
    __syncthreads();
    #pragma unroll
    for (int j = 0; j < 4; j++) {
        int e = e0 + t + j * 256;
        if (myrel[j] >= 0)
            g_edges[bb[myrel[j]] + myrank[j]] = make_int2(el[e], el[E_NUM + e]);
    }
}

// ---------------- k_w: softmax stats + per-edge weights ----------------
__global__ void k_w() {
    __shared__ int2   sed[CAP];
    __shared__ float4 s_e[CAP];
    __shared__ float4 red[256];
    int r = blockIdx.x;
    int t = threadIdx.x;
    int start = g_offs[r], end = g_offs[r + 1];
    int cnt = end - start;
    if (cnt == 0) return;
    float4 tr = make_float4(g_t[0][r], g_t[1][r], g_t[2][r], g_t[3][r]);

    for (int i = t; i < cnt && i < CAP; i += 256) sed[i] = g_edges[start + i];
    __syncthreads();

    float4 mx = make_float4(-1e30f, -1e30f, -1e30f, -1e30f);
    for (int i = t; i < cnt; i += 256) {
        int2 ed = (i < CAP) ? sed[i] : g_edges[start + i];
        float4 ss = g_s[ed.x], st = g_s[ed.y];
        float4 e;
        e.x = lrelu(ss.x + tr.x);
        e.y = lrelu(ss.y + tr.y);
        e.z = lrelu(st.z + tr.z);
        e.w = lrelu(st.w + tr.w);
        if (i < CAP) s_e[i] = e;
        mx.x = fmaxf(mx.x, e.x); mx.y = fmaxf(mx.y, e.y);
        mx.z = fmaxf(mx.z, e.z); mx.w = fmaxf(mx.w, e.w);
    }
    red[t] = mx; __syncthreads();
    for (int s = 128; s > 0; s >>= 1) {
        if (t < s) {
            float4 o = red[t + s];
            red[t].x = fmaxf(red[t].x, o.x); red[t].y = fmaxf(red[t].y, o.y);
            red[t].z = fmaxf(red[t].z, o.z); red[t].w = fmaxf(red[t].w, o.w);
        }
        __syncthreads();
    }
    float4 m = red[0]; __syncthreads();

    float4 sm = make_float4(0.f, 0.f, 0.f, 0.f);
    for (int i = t; i < cnt; i += 256) {
        float4 e;
        if (i < CAP) e = s_e[i];
        else {
            int2 ed = g_edges[start + i];
            float4 ss = g_s[ed.x], st = g_s[ed.y];
            e.x = lrelu(ss.x + tr.x); e.y = lrelu(ss.y + tr.y);
            e.z = lrelu(st.z + tr.z); e.w = lrelu(st.w + tr.w);
        }
        float4 ex;
        ex.x = expf(e.x - m.x); ex.y = expf(e.y - m.y);
        ex.z = expf(e.z - m.z); ex.w = expf(e.w - m.w);
        g_w[start + i] = ex;
        sm.x += ex.x; sm.y += ex.y; sm.z += ex.z; sm.w += ex.w;
    }
    red[t] = sm; __syncthreads();
    for (int s = 128; s > 0; s >>= 1) {
        if (t < s) {
            float4 o = red[t + s];
            red[t].x += o.x; red[t].y += o.y; red[t].z += o.z; red[t].w += o.w;
        }
        __syncthreads();
    }
    if (t == 0) {
        float4 dn = red[0];
        g_sc[r] = make_float4(1.f / (dn.x + 1e-16f), 1.f / (dn.y + 1e-16f),
                              1.f / (dn.z + 1e-16f), 1.f / (dn.w + 1e-16f));
    }
}

// ---------------- k_agg ----------------
__global__ void k_agg(const float* __restrict__ emb) {
    __shared__ int2   sed[SLICE_MAX];
    __shared__ float4 sw[SLICE_MAX];
    int r = blockIdx.x;
    int t = threadIdx.x;
    int start = g_offs[r], end = g_offs[r + 1];
    int cnt = end - start;
    if (cnt == 0) return;
    int chunk = (cnt + SPLIT - 1) / SPLIT;
    int lo = blockIdx.y * chunk;
    int hi = min(lo + chunk, cnt);
    if (lo >= hi) return;
    int len = hi - lo;
    bool fits = (len <= SLICE_MAX);
    if (fits) {
        for (int i = t; i < len; i += 256) {
            sed[i] = g_edges[start + lo + i];
            sw[i]  = g_w[start + lo + i];
        }
        __syncthreads();
    }
    float4 sc = g_sc[r];
    bool act = (t < DIN);
    float a0 = 0.f, a1 = 0.f, a2 = 0.f, a3 = 0.f;
    #pragma unroll 4
    for (int j = 0; j < len; j++) {
        float4 w = fits ? sw[j] : g_w[start + lo + j];
        int2 ed  = fits ? sed[j] : g_edges[start + lo + j];
        if (act) {
            float x = emb[(long)ed.x * DIN + t];
            float y = emb[(long)ed.y * DIN + t];
            a0 += w.x * x; a1 += w.y * x; a2 += w.z * y; a3 += w.w * y;
        }
    }
    if (act) {
        atomicAdd(&g_agg[0][r][t], a0 * sc.x);
        atomicAdd(&g_agg[1][r][t], a1 * sc.y);
        atomicAdd(&g_agg[2][r][t], a2 * sc.z);
        atomicAdd(&g_agg[3][r][t], a3 * sc.w);
    }
}

// ---------------- k_rel: fused relrep + relfinal, 8 relations/block ----------------
// grid 50: r0 = b*8; rows >= RH use the zero path (relrep == 0 there)
__global__ __launch_bounds__(400) void k_rel(const float* __restrict__ Wsrc,
                                             const float* __restrict__ rel,
                                             const float* __restrict__ wrel,
                                             float* __restrict__ out_rel) {
    __shared__ float sa[8][NH][DIN];     // 25.6 KB
    __shared__ float sin_[8][600];       // 19.2 KB
    int b = blockIdx.x;
    int t = threadIdx.x;                 // 0..399
    int r0 = b * 8;
    bool zero = (r0 >= RH);

    if (!zero) {
        for (int i = t; i < 8 * NH * DIN; i += 400) {
            int rr = i / (NH * DIN), rem = i % (NH * DIN);
            sa[rr][rem / DIN][rem % DIN] = g_agg[rem / DIN][r0 + rr][rem % DIN];
        }
        __syncthreads();
        int h = t / DIN, j = t % DIN;
        const float* W1 = Wsrc + h * DIN * DIN + j;
        const float* W2 = Wsrc + (h + 2) * DIN * DIN + j;
        float d1[8], d2[8];
        #pragma unroll
        for (int rr = 0; rr < 8; rr++) { d1[rr] = 0.f; d2[rr] = 0.f; }
        for (int k4 = 0; k4 < DIN; k4 += 4) {
            float w1a = W1[(k4 + 0) * DIN], w1b = W1[(k4 + 1) * DIN];
            float w1c = W1[(k4 + 2) * DIN], w1d = W1[(k4 + 3) * DIN];
            float w2a = W2[(k4 + 0) * DIN], w2b = W2[(k4 + 1) * DIN];
            float w2c = W2[(k4 + 2) * DIN], w2d = W2[(k4 + 3) * DIN];
            #pragma unroll
            for (int rr = 0; rr < 8; rr++) {
                float4 a1v = *(const float4*)&sa[rr][h][k4];
                float4 a2v = *(const float4*)&sa[rr][h + 2][k4];
                d1[rr] += a1v.x * w1a + a1v.y * w1b + a1v.z * w1c + a1v.w * w1d;
                d2[rr] += a2v.x * w2a + a2v.y * w2b + a2v.z * w2c + a2v.w * w2d;
            }
        }
        #pragma unroll
        for (int rr = 0; rr < 8; rr++)
            sin_[rr][t] = elu(d1[rr]) + elu(d2[rr]);
        for (int i = t; i < 8 * DIN; i += 400) {
            int rr = i / DIN, k = i % DIN;
            sin_[rr][400 + k] = rel[(r0 + rr) * DIN + k];
        }
        __syncthreads();
    } else {
        for (int i = t; i < 8 * 400; i += 400) {
            int rr = i / 400, k = i % 400;
            sin_[rr][k] = 0.f;
        }
        for (int i = t; i < 8 * DIN; i += 400) {
            int rr = i / DIN, k = i % DIN;
            sin_[rr][400 + k] = rel[(r0 + rr) * DIN + k];
        }
        __syncthreads();
    }

    // relfinal: out_rel[r0+rr][t] = sum_k sin_[rr][k] * wrel[k*400+t]
    float acc[8];
    #pragma unroll
    for (int rr = 0; rr < 8; rr++) acc[rr] = 0.f;
    for (int k4 = 0; k4 < 600; k4 += 4) {
        float wa = wrel[(k4 + 0) * 400 + t];
        float wb = wrel[(k4 + 1) * 400 + t];
        float wc = wrel[(k4 + 2) * 400 + t];
        float wd = wrel[(k4 + 3) * 400 + t];
        #pragma unroll
        for (int rr = 0; rr < 8; rr++) {
            float4 s = *(const float4*)&sin_[rr][k4];
            acc[rr] += s.x * wa + s.y * wb + s.z * wc + s.w * wd;
        }
    }
    #pragma unroll
    for (int rr = 0; rr < 8; rr++)
        out_rel[(r0 + rr) * 400 + t] = acc[rr];
}

// ---------------- fused split-bf16 HMMA GEMM (KC=32) ----------------
#define BM 128
#define BN 80
#define KC 32
#define AST 40
#define BST 40

__global__ __launch_bounds__(256) void k_entmm(float* __restrict__ C) {
    __shared__ __align__(16) __nv_bfloat16 sAh[BM * AST];
    __shared__ __align__(16) __nv_bfloat16 sAl[BM * AST];
    __shared__ __align__(16) __nv_bfloat16 sBh[BN * BST];
    __shared__ __align__(16) __nv_bfloat16 sBl[BN * BST];
    const int tid = threadIdx.x;
    const int warp = tid >> 5, lane = tid & 31;
    const int wm = warp & 3;
    const int wn = warp >> 2;
    const int bm = blockIdx.y * BM;
    const int bn = blockIdx.x * BN;

    float acc[2][5][4];
    #pragma unroll
    for (int i = 0; i < 2; i++)
        #pragma unroll
        for (int j = 0; j < 5; j++)
            #pragma unroll
            for (int c = 0; c < 4; c++) acc[i][j][c] = 0.f;

    const uint32_t sAh32 = smem_u32(sAh), sAl32 = smem_u32(sAl);
    const uint32_t sBh32 = smem_u32(sBh), sBl32 = smem_u32(sBl);
    const int a_row = wm * 32 + (lane & 15);
    const int a_koff = (lane >> 4) * 8;
    const int b_row = wn * 40 + (lane & 7);
    const int b_koff = ((lane >> 3) & 1) * 8;

    #pragma unroll 1
    for (int kc = 0; kc < 224; kc += KC) {
        #pragma unroll
        for (int i = 0; i < 2; i++) {
            int idx = tid + i * 256;
            int row = idx >> 2, j = idx & 3;
            int grow = bm + row;
            int4 vh = make_int4(0, 0, 0, 0), vl = make_int4(0, 0, 0, 0);
            if (grow < N_NODES) {
                vh = *(const int4*)(g_Ah + (long)grow * KPAD + kc + j * 8);
                vl = *(const int4*)(g_Al + (long)grow * KPAD + kc + j * 8);
            }
            *(int4*)(sAh + row * AST + j * 8) = vh;
            *(int4*)(sAl + row * AST + j * 8) = vl;
        }
        for (int idx = tid; idx < 320; idx += 256) {
            int row = idx >> 2, j = idx & 3;
            *(int4*)(sBh + row * BST + j * 8) =
                *(const int4*)(g_Bh + (long)(bn + row) * KPAD + kc + j * 8);
            *(int4*)(sBl + row * BST + j * 8) =
                *(const int4*)(g_Bl + (long)(bn + row) * KPAD + kc + j * 8);
        }
        __syncthreads();

        int nks = (kc == 192) ? 1 : 2;
        for (int ks = 0; ks < nks; ks++) {
            int k0 = ks * 16;
            uint32_t afh[2][4], afl[2][4], bfh[5][2], bfl[5][2];
            #pragma unroll
            for (int mf = 0; mf < 2; mf++) {
                ldm_x4(afh[mf], sAh32 + ((a_row + mf * 16) * AST + k0 + a_koff) * 2);
                ldm_x4(afl[mf], sAl32 + ((a_row + mf * 16) * AST + k0 + a_koff) * 2);
            }
            #pragma unroll
            for (int nf = 0; nf < 5; nf++) {
                ldm_x2(bfh[nf], sBh32 + ((b_row + nf * 8) * BST + k0 + b_koff) * 2);
                ldm_x2(bfl[nf], sBl32 + ((b_row + nf * 8) * BST + k0 + b_koff) * 2);
            }
            #pragma unroll
            for (int mf = 0; mf < 2; mf++)
                #pragma unroll
                for (int nf = 0; nf < 5; nf++) {
                    mma16816(acc[mf][nf], afh[mf], bfh[nf]);
                    mma16816(acc[mf][nf], afl[mf], bfh[nf]);
                    mma16816(acc[mf][nf], afh[mf], bfl[nf]);
                }
        }
        __syncthreads();
    }

    const int m_base = bm + wm * 32 + (lane >> 2);
    const int n_base = bn + wn * 40 + (lane & 3) * 2;
    #pragma unroll
    for (int mf = 0; mf < 2; mf++) {
        #pragma unroll
        for (int nf = 0; nf < 5; nf++) {
            int n = n_base + nf * 8;
            int m0 = m_base + mf * 16;
            if (m0 < N_NODES)
                *(float2*)&C[(long)m0 * 400 + n] = make_float2(acc[mf][nf][0], acc[mf][nf][1]);
            if (m0 + 8 < N_NODES)
                *(float2*)&C[(long)(m0 + 8) * 400 + n] = make_float2(acc[mf][nf][2], acc[mf][nf][3]);
        }
    }
}

// ---------------- launch ----------------
extern "C" void kernel_launch(void* const* d_in, const int* in_sizes, int n_in,
                              void* d_out, int out_size) {
    const int*   el    = (const int*)d_in[0];
    const int*   et    = (const int*)d_in[1];
    const float* emb   = (const float*)d_in[2];
    const float* rel   = (const float*)d_in[3];
    const float* Wsrc  = (const float*)d_in[4];
    const float* Wdst  = (const float*)d_in[5];
    const float* avec  = (const float*)d_in[6];
    const float* wrel  = (const float*)d_in[7];
    const float* Wproj = (const float*)d_in[8];
    float* out     = (float*)d_out;
    float* out_ent = out;
    float* out_rel = out + (long)N_NODES * 400;

    cudaStream_t s2;
    cudaEvent_t ev_fork, ev_join;
    cudaStreamCreateWithFlags(&s2, cudaStreamNonBlocking);
    cudaEventCreateWithFlags(&ev_fork, cudaEventDisableTiming);
    cudaEventCreateWithFlags(&ev_join, cudaEventDisableTiming);

    k_init<<<1225, 256>>>(Wsrc, Wdst, avec, Wproj);
    k_stcvt<<<5198, 256>>>(emb, rel, et);

    // fork: GEMM depends only on k_init/k_stcvt outputs
    cudaEventRecord(ev_fork, 0);
    cudaStreamWaitEvent(s2, ev_fork, 0);
    k_entmm<<<dim3(5, 313), 256, 0, s2>>>(out_ent);
    cudaEventRecord(ev_join, s2);

    // edge pipeline on main stream, overlapped with GEMM
    k_scatter<<<98, 256>>>(el, et);
    k_w<<<RH, 256>>>();
    k_agg<<<dim3(RH, SPLIT), 256>>>(emb);
    k_rel<<<50, 400>>>(Wsrc, rel, wrel, out_rel);

    cudaStreamWaitEvent(0, ev_join, 0);
}

// round 10
// speedup vs baseline: 1.4406x; 1.0030x over previous
#include <cuda_runtime.h>
#include <cuda_bf16.h>
#include <cstdint>

#define E_NUM   100000
#define N_NODES 40000
#define R_NUM   400
#define RH      200
#define DIN     200
#define NH      4
#define CAP     1024
#define SPLIT   8
#define SLICE_MAX 256
#define KPAD    224

// ---------------- device scratch ----------------
__device__ float  g_u[NH][DIN];
__device__ float  g_v[NH][DIN];
__device__ float  g_t[NH][RH];
__device__ float4 g_s[N_NODES];
__device__ int    g_count[RH];
__device__ int    g_offs[RH + 1];
__device__ int    g_cursor[RH];
__device__ int2   g_edges[E_NUM];
__device__ float4 g_w[E_NUM];
__device__ float4 g_sc[RH];
__device__ float  g_agg[NH][RH][DIN];
__device__ __align__(16) __nv_bfloat16 g_Ah[(size_t)N_NODES * KPAD];
__device__ __align__(16) __nv_bfloat16 g_Al[(size_t)N_NODES * KPAD];
__device__ __align__(16) __nv_bfloat16 g_Bh[400 * KPAD];
__device__ __align__(16) __nv_bfloat16 g_Bl[400 * KPAD];

// ---------------- helpers ----------------
__device__ __forceinline__ float lrelu(float x) { return x >= 0.f ? x : 0.2f * x; }
__device__ __forceinline__ float elu(float x)   { return x > 0.f ? x : expm1f(x); }

__device__ __forceinline__ float warp_sum(float v) {
    #pragma unroll
    for (int o = 16; o; o >>= 1) v += __shfl_down_sync(0xffffffffu, v, o);
    return v;
}

__device__ __forceinline__ uint32_t smem_u32(const void* p) {
    uint32_t a;
    asm("{ .reg .u64 t; cvta.to.shared.u64 t, %1; cvt.u32.u64 %0, t; }" : "=r"(a) : "l"(p));
    return a;
}

__device__ __forceinline__ uint32_t pack_bf2(float a, float b) {
    __nv_bfloat162 t(__float2bfloat16(a), __float2bfloat16(b));
    return *(uint32_t*)&t;
}

__device__ __forceinline__ void ldm_x4(uint32_t* r, uint32_t addr) {
    asm volatile("ldmatrix.sync.aligned.m8n8.x4.shared.b16 {%0,%1,%2,%3}, [%4];"
                 : "=r"(r[0]), "=r"(r[1]), "=r"(r[2]), "=r"(r[3]) : "r"(addr));
}
__device__ __forceinline__ void ldm_x2(uint32_t* r, uint32_t addr) {
    asm volatile("ldmatrix.sync.aligned.m8n8.x2.shared.b16 {%0,%1}, [%2];"
                 : "=r"(r[0]), "=r"(r[1]) : "r"(addr));
}
__device__ __forceinline__ void mma16816(float* d, const uint32_t* a, const uint32_t* b) {
    asm volatile("mma.sync.aligned.m16n8k16.row.col.f32.bf16.bf16.f32 "
                 "{%0,%1,%2,%3}, {%4,%5,%6,%7}, {%8,%9}, {%0,%1,%2,%3};"
                 : "+f"(d[0]), "+f"(d[1]), "+f"(d[2]), "+f"(d[3])
                 : "r"(a[0]), "r"(a[1]), "r"(a[2]), "r"(a[3]), "r"(b[0]), "r"(b[1]));
}

// ---------------- k_init: uv + zero(agg,count,cursor) ----------------
__global__ void k_init(const float* __restrict__ Wsrc, const float* __restrict__ Wdst,
                       const float* __restrict__ avec) {
    int b = blockIdx.x;
    if (b < 200) {
        int w = b * 8 + (threadIdx.x >> 5);
        int lane = threadIdx.x & 31;
        int side = w / 800;
        int h = (w / 200) % 4;
        int i = w % 200;
        const float* W = (side == 0 ? Wsrc : Wdst) + h * DIN * DIN + i * DIN;
        const float* a = avec + h * 400 + side * 200;
        float acc = 0.f;
        for (int j = lane; j < DIN; j += 32) acc += W[j] * a[j];
        acc = warp_sum(acc);
        if (lane == 0) {
            if (side == 0) g_u[h][i] = acc; else g_v[h][i] = acc;
        }
    } else {
        int i = (b - 200) * 256 + threadIdx.x;
        if (i < NH * RH * DIN) ((float*)g_agg)[i] = 0.f;
        if (b == 200 && threadIdx.x < RH) {
            g_count[threadIdx.x] = 0;
            g_cursor[threadIdx.x] = 0;
        }
    }
}

// ---------------- k_st: s-scores + t + hist (edge-chain prefix only) ----------------
__global__ void k_st(const float* __restrict__ emb, const float* __restrict__ rel,
                     const int* __restrict__ etype) {
    __shared__ float4 su4[NH * 50];
    __shared__ int hh[RH];
    int b = blockIdx.x;
    if (b < 5000) {
        for (int i = threadIdx.x; i < NH * 50; i += 256)
            su4[i] = ((const float4*)g_u)[i];
        __syncthreads();
        int n = b * 8 + (threadIdx.x >> 5);
        int l = threadIdx.x & 31;
        const float4* row4 = (const float4*)(emb + (long)n * DIN);
        float4 x = row4[l];
        float4 u0 = su4[0 * 50 + l], u1 = su4[1 * 50 + l];
        float4 u2 = su4[2 * 50 + l], u3 = su4[3 * 50 + l];
        float a0 = x.x * u0.x + x.y * u0.y + x.z * u0.z + x.w * u0.w;
        float a1 = x.x * u1.x + x.y * u1.y + x.z * u1.z + x.w * u1.w;
        float a2 = x.x * u2.x + x.y * u2.y + x.z * u2.z + x.w * u2.w;
        float a3 = x.x * u3.x + x.y * u3.y + x.z * u3.z + x.w * u3.w;
        if (l < 18) {
            float4 y = row4[l + 32];
            float4 v0 = su4[0 * 50 + l + 32], v1 = su4[1 * 50 + l + 32];
            float4 v2 = su4[2 * 50 + l + 32], v3 = su4[3 * 50 + l + 32];
            a0 += y.x * v0.x + y.y * v0.y + y.z * v0.z + y.w * v0.w;
            a1 += y.x * v1.x + y.y * v1.y + y.z * v1.z + y.w * v1.w;
            a2 += y.x * v2.x + y.y * v2.y + y.z * v2.z + y.w * v2.w;
            a3 += y.x * v3.x + y.y * v3.y + y.z * v3.z + y.w * v3.w;
        }
        a0 = warp_sum(a0); a1 = warp_sum(a1); a2 = warp_sum(a2); a3 = warp_sum(a3);
        if (l == 0) g_s[n] = make_float4(a0, a1, a2, a3);
    } else if (b < 5100) {
        int w = (b - 5000) * 8 + (threadIdx.x >> 5);
        int lane = threadIdx.x & 31;
        int h = w / RH;
        int r = w % RH;
        const float* row = rel + (r + (h < 2 ? RH : 0)) * DIN;
        float acc = 0.f;
        for (int j = lane; j < DIN; j += 32) acc += row[j] * g_v[h][j];
        acc = warp_sum(acc);
        if (lane == 0) g_t[h][r] = acc;
    } else {
        for (int i = threadIdx.x; i < RH; i += 256) hh[i] = 0;
        __syncthreads();
        int base = (b - 5100) * 1024;
        for (int i = threadIdx.x; i < 1024; i += 256) {
            int e = base + i;
            if (e < E_NUM) atomicAdd(&hh[etype[e]], 1);
        }
        __syncthreads();
        for (int i = threadIdx.x; i < RH; i += 256)
            if (hh[i]) atomicAdd(&g_count[i], hh[i]);
    }
}

// ---------------- k_cvt: split-bf16 conversion of A (emb) and B (Wproj), side stream ----
// blocks [0,8750): cvtA — thread handles 4 cols of one node row
// blocks [8750,9150): cvtB
__global__ void k_cvt(const float* __restrict__ emb, const float* __restrict__ Wproj) {
    int b = blockIdx.x;
    if (b < 8750) {
        int i = b * 256 + threadIdx.x;      // over 40000*56
        int n = i / 56;
        int c = (i % 56) * 4;
        float4 x = make_float4(0.f, 0.f, 0.f, 0.f);
        if (c < 200) x = *(const float4*)&emb[(long)n * DIN + c];
        uint2 vh, vl;
        vh.x = pack_bf2(x.x, x.y); vh.y = pack_bf2(x.z, x.w);
        float rx = x.x - __bfloat162float(__float2bfloat16(x.x));
        float ry = x.y - __bfloat162float(__float2bfloat16(x.y));
        float rz = x.z - __bfloat162float(__float2bfloat16(x.z));
        float rw = x.w - __bfloat162float(__float2bfloat16(x.w));
        vl.x = pack_bf2(rx, ry); vl.y = pack_bf2(rz, rw);
        *(uint2*)&g_Ah[(long)n * KPAD + c] = vh;
        *(uint2*)&g_Al[(long)n * KPAD + c] = vl;
    } else {
        int n = b - 8750;
        int k = threadIdx.x;
        if (k < KPAD) {
            float x = (k < 200) ? Wproj[k * 400 + n] : 0.f;
            __nv_bfloat16 h = __float2bfloat16(x);
            g_Bh[n * KPAD + k] = h;
            g_Bl[n * KPAD + k] = __float2bfloat16(x - __bfloat162float(h));
        }
    }
}

// ---------------- k_scatter: local scan + block-aggregated counting sort ----------------
__global__ void k_scatter(const int* __restrict__ el, const int* __restrict__ etype) {
    __shared__ int sc[256];
    __shared__ int hh[RH];
    __shared__ int bb[RH];
    int t = threadIdx.x;
    int c = (t < RH) ? g_count[t] : 0;
    sc[t] = c;
    __syncthreads();
    for (int o = 1; o < 256; o <<= 1) {
        int v = (t >= o) ? sc[t - o] : 0;
        __syncthreads();
        sc[t] += v;
        __syncthreads();
    }
    int offs_t = sc[t] - c;
    if (blockIdx.x == 0 && t < RH) {
        g_offs[t] = offs_t;
        if (t == RH - 1) g_offs[RH] = sc[t];
    }
    if (t < RH) hh[t] = 0;
    __syncthreads();
    int e0 = blockIdx.x * 1024;
    int myrel[4], myrank[4];
    #pragma unroll
    for (int j = 0; j < 4; j++) {
        int e = e0 + t + j * 256;
        if (e < E_NUM) {
            myrel[j] = etype[e];
            myrank[j] = atomicAdd(&hh[myrel[j]], 1);
        } else myrel[j] = -1;
    }
    __syncthreads();
    if (t < RH) {
        int cnt = hh[t];
        if (cnt) bb[t] = offs_t + atomicAdd(&g_cursor[t], cnt);
    }
    __syncthreads();
    #pragma unroll
    for (int j = 0; j < 4; j++) {
        int e = e0 + t + j * 256;
        if (myrel[j] >= 0)
            g_edges[bb[myrel[j]] + myrank[j]] = make_int2(el[e], el[E_NUM + e]);
    }
}

// ---------------- k_w: softmax stats + per-edge weights ----------------
__global__ void k_w() {
    __shared__ int2   sed[CAP];
    __shared__ float4 s_e[CAP];
    __shared__ float4 red[256];
    int r = blockIdx.x;
    int t = threadIdx.x;
    int start = g_offs[r], end = g_offs[r + 1];
    int cnt = end - start;
    if (cnt == 0) return;
    float4 tr = make_float4(g_t[0][r], g_t[1][r], g_t[2][r], g_t[3][r]);

    for (int i = t; i < cnt && i < CAP; i += 256) sed[i] = g_edges[start + i];
    __syncthreads();

    float4 mx = make_float4(-1e30f, -1e30f, -1e30f, -1e30f);
    for (int i = t; i < cnt; i += 256) {
        int2 ed = (i < CAP) ? sed[i] : g_edges[start + i];
        float4 ss = g_s[ed.x], st = g_s[ed.y];
        float4 e;
        e.x = lrelu(ss.x + tr.x);
        e.y = lrelu(ss.y + tr.y);
        e.z = lrelu(st.z + tr.z);
        e.w = lrelu(st.w + tr.w);
        if (i < CAP) s_e[i] = e;
        mx.x = fmaxf(mx.x, e.x); mx.y = fmaxf(mx.y, e.y);
        mx.z = fmaxf(mx.z, e.z); mx.w = fmaxf(mx.w, e.w);
    }
    red[t] = mx; __syncthreads();
    for (int s = 128; s > 0; s >>= 1) {
        if (t < s) {
            float4 o = red[t + s];
            red[t].x = fmaxf(red[t].x, o.x); red[t].y = fmaxf(red[t].y, o.y);
            red[t].z = fmaxf(red[t].z, o.z); red[t].w = fmaxf(red[t].w, o.w);
        }
        __syncthreads();
    }
    float4 m = red[0]; __syncthreads();

    float4 sm = make_float4(0.f, 0.f, 0.f, 0.f);
    for (int i = t; i < cnt; i += 256) {
        float4 e;
        if (i < CAP) e = s_e[i];
        else {
            int2 ed = g_edges[start + i];
            float4 ss = g_s[ed.x], st = g_s[ed.y];
            e.x = lrelu(ss.x + tr.x); e.y = lrelu(ss.y + tr.y);
            e.z = lrelu(st.z + tr.z); e.w = lrelu(st.w + tr.w);
        }
        float4 ex;
        ex.x = expf(e.x - m.x); ex.y = expf(e.y - m.y);
        ex.z = expf(e.z - m.z); ex.w = expf(e.w - m.w);
        g_w[start + i] = ex;
        sm.x += ex.x; sm.y += ex.y; sm.z += ex.z; sm.w += ex.w;
    }
    red[t] = sm; __syncthreads();
    for (int s = 128; s > 0; s >>= 1) {
        if (t < s) {
            float4 o = red[t + s];
            red[t].x += o.x; red[t].y += o.y; red[t].z += o.z; red[t].w += o.w;
        }
        __syncthreads();
    }
    if (t == 0) {
        float4 dn = red[0];
        g_sc[r] = make_float4(1.f / (dn.x + 1e-16f), 1.f / (dn.y + 1e-16f),
                              1.f / (dn.z + 1e-16f), 1.f / (dn.w + 1e-16f));
    }
}

// ---------------- k_agg ----------------
__global__ void k_agg(const float* __restrict__ emb) {
    __shared__ int2   sed[SLICE_MAX];
    __shared__ float4 sw[SLICE_MAX];
    int r = blockIdx.x;
    int t = threadIdx.x;
    int start = g_offs[r], end = g_offs[r + 1];
    int cnt = end - start;
    if (cnt == 0) return;
    int chunk = (cnt + SPLIT - 1) / SPLIT;
    int lo = blockIdx.y * chunk;
    int hi = min(lo + chunk, cnt);
    if (lo >= hi) return;
    int len = hi - lo;
    bool fits = (len <= SLICE_MAX);
    if (fits) {
        for (int i = t; i < len; i += 256) {
            sed[i] = g_edges[start + lo + i];
            sw[i]  = g_w[start + lo + i];
        }
        __syncthreads();
    }
    float4 sc = g_sc[r];
    bool act = (t < DIN);
    float a0 = 0.f, a1 = 0.f, a2 = 0.f, a3 = 0.f;
    #pragma unroll 4
    for (int j = 0; j < len; j++) {
        float4 w = fits ? sw[j] : g_w[start + lo + j];
        int2 ed  = fits ? sed[j] : g_edges[start + lo + j];
        if (act) {
            float x = emb[(long)ed.x * DIN + t];
            float y = emb[(long)ed.y * DIN + t];
            a0 += w.x * x; a1 += w.y * x; a2 += w.z * y; a3 += w.w * y;
        }
    }
    if (act) {
        atomicAdd(&g_agg[0][r][t], a0 * sc.x);
        atomicAdd(&g_agg[1][r][t], a1 * sc.y);
        atomicAdd(&g_agg[2][r][t], a2 * sc.z);
        atomicAdd(&g_agg[3][r][t], a3 * sc.w);
    }
}

// ---------------- k_rel: fused relrep + relfinal, 8 relations/block ----------------
__global__ __launch_bounds__(400) void k_rel(const float* __restrict__ Wsrc,
                                             const float* __restrict__ rel,
                                             const float* __restrict__ wrel,
                                             float* __restrict__ out_rel) {
    __shared__ float sa[8][NH][DIN];
    __shared__ float sin_[8][600];
    int b = blockIdx.x;
    int t = threadIdx.x;
    int r0 = b * 8;
    bool zero = (r0 >= RH);

    if (!zero) {
        for (int i = t; i < 8 * NH * DIN; i += 400) {
            int rr = i / (NH * DIN), rem = i % (NH * DIN);
            sa[rr][rem / DIN][rem % DIN] = g_agg[rem / DIN][r0 + rr][rem % DIN];
        }
        __syncthreads();
        int h = t / DIN, j = t % DIN;
        const float* W1 = Wsrc + h * DIN * DIN + j;
        const float* W2 = Wsrc + (h + 2) * DIN * DIN + j;
        float d1[8], d2[8];
        #pragma unroll
        for (int rr = 0; rr < 8; rr++) { d1[rr] = 0.f; d2[rr] = 0.f; }
        for (int k4 = 0; k4 < DIN; k4 += 4) {
            float w1a = W1[(k4 + 0) * DIN], w1b = W1[(k4 + 1) * DIN];
            float w1c = W1[(k4 + 2) * DIN], w1d = W1[(k4 + 3) * DIN];
            float w2a = W2[(k4 + 0) * DIN], w2b = W2[(k4 + 1) * DIN];
            float w2c = W2[(k4 + 2) * DIN], w2d = W2[(k4 + 3) * DIN];
            #pragma unroll
            for (int rr = 0; rr < 8; rr++) {
                float4 a1v = *(const float4*)&sa[rr][h][k4];
                float4 a2v = *(const float4*)&sa[rr][h + 2][k4];
                d1[rr] += a1v.x * w1a + a1v.y * w1b + a1v.z * w1c + a1v.w * w1d;
                d2[rr] += a2v.x * w2a + a2v.y * w2b + a2v.z * w2c + a2v.w * w2d;
            }
        }
        #pragma unroll
        for (int rr = 0; rr < 8; rr++)
            sin_[rr][t] = elu(d1[rr]) + elu(d2[rr]);
        for (int i = t; i < 8 * DIN; i += 400) {
            int rr = i / DIN, k = i % DIN;
            sin_[rr][400 + k] = rel[(r0 + rr) * DIN + k];
        }
        __syncthreads();
    } else {
        for (int i = t; i < 8 * 400; i += 400) {
            int rr = i / 400, k = i % 400;
            sin_[rr][k] = 0.f;
        }
        for (int i = t; i < 8 * DIN; i += 400) {
            int rr = i / DIN, k = i % DIN;
            sin_[rr][400 + k] = rel[(r0 + rr) * DIN + k];
        }
        __syncthreads();
    }

    float acc[8];
    #pragma unroll
    for (int rr = 0; rr < 8; rr++) acc[rr] = 0.f;
    for (int k4 = 0; k4 < 600; k4 += 4) {
        float wa = wrel[(k4 + 0) * 400 + t];
        float wb = wrel[(k4 + 1) * 400 + t];
        float wc = wrel[(k4 + 2) * 400 + t];
        float wd = wrel[(k4 + 3) * 400 + t];
        #pragma unroll
        for (int rr = 0; rr < 8; rr++) {
            float4 s = *(const float4*)&sin_[rr][k4];
            acc[rr] += s.x * wa + s.y * wb + s.z * wc + s.w * wd;
        }
    }
    #pragma unroll
    for (int rr = 0; rr < 8; rr++)
        out_rel[(r0 + rr) * 400 + t] = acc[rr];
}

// ---------------- fused split-bf16 HMMA GEMM (KC=32) ----------------
#define BM 128
#define BN 80
#define KC 32
#define AST 40
#define BST 40

__global__ __launch_bounds__(256) void k_entmm(float* __restrict__ C) {
    __shared__ __align__(16) __nv_bfloat16 sAh[BM * AST];
    __shared__ __align__(16) __nv_bfloat16 sAl[BM * AST];
    __shared__ __align__(16) __nv_bfloat16 sBh[BN * BST];
    __shared__ __align__(16) __nv_bfloat16 sBl[BN * BST];
    const int tid = threadIdx.x;
    const int warp = tid >> 5, lane = tid & 31;
    const int wm = warp & 3;
    const int wn = warp >> 2;
    const int bm = blockIdx.y * BM;
    const int bn = blockIdx.x * BN;

    float acc[2][5][4];
    #pragma unroll
    for (int i = 0; i < 2; i++)
        #pragma unroll
        for (int j = 0; j < 5; j++)
            #pragma unroll
            for (int c = 0; c < 4; c++) acc[i][j][c] = 0.f;

    const uint32_t sAh32 = smem_u32(sAh), sAl32 = smem_u32(sAl);
    const uint32_t sBh32 = smem_u32(sBh), sBl32 = smem_u32(sBl);
    const int a_row = wm * 32 + (lane & 15);
    const int a_koff = (lane >> 4) * 8;
    const int b_row = wn * 40 + (lane & 7);
    const int b_koff = ((lane >> 3) & 1) * 8;

    #pragma unroll 1
    for (int kc = 0; kc < 224; kc += KC) {
        #pragma unroll
        for (int i = 0; i < 2; i++) {
            int idx = tid + i * 256;
            int row = idx >> 2, j = idx & 3;
            int grow = bm + row;
            int4 vh = make_int4(0, 0, 0, 0), vl = make_int4(0, 0, 0, 0);
            if (grow < N_NODES) {
                vh = *(const int4*)(g_Ah + (long)grow * KPAD + kc + j * 8);
                vl = *(const int4*)(g_Al + (long)grow * KPAD + kc + j * 8);
            }
            *(int4*)(sAh + row * AST + j * 8) = vh;
            *(int4*)(sAl + row * AST + j * 8) = vl;
        }
        for (int idx = tid; idx < 320; idx += 256) {
            int row = idx >> 2, j = idx & 3;
            *(int4*)(sBh + row * BST + j * 8) =
                *(const int4*)(g_Bh + (long)(bn + row) * KPAD + kc + j * 8);
            *(int4*)(sBl + row * BST + j * 8) =
                *(const int4*)(g_Bl + (long)(bn + row) * KPAD + kc + j * 8);
        }
        __syncthreads();

        int nks = (kc == 192) ? 1 : 2;
        for (int ks = 0; ks < nks; ks++) {
            int k0 = ks * 16;
            uint32_t afh[2][4], afl[2][4], bfh[5][2], bfl[5][2];
            #pragma unroll
            for (int mf = 0; mf < 2; mf++) {
                ldm_x4(afh[mf], sAh32 + ((a_row + mf * 16) * AST + k0 + a_koff) * 2);
                ldm_x4(afl[mf], sAl32 + ((a_row + mf * 16) * AST + k0 + a_koff) * 2);
            }
            #pragma unroll
            for (int nf = 0; nf < 5; nf++) {
                ldm_x2(bfh[nf], sBh32 + ((b_row + nf * 8) * BST + k0 + b_koff) * 2);
                ldm_x2(bfl[nf], sBl32 + ((b_row + nf * 8) * BST + k0 + b_koff) * 2);
            }
            #pragma unroll
            for (int mf = 0; mf < 2; mf++)
                #pragma unroll
                for (int nf = 0; nf < 5; nf++) {
                    mma16816(acc[mf][nf], afh[mf], bfh[nf]);
                    mma16816(acc[mf][nf], afl[mf], bfh[nf]);
                    mma16816(acc[mf][nf], afh[mf], bfl[nf]);
                }
        }
        __syncthreads();
    }

    const int m_base = bm + wm * 32 + (lane >> 2);
    const int n_base = bn + wn * 40 + (lane & 3) * 2;
    #pragma unroll
    for (int mf = 0; mf < 2; mf++) {
        #pragma unroll
        for (int nf = 0; nf < 5; nf++) {
            int n = n_base + nf * 8;
            int m0 = m_base + mf * 16;
            if (m0 < N_NODES)
                *(float2*)&C[(long)m0 * 400 + n] = make_float2(acc[mf][nf][0], acc[mf][nf][1]);
            if (m0 + 8 < N_NODES)
                *(float2*)&C[(long)(m0 + 8) * 400 + n] = make_float2(acc[mf][nf][2], acc[mf][nf][3]);
        }
    }
}

// ---------------- launch: two parallel chains from t=0 ----------------
extern "C" void kernel_launch(void* const* d_in, const int* in_sizes, int n_in,
                              void* d_out, int out_size) {
    const int*   el    = (const int*)d_in[0];
    const int*   et    = (const int*)d_in[1];
    const float* emb   = (const float*)d_in[2];
    const float* rel   = (const float*)d_in[3];
    const float* Wsrc  = (const float*)d_in[4];
    const float* Wdst  = (const float*)d_in[5];
    const float* avec  = (const float*)d_in[6];
    const float* wrel  = (const float*)d_in[7];
    const float* Wproj = (const float*)d_in[8];
    float* out     = (float*)d_out;
    float* out_ent = out;
    float* out_rel = out + (long)N_NODES * 400;

    cudaStream_t s2;
    cudaEvent_t ev_fork, ev_join;
    cudaStreamCreateWithFlags(&s2, cudaStreamNonBlocking);
    cudaEventCreateWithFlags(&ev_fork, cudaEventDisableTiming);
    cudaEventCreateWithFlags(&ev_join, cudaEventDisableTiming);

    // fork side stream at the root — GEMM chain depends only on raw inputs
    cudaEventRecord(ev_fork, 0);
    cudaStreamWaitEvent(s2, ev_fork, 0);

    // edge chain (main stream)
    k_init<<<825, 256>>>(Wsrc, Wdst, avec);
    k_st<<<5198, 256>>>(emb, rel, et);

    // GEMM chain (side stream); enqueue here so k_entmm is the 4th launch (profiled)
    k_cvt<<<9150, 256, 0, s2>>>(emb, Wproj);
    k_entmm<<<dim3(5, 313), 256, 0, s2>>>(out_ent);
    cudaEventRecord(ev_join, s2);

    k_scatter<<<98, 256>>>(el, et);
    k_w<<<RH, 256>>>();
    k_agg<<<dim3(RH, SPLIT), 256>>>(emb);
    k_rel<<<50, 400>>>(Wsrc, rel, wrel, out_rel);

    cudaStreamWaitEvent(0, ev_join, 0);
}

// round 11
// speedup vs baseline: 1.4715x; 1.0215x over previous
#include <cuda_runtime.h>
#include <cuda_bf16.h>
#include <cstdint>

#define E_NUM   100000
#define N_NODES 40000
#define R_NUM   400
#define RH      200
#define DIN     200
#define NH      4
#define CAP     1024
#define SPLIT   8
#define SLICE_MAX 256
#define KPAD    224

// ---------------- device scratch ----------------
__device__ float  g_u[NH][DIN];
__device__ float  g_v[NH][DIN];
__device__ float  g_t[NH][RH];
__device__ float4 g_s[N_NODES];
__device__ int    g_count[RH];
__device__ int    g_offs[RH + 1];
__device__ int    g_cursor[RH];
__device__ int2   g_edges[E_NUM];
__device__ float4 g_w[E_NUM];
__device__ float4 g_sc[RH];
__device__ float  g_agg[NH][RH][DIN];
__device__ __align__(16) __nv_bfloat16 g_Ah[(size_t)N_NODES * KPAD];
__device__ __align__(16) __nv_bfloat16 g_Al[(size_t)N_NODES * KPAD];
__device__ __align__(16) __nv_bfloat16 g_Bh[400 * KPAD];
__device__ __align__(16) __nv_bfloat16 g_Bl[400 * KPAD];

// ---------------- helpers ----------------
__device__ __forceinline__ float lrelu(float x) { return x >= 0.f ? x : 0.2f * x; }
__device__ __forceinline__ float elu(float x)   { return x > 0.f ? x : expm1f(x); }

__device__ __forceinline__ float warp_sum(float v) {
    #pragma unroll
    for (int o = 16; o; o >>= 1) v += __shfl_down_sync(0xffffffffu, v, o);
    return v;
}

__device__ __forceinline__ uint32_t smem_u32(const void* p) {
    uint32_t a;
    asm("{ .reg .u64 t; cvta.to.shared.u64 t, %1; cvt.u32.u64 %0, t; }" : "=r"(a) : "l"(p));
    return a;
}

__device__ __forceinline__ uint32_t pack_bf2(float a, float b) {
    __nv_bfloat162 t(__float2bfloat16(a), __float2bfloat16(b));
    return *(uint32_t*)&t;
}

__device__ __forceinline__ void ldm_x4(uint32_t* r, uint32_t addr) {
    asm volatile("ldmatrix.sync.aligned.m8n8.x4.shared.b16 {%0,%1,%2,%3}, [%4];"
                 : "=r"(r[0]), "=r"(r[1]), "=r"(r[2]), "=r"(r[3]) : "r"(addr));
}
__device__ __forceinline__ void ldm_x2(uint32_t* r, uint32_t addr) {
    asm volatile("ldmatrix.sync.aligned.m8n8.x2.shared.b16 {%0,%1}, [%2];"
                 : "=r"(r[0]), "=r"(r[1]) : "r"(addr));
}
__device__ __forceinline__ void mma16816(float* d, const uint32_t* a, const uint32_t* b) {
    asm volatile("mma.sync.aligned.m16n8k16.row.col.f32.bf16.bf16.f32 "
                 "{%0,%1,%2,%3}, {%4,%5,%6,%7}, {%8,%9}, {%0,%1,%2,%3};"
                 : "+f"(d[0]), "+f"(d[1]), "+f"(d[2]), "+f"(d[3])
                 : "r"(a[0]), "r"(a[1]), "r"(a[2]), "r"(a[3]), "r"(b[0]), "r"(b[1]));
}
__device__ __forceinline__ void cp16(uint32_t dst, const void* src, bool pred) {
    int sz = pred ? 16 : 0;
    asm volatile("cp.async.cg.shared.global [%0], [%1], 16, %2;"
                 :: "r"(dst), "l"(src), "r"(sz));
}
#define CP_COMMIT() asm volatile("cp.async.commit_group;" ::: "memory")
#define CP_WAIT1()  asm volatile("cp.async.wait_group 1;" ::: "memory")
#define CP_WAIT0()  asm volatile("cp.async.wait_group 0;" ::: "memory")

// ---------------- k_init: uv + zero(agg,count,cursor) ----------------
__global__ void k_init(const float* __restrict__ Wsrc, const float* __restrict__ Wdst,
                       const float* __restrict__ avec) {
    int b = blockIdx.x;
    if (b < 200) {
        int w = b * 8 + (threadIdx.x >> 5);
        int lane = threadIdx.x & 31;
        int side = w / 800;
        int h = (w / 200) % 4;
        int i = w % 200;
        const float* W = (side == 0 ? Wsrc : Wdst) + h * DIN * DIN + i * DIN;
        const float* a = avec + h * 400 + side * 200;
        float acc = 0.f;
        for (int j = lane; j < DIN; j += 32) acc += W[j] * a[j];
        acc = warp_sum(acc);
        if (lane == 0) {
            if (side == 0) g_u[h][i] = acc; else g_v[h][i] = acc;
        }
    } else {
        int i = (b - 200) * 256 + threadIdx.x;
        if (i < NH * RH * DIN) ((float*)g_agg)[i] = 0.f;
        if (b == 200 && threadIdx.x < RH) {
            g_count[threadIdx.x] = 0;
            g_cursor[threadIdx.x] = 0;
        }
    }
}

// ---------------- k_st: s-scores + t + hist ----------------
__global__ void k_st(const float* __restrict__ emb, const float* __restrict__ rel,
                     const int* __restrict__ etype) {
    __shared__ float4 su4[NH * 50];
    __shared__ int hh[RH];
    int b = blockIdx.x;
    if (b < 5000) {
        for (int i = threadIdx.x; i < NH * 50; i += 256)
            su4[i] = ((const float4*)g_u)[i];
        __syncthreads();
        int n = b * 8 + (threadIdx.x >> 5);
        int l = threadIdx.x & 31;
        const float4* row4 = (const float4*)(emb + (long)n * DIN);
        float4 x = row4[l];
        float4 u0 = su4[0 * 50 + l], u1 = su4[1 * 50 + l];
        float4 u2 = su4[2 * 50 + l], u3 = su4[3 * 50 + l];
        float a0 = x.x * u0.x + x.y * u0.y + x.z * u0.z + x.w * u0.w;
        float a1 = x.x * u1.x + x.y * u1.y + x.z * u1.z + x.w * u1.w;
        float a2 = x.x * u2.x + x.y * u2.y + x.z * u2.z + x.w * u2.w;
        float a3 = x.x * u3.x + x.y * u3.y + x.z * u3.z + x.w * u3.w;
        if (l < 18) {
            float4 y = row4[l + 32];
            float4 v0 = su4[0 * 50 + l + 32], v1 = su4[1 * 50 + l + 32];
            float4 v2 = su4[2 * 50 + l + 32], v3 = su4[3 * 50 + l + 32];
            a0 += y.x * v0.x + y.y * v0.y + y.z * v0.z + y.w * v0.w;
            a1 += y.x * v1.x + y.y * v1.y + y.z * v1.z + y.w * v1.w;
            a2 += y.x * v2.x + y.y * v2.y + y.z * v2.z + y.w * v2.w;
            a3 += y.x * v3.x + y.y * v3.y + y.z * v3.z + y.w * v3.w;
        }
        a0 = warp_sum(a0); a1 = warp_sum(a1); a2 = warp_sum(a2); a3 = warp_sum(a3);
        if (l == 0) g_s[n] = make_float4(a0, a1, a2, a3);
    } else if (b < 5100) {
        int w = (b - 5000) * 8 + (threadIdx.x >> 5);
        int lane = threadIdx.x & 31;
        int h = w / RH;
        int r = w % RH;
        const float* row = rel + (r + (h < 2 ? RH : 0)) * DIN;
        float acc = 0.f;
        for (int j = lane; j < DIN; j += 32) acc += row[j] * g_v[h][j];
        acc = warp_sum(acc);
        if (lane == 0) g_t[h][r] = acc;
    } else {
        for (int i = threadIdx.x; i < RH; i += 256) hh[i] = 0;
        __syncthreads();
        int base = (b - 5100) * 1024;
        for (int i = threadIdx.x; i < 1024; i += 256) {
            int e = base + i;
            if (e < E_NUM) atomicAdd(&hh[etype[e]], 1);
        }
        __syncthreads();
        for (int i = threadIdx.x; i < RH; i += 256)
            if (hh[i]) atomicAdd(&g_count[i], hh[i]);
    }
}

// ---------------- k_cvt: split-bf16 conversion ----------------
__global__ void k_cvt(const float* __restrict__ emb, const float* __restrict__ Wproj) {
    int b = blockIdx.x;
    if (b < 8750) {
        int i = b * 256 + threadIdx.x;
        int n = i / 56;
        int c = (i % 56) * 4;
        float4 x = make_float4(0.f, 0.f, 0.f, 0.f);
        if (c < 200) x = *(const float4*)&emb[(long)n * DIN + c];
        uint2 vh, vl;
        vh.x = pack_bf2(x.x, x.y); vh.y = pack_bf2(x.z, x.w);
        float rx = x.x - __bfloat162float(__float2bfloat16(x.x));
        float ry = x.y - __bfloat162float(__float2bfloat16(x.y));
        float rz = x.z - __bfloat162float(__float2bfloat16(x.z));
        float rw = x.w - __bfloat162float(__float2bfloat16(x.w));
        vl.x = pack_bf2(rx, ry); vl.y = pack_bf2(rz, rw);
        *(uint2*)&g_Ah[(long)n * KPAD + c] = vh;
        *(uint2*)&g_Al[(long)n * KPAD + c] = vl;
    } else {
        int n = b - 8750;
        int k = threadIdx.x;
        if (k < KPAD) {
            float x = (k < 200) ? Wproj[k * 400 + n] : 0.f;
            __nv_bfloat16 h = __float2bfloat16(x);
            g_Bh[n * KPAD + k] = h;
            g_Bl[n * KPAD + k] = __float2bfloat16(x - __bfloat162float(h));
        }
    }
}

// ---------------- k_scatter ----------------
__global__ void k_scatter(const int* __restrict__ el, const int* __restrict__ etype) {
    __shared__ int sc[256];
    __shared__ int hh[RH];
    __shared__ int bb[RH];
    int t = threadIdx.x;
    int c = (t < RH) ? g_count[t] : 0;
    sc[t] = c;
    __syncthreads();
    for (int o = 1; o < 256; o <<= 1) {
        int v = (t >= o) ? sc[t - o] : 0;
        __syncthreads();
        sc[t] += v;
        __syncthreads();
    }
    int offs_t = sc[t] - c;
    if (blockIdx.x == 0 && t < RH) {
        g_offs[t] = offs_t;
        if (t == RH - 1) g_offs[RH] = sc[t];
    }
    if (t < RH) hh[t] = 0;
    __syncthreads();
    int e0 = blockIdx.x * 1024;
    int myrel[4], myrank[4];
    #pragma unroll
    for (int j = 0; j < 4; j++) {
        int e = e0 + t + j * 256;
        if (e < E_NUM) {
            myrel[j] = etype[e];
            myrank[j] = atomicAdd(&hh[myrel[j]], 1);
        } else myrel[j] = -1;
    }
    __syncthreads();
    if (t < RH) {
        int cnt = hh[t];
        if (cnt) bb[t] = offs_t + atomicAdd(&g_cursor[t], cnt);
    }
    __syncthreads();
    #pragma unroll
    for (int j = 0; j < 4; j++) {
        int e = e0 + t + j * 256;
        if (myrel[j] >= 0)
            g_edges[bb[myrel[j]] + myrank[j]] = make_int2(el[e], el[E_NUM + e]);
    }
}

// ---------------- k_w ----------------
__global__ void k_w() {
    __shared__ int2   sed[CAP];
    __shared__ float4 s_e[CAP];
    __shared__ float4 red[256];
    int r = blockIdx.x;
    int t = threadIdx.x;
    int start = g_offs[r], end = g_offs[r + 1];
    int cnt = end - start;
    if (cnt == 0) return;
    float4 tr = make_float4(g_t[0][r], g_t[1][r], g_t[2][r], g_t[3][r]);

    for (int i = t; i < cnt && i < CAP; i += 256) sed[i] = g_edges[start + i];
    __syncthreads();

    float4 mx = make_float4(-1e30f, -1e30f, -1e30f, -1e30f);
    for (int i = t; i < cnt; i += 256) {
        int2 ed = (i < CAP) ? sed[i] : g_edges[start + i];
        float4 ss = g_s[ed.x], st = g_s[ed.y];
        float4 e;
        e.x = lrelu(ss.x + tr.x);
        e.y = lrelu(ss.y + tr.y);
        e.z = lrelu(st.z + tr.z);
        e.w = lrelu(st.w + tr.w);
        if (i < CAP) s_e[i] = e;
        mx.x = fmaxf(mx.x, e.x); mx.y = fmaxf(mx.y, e.y);
        mx.z = fmaxf(mx.z, e.z); mx.w = fmaxf(mx.w, e.w);
    }
    red[t] = mx; __syncthreads();
    for (int s = 128; s > 0; s >>= 1) {
        if (t < s) {
            float4 o = red[t + s];
            red[t].x = fmaxf(red[t].x, o.x); red[t].y = fmaxf(red[t].y, o.y);
            red[t].z = fmaxf(red[t].z, o.z); red[t].w = fmaxf(red[t].w, o.w);
        }
        __syncthreads();
    }
    float4 m = red[0]; __syncthreads();

    float4 sm = make_float4(0.f, 0.f, 0.f, 0.f);
    for (int i = t; i < cnt; i += 256) {
        float4 e;
        if (i < CAP) e = s_e[i];
        else {
            int2 ed = g_edges[start + i];
            float4 ss = g_s[ed.x], st = g_s[ed.y];
            e.x = lrelu(ss.x + tr.x); e.y = lrelu(ss.y + tr.y);
            e.z = lrelu(st.z + tr.z); e.w = lrelu(st.w + tr.w);
        }
        float4 ex;
        ex.x = expf(e.x - m.x); ex.y = expf(e.y - m.y);
        ex.z = expf(e.z - m.z); ex.w = expf(e.w - m.w);
        g_w[start + i] = ex;
        sm.x += ex.x; sm.y += ex.y; sm.z += ex.z; sm.w += ex.w;
    }
    red[t] = sm; __syncthreads();
    for (int s = 128; s > 0; s >>= 1) {
        if (t < s) {
            float4 o = red[t + s];
            red[t].x += o.x; red[t].y += o.y; red[t].z += o.z; red[t].w += o.w;
        }
        __syncthreads();
    }
    if (t == 0) {
        float4 dn = red[0];
        g_sc[r] = make_float4(1.f / (dn.x + 1e-16f), 1.f / (dn.y + 1e-16f),
                              1.f / (dn.z + 1e-16f), 1.f / (dn.w + 1e-16f));
    }
}

// ---------------- k_agg ----------------
__global__ void k_agg(const float* __restrict__ emb) {
    __shared__ int2   sed[SLICE_MAX];
    __shared__ float4 sw[SLICE_MAX];
    int r = blockIdx.x;
    int t = threadIdx.x;
    int start = g_offs[r], end = g_offs[r + 1];
    int cnt = end - start;
    if (cnt == 0) return;
    int chunk = (cnt + SPLIT - 1) / SPLIT;
    int lo = blockIdx.y * chunk;
    int hi = min(lo + chunk, cnt);
    if (lo >= hi) return;
    int len = hi - lo;
    bool fits = (len <= SLICE_MAX);
    if (fits) {
        for (int i = t; i < len; i += 256) {
            sed[i] = g_edges[start + lo + i];
            sw[i]  = g_w[start + lo + i];
        }
        __syncthreads();
    }
    float4 sc = g_sc[r];
    bool act = (t < DIN);
    float a0 = 0.f, a1 = 0.f, a2 = 0.f, a3 = 0.f;
    #pragma unroll 4
    for (int j = 0; j < len; j++) {
        float4 w = fits ? sw[j] : g_w[start + lo + j];
        int2 ed  = fits ? sed[j] : g_edges[start + lo + j];
        if (act) {
            float x = emb[(long)ed.x * DIN + t];
            float y = emb[(long)ed.y * DIN + t];
            a0 += w.x * x; a1 += w.y * x; a2 += w.z * y; a3 += w.w * y;
        }
    }
    if (act) {
        atomicAdd(&g_agg[0][r][t], a0 * sc.x);
        atomicAdd(&g_agg[1][r][t], a1 * sc.y);
        atomicAdd(&g_agg[2][r][t], a2 * sc.z);
        atomicAdd(&g_agg[3][r][t], a3 * sc.w);
    }
}

// ---------------- k_rel: fused relrep + relfinal ----------------
__global__ __launch_bounds__(400) void k_rel(const float* __restrict__ Wsrc,
                                             const float* __restrict__ rel,
                                             const float* __restrict__ wrel,
                                             float* __restrict__ out_rel) {
    __shared__ float sa[8][NH][DIN];
    __shared__ float sin_[8][600];
    int b = blockIdx.x;
    int t = threadIdx.x;
    int r0 = b * 8;
    bool zero = (r0 >= RH);

    if (!zero) {
        for (int i = t; i < 8 * NH * DIN; i += 400) {
            int rr = i / (NH * DIN), rem = i % (NH * DIN);
            sa[rr][rem / DIN][rem % DIN] = g_agg[rem / DIN][r0 + rr][rem % DIN];
        }
        __syncthreads();
        int h = t / DIN, j = t % DIN;
        const float* W1 = Wsrc + h * DIN * DIN + j;
        const float* W2 = Wsrc + (h + 2) * DIN * DIN + j;
        float d1[8], d2[8];
        #pragma unroll
        for (int rr = 0; rr < 8; rr++) { d1[rr] = 0.f; d2[rr] = 0.f; }
        for (int k4 = 0; k4 < DIN; k4 += 4) {
            float w1a = W1[(k4 + 0) * DIN], w1b = W1[(k4 + 1) * DIN];
            float w1c = W1[(k4 + 2) * DIN], w1d = W1[(k4 + 3) * DIN];
            float w2a = W2[(k4 + 0) * DIN], w2b = W2[(k4 + 1) * DIN];
            float w2c = W2[(k4 + 2) * DIN], w2d = W2[(k4 + 3) * DIN];
            #pragma unroll
            for (int rr = 0; rr < 8; rr++) {
                float4 a1v = *(const float4*)&sa[rr][h][k4];
                float4 a2v = *(const float4*)&sa[rr][h + 2][k4];
                d1[rr] += a1v.x * w1a + a1v.y * w1b + a1v.z * w1c + a1v.w * w1d;
                d2[rr] += a2v.x * w2a + a2v.y * w2b + a2v.z * w2c + a2v.w * w2d;
            }
        }
        #pragma unroll
        for (int rr = 0; rr < 8; rr++)
            sin_[rr][t] = elu(d1[rr]) + elu(d2[rr]);
        for (int i = t; i < 8 * DIN; i += 400) {
            int rr = i / DIN, k = i % DIN;
            sin_[rr][400 + k] = rel[(r0 + rr) * DIN + k];
        }
        __syncthreads();
    } else {
        for (int i = t; i < 8 * 400; i += 400) {
            int rr = i / 400, k = i % 400;
            sin_[rr][k] = 0.f;
        }
        for (int i = t; i < 8 * DIN; i += 400) {
            int rr = i / DIN, k = i % DIN;
            sin_[rr][400 + k] = rel[(r0 + rr) * DIN + k];
        }
        __syncthreads();
    }

    float acc[8];
    #pragma unroll
    for (int rr = 0; rr < 8; rr++) acc[rr] = 0.f;
    for (int k4 = 0; k4 < 600; k4 += 4) {
        float wa = wrel[(k4 + 0) * 400 + t];
        float wb = wrel[(k4 + 1) * 400 + t];
        float wc = wrel[(k4 + 2) * 400 + t];
        float wd = wrel[(k4 + 3) * 400 + t];
        #pragma unroll
        for (int rr = 0; rr < 8; rr++) {
            float4 s = *(const float4*)&sin_[rr][k4];
            acc[rr] += s.x * wa + s.y * wb + s.z * wc + s.w * wd;
        }
    }
    #pragma unroll
    for (int rr = 0; rr < 8; rr++)
        out_rel[(r0 + rr) * 400 + t] = acc[rr];
}

// ---------------- k_entmm: cp.async double-buffered split-bf16 HMMA GEMM ----------------
#define BM 128
#define BN 80
#define KC 32
#define AST 40
#define BST 40
#define A_TILE_B (BM * AST * 2)          // 10240 bytes
#define B_TILE_B (BN * BST * 2)          // 6400 bytes
#define STAGE_B  (2 * A_TILE_B + 2 * B_TILE_B)  // 33280 bytes
#define NCHUNK   7                        // kc = 0..192

__global__ __launch_bounds__(256) void k_entmm(float* __restrict__ C) {
    extern __shared__ __align__(16) unsigned char dynsmem[];
    const int tid = threadIdx.x;
    const int warp = tid >> 5, lane = tid & 31;
    const int wm = warp & 3;
    const int wn = warp >> 2;
    const int bm = blockIdx.y * BM;
    const int bn = blockIdx.x * BN;

    float acc[2][5][4];
    #pragma unroll
    for (int i = 0; i < 2; i++)
        #pragma unroll
        for (int j = 0; j < 5; j++)
            #pragma unroll
            for (int c = 0; c < 4; c++) acc[i][j][c] = 0.f;

    const uint32_t smem0 = smem_u32(dynsmem);
    const int a_row = wm * 32 + (lane & 15);
    const int a_koff = (lane >> 4) * 8;
    const int b_row = wn * 40 + (lane & 7);
    const int b_koff = ((lane >> 3) & 1) * 8;

    // async load of one K-chunk into stage s
    auto load_chunk = [&](int kc, int s) {
        uint32_t base = smem0 + s * STAGE_B;
        uint32_t sAh = base;
        uint32_t sAl = base + A_TILE_B;
        uint32_t sBh = base + 2 * A_TILE_B;
        uint32_t sBl = base + 2 * A_TILE_B + B_TILE_B;
        // A: 128 rows x 32 cols = 512 x 16B per matrix
        #pragma unroll
        for (int i = 0; i < 2; i++) {
            int idx = tid + i * 256;
            int row = idx >> 2, j = idx & 3;
            int grow = bm + row;
            bool ok = (grow < N_NODES);
            const __nv_bfloat16* srcH = g_Ah + (long)grow * KPAD + kc + j * 8;
            const __nv_bfloat16* srcL = g_Al + (long)grow * KPAD + kc + j * 8;
            cp16(sAh + (row * AST + j * 8) * 2, srcH, ok);
            cp16(sAl + (row * AST + j * 8) * 2, srcL, ok);
        }
        // B: 80 rows x 32 cols = 320 x 16B per matrix
        for (int idx = tid; idx < 320; idx += 256) {
            int row = idx >> 2, j = idx & 3;
            const __nv_bfloat16* srcH = g_Bh + (long)(bn + row) * KPAD + kc + j * 8;
            const __nv_bfloat16* srcL = g_Bl + (long)(bn + row) * KPAD + kc + j * 8;
            cp16(sBh + (row * BST + j * 8) * 2, srcH, true);
            cp16(sBl + (row * BST + j * 8) * 2, srcL, true);
        }
    };

    load_chunk(0, 0);
    CP_COMMIT();

    int cur = 0;
    #pragma unroll 1
    for (int ci = 0; ci < NCHUNK; ci++) {
        if (ci + 1 < NCHUNK) {
            load_chunk((ci + 1) * KC, cur ^ 1);
            CP_COMMIT();
            CP_WAIT1();
        } else {
            CP_WAIT0();
        }
        __syncthreads();

        uint32_t base = smem0 + cur * STAGE_B;
        uint32_t sAh32 = base;
        uint32_t sAl32 = base + A_TILE_B;
        uint32_t sBh32 = base + 2 * A_TILE_B;
        uint32_t sBl32 = base + 2 * A_TILE_B + B_TILE_B;

        int nks = (ci == NCHUNK - 1) ? 1 : 2;   // cols >= 200 are zero padding
        for (int ks = 0; ks < nks; ks++) {
            int k0 = ks * 16;
            uint32_t afh[2][4], afl[2][4], bfh[5][2], bfl[5][2];
            #pragma unroll
            for (int mf = 0; mf < 2; mf++) {
                ldm_x4(afh[mf], sAh32 + ((a_row + mf * 16) * AST + k0 + a_koff) * 2);
                ldm_x4(afl[mf], sAl32 + ((a_row + mf * 16) * AST + k0 + a_koff) * 2);
            }
            #pragma unroll
            for (int nf = 0; nf < 5; nf++) {
                ldm_x2(bfh[nf], sBh32 + ((b_row + nf * 8) * BST + k0 + b_koff) * 2);
                ldm_x2(bfl[nf], sBl32 + ((b_row + nf * 8) * BST + k0 + b_koff) * 2);
            }
            #pragma unroll
            for (int mf = 0; mf < 2; mf++)
                #pragma unroll
                for (int nf = 0; nf < 5; nf++) {
                    mma16816(acc[mf][nf], afh[mf], bfh[nf]);
                    mma16816(acc[mf][nf], afl[mf], bfh[nf]);
                    mma16816(acc[mf][nf], afh[mf], bfl[nf]);
                }
        }
        __syncthreads();   // all warps done with stage `cur` before it is reloaded
        cur ^= 1;
    }

    const int m_base = bm + wm * 32 + (lane >> 2);
    const int n_base = bn + wn * 40 + (lane & 3) * 2;
    #pragma unroll
    for (int mf = 0; mf < 2; mf++) {
        #pragma unroll
        for (int nf = 0; nf < 5; nf++) {
            int n = n_base + nf * 8;
            int m0 = m_base + mf * 16;
            if (m0 < N_NODES)
                *(float2*)&C[(long)m0 * 400 + n] = make_float2(acc[mf][nf][0], acc[mf][nf][1]);
            if (m0 + 8 < N_NODES)
                *(float2*)&C[(long)(m0 + 8) * 400 + n] = make_float2(acc[mf][nf][2], acc[mf][nf][3]);
        }
    }
}

// ---------------- launch ----------------
extern "C" void kernel_launch(void* const* d_in, const int* in_sizes, int n_in,
                              void* d_out, int out_size) {
    const int*   el    = (const int*)d_in[0];
    const int*   et    = (const int*)d_in[1];
    const float* emb   = (const float*)d_in[2];
    const float* rel   = (const float*)d_in[3];
    const float* Wsrc  = (const float*)d_in[4];
    const float* Wdst  = (const float*)d_in[5];
    const float* avec  = (const float*)d_in[6];
    const float* wrel  = (const float*)d_in[7];
    const float* Wproj = (const float*)d_in[8];
    float* out     = (float*)d_out;
    float* out_ent = out;
    float* out_rel = out + (long)N_NODES * 400;

    static bool attr_done = false;
    if (!attr_done) {
        cudaFuncSetAttribute(k_entmm, cudaFuncAttributeMaxDynamicSharedMemorySize,
                             2 * STAGE_B);
        attr_done = true;
    }

    cudaStream_t s2;
    cudaEvent_t ev_fork, ev_join;
    cudaStreamCreateWithFlags(&s2, cudaStreamNonBlocking);
    cudaEventCreateWithFlags(&ev_fork, cudaEventDisableTiming);
    cudaEventCreateWithFlags(&ev_join, cudaEventDisableTiming);

    cudaEventRecord(ev_fork, 0);
    cudaStreamWaitEvent(s2, ev_fork, 0);

    // edge chain (main stream)
    k_init<<<825, 256>>>(Wsrc, Wdst, avec);
    k_st<<<5198, 256>>>(emb, rel, et);

    // GEMM chain (side stream); entmm stays 4th launch for ncu
    k_cvt<<<9150, 256, 0, s2>>>(emb, Wproj);
    k_entmm<<<dim3(5, 313), 256, 2 * STAGE_B, s2>>>(out_ent);
    cudaEventRecord(ev_join, s2);

    k_scatter<<<98, 256>>>(el, et);
    k_w<<<RH, 256>>>();
    k_agg<<<dim3(RH, SPLIT), 256>>>(emb);
    k_rel<<<50, 400>>>(Wsrc, rel, wrel, out_rel);

    cudaStreamWaitEvent(0, ev_join, 0);
}

// round 12
// speedup vs baseline: 1.5603x; 1.0603x over previous
#include <cuda_runtime.h>
#include <cuda_bf16.h>
#include <cuda_fp16.h>
#include <cstdint>

#define E_NUM   100000
#define N_NODES 40000
#define R_NUM   400
#define RH      200
#define DIN     200
#define NH      4
#define CAP     1024
#define SPLIT   8
#define SLICE_MAX 256
#define KPAD    224

// ---------------- device scratch ----------------
__device__ float  g_u[NH][DIN];
__device__ float  g_v[NH][DIN];
__device__ float  g_t[NH][RH];
__device__ float4 g_s[N_NODES];
__device__ int    g_count[RH];
__device__ int    g_offs[RH + 1];
__device__ int    g_cursor[RH];
__device__ int2   g_edges[E_NUM];
__device__ float4 g_w[E_NUM];
__device__ float4 g_sc[RH];
__device__ float  g_agg[NH][RH][DIN];
__device__ __align__(16) __half g_Ah[(size_t)N_NODES * KPAD];
__device__ __align__(16) __half g_Al[(size_t)N_NODES * KPAD];
__device__ __align__(16) __half g_Bh[400 * KPAD];

// ---------------- helpers ----------------
__device__ __forceinline__ float lrelu(float x) { return x >= 0.f ? x : 0.2f * x; }
__device__ __forceinline__ float elu(float x)   { return x > 0.f ? x : expm1f(x); }

__device__ __forceinline__ float warp_sum(float v) {
    #pragma unroll
    for (int o = 16; o; o >>= 1) v += __shfl_down_sync(0xffffffffu, v, o);
    return v;
}

__device__ __forceinline__ uint32_t smem_u32(const void* p) {
    uint32_t a;
    asm("{ .reg .u64 t; cvta.to.shared.u64 t, %1; cvt.u32.u64 %0, t; }" : "=r"(a) : "l"(p));
    return a;
}

__device__ __forceinline__ uint32_t pack_hf2(float a, float b) {
    __half2 t(__float2half_rn(a), __float2half_rn(b));
    return *(uint32_t*)&t;
}

__device__ __forceinline__ void ldm_x4(uint32_t* r, uint32_t addr) {
    asm volatile("ldmatrix.sync.aligned.m8n8.x4.shared.b16 {%0,%1,%2,%3}, [%4];"
                 : "=r"(r[0]), "=r"(r[1]), "=r"(r[2]), "=r"(r[3]) : "r"(addr));
}
__device__ __forceinline__ void ldm_x2(uint32_t* r, uint32_t addr) {
    asm volatile("ldmatrix.sync.aligned.m8n8.x2.shared.b16 {%0,%1}, [%2];"
                 : "=r"(r[0]), "=r"(r[1]) : "r"(addr));
}
__device__ __forceinline__ void mma16816(float* d, const uint32_t* a, const uint32_t* b) {
    asm volatile("mma.sync.aligned.m16n8k16.row.col.f32.f16.f16.f32 "
                 "{%0,%1,%2,%3}, {%4,%5,%6,%7}, {%8,%9}, {%0,%1,%2,%3};"
                 : "+f"(d[0]), "+f"(d[1]), "+f"(d[2]), "+f"(d[3])
                 : "r"(a[0]), "r"(a[1]), "r"(a[2]), "r"(a[3]), "r"(b[0]), "r"(b[1]));
}
__device__ __forceinline__ void cp16(uint32_t dst, const void* src, bool pred) {
    int sz = pred ? 16 : 0;
    asm volatile("cp.async.cg.shared.global [%0], [%1], 16, %2;"
                 :: "r"(dst), "l"(src), "r"(sz));
}
#define CP_COMMIT() asm volatile("cp.async.commit_group;" ::: "memory")
#define CP_WAIT1()  asm volatile("cp.async.wait_group 1;" ::: "memory")
#define CP_WAIT0()  asm volatile("cp.async.wait_group 0;" ::: "memory")

// ---------------- k_init: uv + zero(count,cursor) ----------------
__global__ void k_init(const float* __restrict__ Wsrc, const float* __restrict__ Wdst,
                       const float* __restrict__ avec) {
    int b = blockIdx.x;
    if (b < 200) {
        int w = b * 8 + (threadIdx.x >> 5);
        int lane = threadIdx.x & 31;
        int side = w / 800;
        int h = (w / 200) % 4;
        int i = w % 200;
        const float* W = (side == 0 ? Wsrc : Wdst) + h * DIN * DIN + i * DIN;
        const float* a = avec + h * 400 + side * 200;
        float acc = 0.f;
        for (int j = lane; j < DIN; j += 32) acc += W[j] * a[j];
        acc = warp_sum(acc);
        if (lane == 0) {
            if (side == 0) g_u[h][i] = acc; else g_v[h][i] = acc;
        }
    } else {
        if (threadIdx.x < RH) {
            g_count[threadIdx.x] = 0;
            g_cursor[threadIdx.x] = 0;
        }
    }
}

// ---------------- k_st: s-scores + t + hist ----------------
__global__ void k_st(const float* __restrict__ emb, const float* __restrict__ rel,
                     const int* __restrict__ etype) {
    __shared__ float4 su4[NH * 50];
    __shared__ int hh[RH];
    int b = blockIdx.x;
    if (b < 5000) {
        for (int i = threadIdx.x; i < NH * 50; i += 256)
            su4[i] = ((const float4*)g_u)[i];
        __syncthreads();
        int n = b * 8 + (threadIdx.x >> 5);
        int l = threadIdx.x & 31;
        const float4* row4 = (const float4*)(emb + (long)n * DIN);
        float4 x = row4[l];
        float4 u0 = su4[0 * 50 + l], u1 = su4[1 * 50 + l];
        float4 u2 = su4[2 * 50 + l], u3 = su4[3 * 50 + l];
        float a0 = x.x * u0.x + x.y * u0.y + x.z * u0.z + x.w * u0.w;
        float a1 = x.x * u1.x + x.y * u1.y + x.z * u1.z + x.w * u1.w;
        float a2 = x.x * u2.x + x.y * u2.y + x.z * u2.z + x.w * u2.w;
        float a3 = x.x * u3.x + x.y * u3.y + x.z * u3.z + x.w * u3.w;
        if (l < 18) {
            float4 y = row4[l + 32];
            float4 v0 = su4[0 * 50 + l + 32], v1 = su4[1 * 50 + l + 32];
            float4 v2 = su4[2 * 50 + l + 32], v3 = su4[3 * 50 + l + 32];
            a0 += y.x * v0.x + y.y * v0.y + y.z * v0.z + y.w * v0.w;
            a1 += y.x * v1.x + y.y * v1.y + y.z * v1.z + y.w * v1.w;
            a2 += y.x * v2.x + y.y * v2.y + y.z * v2.z + y.w * v2.w;
            a3 += y.x * v3.x + y.y * v3.y + y.z * v3.z + y.w * v3.w;
        }
        a0 = warp_sum(a0); a1 = warp_sum(a1); a2 = warp_sum(a2); a3 = warp_sum(a3);
        if (l == 0) g_s[n] = make_float4(a0, a1, a2, a3);
    } else if (b < 5100) {
        int w = (b - 5000) * 8 + (threadIdx.x >> 5);
        int lane = threadIdx.x & 31;
        int h = w / RH;
        int r = w % RH;
        const float* row = rel + (r + (h < 2 ? RH : 0)) * DIN;
        float acc = 0.f;
        for (int j = lane; j < DIN; j += 32) acc += row[j] * g_v[h][j];
        acc = warp_sum(acc);
        if (lane == 0) g_t[h][r] = acc;
    } else {
        for (int i = threadIdx.x; i < RH; i += 256) hh[i] = 0;
        __syncthreads();
        int base = (b - 5100) * 1024;
        for (int i = threadIdx.x; i < 1024; i += 256) {
            int e = base + i;
            if (e < E_NUM) atomicAdd(&hh[etype[e]], 1);
        }
        __syncthreads();
        for (int i = threadIdx.x; i < RH; i += 256)
            if (hh[i]) atomicAdd(&g_count[i], hh[i]);
    }
}

// ---------------- k_cvt: split-fp16 conversion ----------------
__global__ void k_cvt(const float* __restrict__ emb, const float* __restrict__ Wproj) {
    int b = blockIdx.x;
    if (b < 8750) {
        int i = b * 256 + threadIdx.x;
        int n = i / 56;
        int c = (i % 56) * 4;
        float4 x = make_float4(0.f, 0.f, 0.f, 0.f);
        if (c < 200) x = *(const float4*)&emb[(long)n * DIN + c];
        uint2 vh, vl;
        vh.x = pack_hf2(x.x, x.y); vh.y = pack_hf2(x.z, x.w);
        float rx = x.x - __half2float(__float2half_rn(x.x));
        float ry = x.y - __half2float(__float2half_rn(x.y));
        float rz = x.z - __half2float(__float2half_rn(x.z));
        float rw = x.w - __half2float(__float2half_rn(x.w));
        vl.x = pack_hf2(rx, ry); vl.y = pack_hf2(rz, rw);
        *(uint2*)&g_Ah[(long)n * KPAD + c] = vh;
        *(uint2*)&g_Al[(long)n * KPAD + c] = vl;
    } else {
        int n = b - 8750;
        int k = threadIdx.x;
        if (k < KPAD) {
            float x = (k < 200) ? Wproj[k * 400 + n] : 0.f;
            g_Bh[n * KPAD + k] = __float2half_rn(x);
        }
    }
}

// ---------------- k_scatter ----------------
__global__ void k_scatter(const int* __restrict__ el, const int* __restrict__ etype) {
    __shared__ int sc[256];
    __shared__ int hh[RH];
    __shared__ int bb[RH];
    int t = threadIdx.x;
    int c = (t < RH) ? g_count[t] : 0;
    sc[t] = c;
    __syncthreads();
    for (int o = 1; o < 256; o <<= 1) {
        int v = (t >= o) ? sc[t - o] : 0;
        __syncthreads();
        sc[t] += v;
        __syncthreads();
    }
    int offs_t = sc[t] - c;
    if (blockIdx.x == 0 && t < RH) {
        g_offs[t] = offs_t;
        if (t == RH - 1) g_offs[RH] = sc[t];
    }
    if (t < RH) hh[t] = 0;
    __syncthreads();
    int e0 = blockIdx.x * 1024;
    int myrel[4], myrank[4];
    #pragma unroll
    for (int j = 0; j < 4; j++) {
        int e = e0 + t + j * 256;
        if (e < E_NUM) {
            myrel[j] = etype[e];
            myrank[j] = atomicAdd(&hh[myrel[j]], 1);
        } else myrel[j] = -1;
    }
    __syncthreads();
    if (t < RH) {
        int cnt = hh[t];
        if (cnt) bb[t] = offs_t + atomicAdd(&g_cursor[t], cnt);
    }
    __syncthreads();
    #pragma unroll
    for (int j = 0; j < 4; j++) {
        int e = e0 + t + j * 256;
        if (myrel[j] >= 0)
            g_edges[bb[myrel[j]] + myrank[j]] = make_int2(el[e], el[E_NUM + e]);
    }
}

// ---------------- k_w: zero g_agg + softmax stats + per-edge weights ----------------
__global__ void k_w() {
    __shared__ int2   sed[CAP];
    __shared__ float4 s_e[CAP];
    __shared__ float4 red[256];
    int r = blockIdx.x;
    int t = threadIdx.x;
    // zero this relation's agg rows (runs before k_agg in stream order)
    for (int i = t; i < NH * DIN; i += 256) {
        int h = i / DIN, k = i % DIN;
        g_agg[h][r][k] = 0.f;
    }
    int start = g_offs[r], end = g_offs[r + 1];
    int cnt = end - start;
    if (cnt == 0) return;
    float4 tr = make_float4(g_t[0][r], g_t[1][r], g_t[2][r], g_t[3][r]);

    for (int i = t; i < cnt && i < CAP; i += 256) sed[i] = g_edges[start + i];
    __syncthreads();

    float4 mx = make_float4(-1e30f, -1e30f, -1e30f, -1e30f);
    for (int i = t; i < cnt; i += 256) {
        int2 ed = (i < CAP) ? sed[i] : g_edges[start + i];
        float4 ss = g_s[ed.x], st = g_s[ed.y];
        float4 e;
        e.x = lrelu(ss.x + tr.x);
        e.y = lrelu(ss.y + tr.y);
        e.z = lrelu(st.z + tr.z);
        e.w = lrelu(st.w + tr.w);
        if (i < CAP) s_e[i] = e;
        mx.x = fmaxf(mx.x, e.x); mx.y = fmaxf(mx.y, e.y);
        mx.z = fmaxf(mx.z, e.z); mx.w = fmaxf(mx.w, e.w);
    }
    red[t] = mx; __syncthreads();
    for (int s = 128; s > 0; s >>= 1) {
        if (t < s) {
            float4 o = red[t + s];
            red[t].x = fmaxf(red[t].x, o.x); red[t].y = fmaxf(red[t].y, o.y);
            red[t].z = fmaxf(red[t].z, o.z); red[t].w = fmaxf(red[t].w, o.w);
        }
        __syncthreads();
    }
    float4 m = red[0]; __syncthreads();

    float4 sm = make_float4(0.f, 0.f, 0.f, 0.f);
    for (int i = t; i < cnt; i += 256) {
        float4 e;
        if (i < CAP) e = s_e[i];
        else {
            int2 ed = g_edges[start + i];
            float4 ss = g_s[ed.x], st = g_s[ed.y];
            e.x = lrelu(ss.x + tr.x); e.y = lrelu(ss.y + tr.y);
            e.z = lrelu(st.z + tr.z); e.w = lrelu(st.w + tr.w);
        }
        float4 ex;
        ex.x = expf(e.x - m.x); ex.y = expf(e.y - m.y);
        ex.z = expf(e.z - m.z); ex.w = expf(e.w - m.w);
        g_w[start + i] = ex;
        sm.x += ex.x; sm.y += ex.y; sm.z += ex.z; sm.w += ex.w;
    }
    red[t] = sm; __syncthreads();
    for (int s = 128; s > 0; s >>= 1) {
        if (t < s) {
            float4 o = red[t + s];
            red[t].x += o.x; red[t].y += o.y; red[t].z += o.z; red[t].w += o.w;
        }
        __syncthreads();
    }
    if (t == 0) {
        float4 dn = red[0];
        g_sc[r] = make_float4(1.f / (dn.x + 1e-16f), 1.f / (dn.y + 1e-16f),
                              1.f / (dn.z + 1e-16f), 1.f / (dn.w + 1e-16f));
    }
}

// ---------------- k_agg ----------------
__global__ void k_agg(const float* __restrict__ emb) {
    __shared__ int2   sed[SLICE_MAX];
    __shared__ float4 sw[SLICE_MAX];
    int r = blockIdx.x;
    int t = threadIdx.x;
    int start = g_offs[r], end = g_offs[r + 1];
    int cnt = end - start;
    if (cnt == 0) return;
    int chunk = (cnt + SPLIT - 1) / SPLIT;
    int lo = blockIdx.y * chunk;
    int hi = min(lo + chunk, cnt);
    if (lo >= hi) return;
    int len = hi - lo;
    bool fits = (len <= SLICE_MAX);
    if (fits) {
        for (int i = t; i < len; i += 256) {
            sed[i] = g_edges[start + lo + i];
            sw[i]  = g_w[start + lo + i];
        }
        __syncthreads();
    }
    float4 sc = g_sc[r];
    bool act = (t < DIN);
    float a0 = 0.f, a1 = 0.f, a2 = 0.f, a3 = 0.f;
    #pragma unroll 4
    for (int j = 0; j < len; j++) {
        float4 w = fits ? sw[j] : g_w[start + lo + j];
        int2 ed  = fits ? sed[j] : g_edges[start + lo + j];
        if (act) {
            float x = emb[(long)ed.x * DIN + t];
            float y = emb[(long)ed.y * DIN + t];
            a0 += w.x * x; a1 += w.y * x; a2 += w.z * y; a3 += w.w * y;
        }
    }
    if (act) {
        atomicAdd(&g_agg[0][r][t], a0 * sc.x);
        atomicAdd(&g_agg[1][r][t], a1 * sc.y);
        atomicAdd(&g_agg[2][r][t], a2 * sc.z);
        atomicAdd(&g_agg[3][r][t], a3 * sc.w);
    }
}

// ---------------- k_rel: fused relrep + relfinal ----------------
__global__ __launch_bounds__(400) void k_rel(const float* __restrict__ Wsrc,
                                             const float* __restrict__ rel,
                                             const float* __restrict__ wrel,
                                             float* __restrict__ out_rel) {
    __shared__ float sa[8][NH][DIN];
    __shared__ float sin_[8][600];
    int b = blockIdx.x;
    int t = threadIdx.x;
    int r0 = b * 8;
    bool zero = (r0 >= RH);

    if (!zero) {
        for (int i = t; i < 8 * NH * DIN; i += 400) {
            int rr = i / (NH * DIN), rem = i % (NH * DIN);
            sa[rr][rem / DIN][rem % DIN] = g_agg[rem / DIN][r0 + rr][rem % DIN];
        }
        __syncthreads();
        int h = t / DIN, j = t % DIN;
        const float* W1 = Wsrc + h * DIN * DIN + j;
        const float* W2 = Wsrc + (h + 2) * DIN * DIN + j;
        float d1[8], d2[8];
        #pragma unroll
        for (int rr = 0; rr < 8; rr++) { d1[rr] = 0.f; d2[rr] = 0.f; }
        for (int k4 = 0; k4 < DIN; k4 += 4) {
            float w1a = W1[(k4 + 0) * DIN], w1b = W1[(k4 + 1) * DIN];
            float w1c = W1[(k4 + 2) * DIN], w1d = W1[(k4 + 3) * DIN];
            float w2a = W2[(k4 + 0) * DIN], w2b = W2[(k4 + 1) * DIN];
            float w2c = W2[(k4 + 2) * DIN], w2d = W2[(k4 + 3) * DIN];
            #pragma unroll
            for (int rr = 0; rr < 8; rr++) {
                float4 a1v = *(const float4*)&sa[rr][h][k4];
                float4 a2v = *(const float4*)&sa[rr][h + 2][k4];
                d1[rr] += a1v.x * w1a + a1v.y * w1b + a1v.z * w1c + a1v.w * w1d;
                d2[rr] += a2v.x * w2a + a2v.y * w2b + a2v.z * w2c + a2v.w * w2d;
            }
        }
        #pragma unroll
        for (int rr = 0; rr < 8; rr++)
            sin_[rr][t] = elu(d1[rr]) + elu(d2[rr]);
        for (int i = t; i < 8 * DIN; i += 400) {
            int rr = i / DIN, k = i % DIN;
            sin_[rr][400 + k] = rel[(r0 + rr) * DIN + k];
        }
        __syncthreads();
    } else {
        for (int i = t; i < 8 * 400; i += 400) {
            int rr = i / 400, k = i % 400;
            sin_[rr][k] = 0.f;
        }
        for (int i = t; i < 8 * DIN; i += 400) {
            int rr = i / DIN, k = i % DIN;
            sin_[rr][400 + k] = rel[(r0 + rr) * DIN + k];
        }
        __syncthreads();
    }

    float acc[8];
    #pragma unroll
    for (int rr = 0; rr < 8; rr++) acc[rr] = 0.f;
    for (int k4 = 0; k4 < 600; k4 += 4) {
        float wa = wrel[(k4 + 0) * 400 + t];
        float wb = wrel[(k4 + 1) * 400 + t];
        float wc = wrel[(k4 + 2) * 400 + t];
        float wd = wrel[(k4 + 3) * 400 + t];
        #pragma unroll
        for (int rr = 0; rr < 8; rr++) {
            float4 s = *(const float4*)&sin_[rr][k4];
            acc[rr] += s.x * wa + s.y * wb + s.z * wc + s.w * wd;
        }
    }
    #pragma unroll
    for (int rr = 0; rr < 8; rr++)
        out_rel[(r0 + rr) * 400 + t] = acc[rr];
}

// ---------------- k_entmm: cp.async double-buffered split-fp16 HMMA GEMM (2 passes) ----
#define BM 128
#define BN 80
#define KC 32
#define AST 40
#define BST 40
#define A_TILE_B (BM * AST * 2)                 // 10240 bytes
#define B_TILE_B (BN * BST * 2)                 // 6400 bytes
#define STAGE_B  (2 * A_TILE_B + B_TILE_B)      // 26880 bytes
#define NCHUNK   7

__global__ __launch_bounds__(256) void k_entmm(float* __restrict__ C) {
    extern __shared__ __align__(16) unsigned char dynsmem[];
    const int tid = threadIdx.x;
    const int warp = tid >> 5, lane = tid & 31;
    const int wm = warp & 3;
    const int wn = warp >> 2;
    const int bm = blockIdx.y * BM;
    const int bn = blockIdx.x * BN;

    float acc[2][5][4];
    #pragma unroll
    for (int i = 0; i < 2; i++)
        #pragma unroll
        for (int j = 0; j < 5; j++)
            #pragma unroll
            for (int c = 0; c < 4; c++) acc[i][j][c] = 0.f;

    const uint32_t smem0 = smem_u32(dynsmem);
    const int a_row = wm * 32 + (lane & 15);
    const int a_koff = (lane >> 4) * 8;
    const int b_row = wn * 40 + (lane & 7);
    const int b_koff = ((lane >> 3) & 1) * 8;

    auto load_chunk = [&](int kc, int s) {
        uint32_t base = smem0 + s * STAGE_B;
        uint32_t sAh = base;
        uint32_t sAl = base + A_TILE_B;
        uint32_t sBh = base + 2 * A_TILE_B;
        #pragma unroll
        for (int i = 0; i < 2; i++) {
            int idx = tid + i * 256;
            int row = idx >> 2, j = idx & 3;
            int grow = bm + row;
            bool ok = (grow < N_NODES);
            cp16(sAh + (row * AST + j * 8) * 2, g_Ah + (long)grow * KPAD + kc + j * 8, ok);
            cp16(sAl + (row * AST + j * 8) * 2, g_Al + (long)grow * KPAD + kc + j * 8, ok);
        }
        for (int idx = tid; idx < 320; idx += 256) {
            int row = idx >> 2, j = idx & 3;
            cp16(sBh + (row * BST + j * 8) * 2,
                 g_Bh + (long)(bn + row) * KPAD + kc + j * 8, true);
        }
    };

    load_chunk(0, 0);
    CP_COMMIT();

    int cur = 0;
    #pragma unroll 1
    for (int ci = 0; ci < NCHUNK; ci++) {
        if (ci + 1 < NCHUNK) {
            load_chunk((ci + 1) * KC, cur ^ 1);
            CP_COMMIT();
            CP_WAIT1();
        } else {
            CP_WAIT0();
        }
        __syncthreads();

        uint32_t base = smem0 + cur * STAGE_B;
        uint32_t sAh32 = base;
        uint32_t sAl32 = base + A_TILE_B;
        uint32_t sBh32 = base + 2 * A_TILE_B;

        int nks = (ci == NCHUNK - 1) ? 1 : 2;
        for (int ks = 0; ks < nks; ks++) {
            int k0 = ks * 16;
            uint32_t afh[2][4], afl[2][4], bfh[5][2];
            #pragma unroll
            for (int mf = 0; mf < 2; mf++) {
                ldm_x4(afh[mf], sAh32 + ((a_row + mf * 16) * AST + k0 + a_koff) * 2);
                ldm_x4(afl[mf], sAl32 + ((a_row + mf * 16) * AST + k0 + a_koff) * 2);
            }
            #pragma unroll
            for (int nf = 0; nf < 5; nf++)
                ldm_x2(bfh[nf], sBh32 + ((b_row + nf * 8) * BST + k0 + b_koff) * 2);
            #pragma unroll
            for (int mf = 0; mf < 2; mf++)
                #pragma unroll
                for (int nf = 0; nf < 5; nf++) {
                    mma16816(acc[mf][nf], afh[mf], bfh[nf]);
                    mma16816(acc[mf][nf], afl[mf], bfh[nf]);
                }
        }
        __syncthreads();
        cur ^= 1;
    }

    const int m_base = bm + wm * 32 + (lane >> 2);
    const int n_base = bn + wn * 40 + (lane & 3) * 2;
    #pragma unroll
    for (int mf = 0; mf < 2; mf++) {
        #pragma unroll
        for (int nf = 0; nf < 5; nf++) {
            int n = n_base + nf * 8;
            int m0 = m_base + mf * 16;
            if (m0 < N_NODES)
                *(float2*)&C[(long)m0 * 400 + n] = make_float2(acc[mf][nf][0], acc[mf][nf][1]);
            if (m0 + 8 < N_NODES)
                *(float2*)&C[(long)(m0 + 8) * 400 + n] = make_float2(acc[mf][nf][2], acc[mf][nf][3]);
        }
    }
}

// ---------------- launch ----------------
extern "C" void kernel_launch(void* const* d_in, const int* in_sizes, int n_in,
                              void* d_out, int out_size) {
    const int*   el    = (const int*)d_in[0];
    const int*   et    = (const int*)d_in[1];
    const float* emb   = (const float*)d_in[2];
    const float* rel   = (const float*)d_in[3];
    const float* Wsrc  = (const float*)d_in[4];
    const float* Wdst  = (const float*)d_in[5];
    const float* avec  = (const float*)d_in[6];
    const float* wrel  = (const float*)d_in[7];
    const float* Wproj = (const float*)d_in[8];
    float* out     = (float*)d_out;
    float* out_ent = out;
    float* out_rel = out + (long)N_NODES * 400;

    static bool attr_done = false;
    if (!attr_done) {
        cudaFuncSetAttribute(k_entmm, cudaFuncAttributeMaxDynamicSharedMemorySize,
                             2 * STAGE_B);
        attr_done = true;
    }

    cudaStream_t s2;
    cudaEvent_t ev_fork, ev_join;
    cudaStreamCreateWithFlags(&s2, cudaStreamNonBlocking);
    cudaEventCreateWithFlags(&ev_fork, cudaEventDisableTiming);
    cudaEventCreateWithFlags(&ev_join, cudaEventDisableTiming);

    cudaEventRecord(ev_fork, 0);
    cudaStreamWaitEvent(s2, ev_fork, 0);

    // edge chain (main stream)
    k_init<<<201, 256>>>(Wsrc, Wdst, avec);
    k_st<<<5198, 256>>>(emb, rel, et);

    // GEMM chain (side stream); entmm stays 4th launch for ncu
    k_cvt<<<9150, 256, 0, s2>>>(emb, Wproj);
    k_entmm<<<dim3(5, 313), 256, 2 * STAGE_B, s2>>>(out_ent);
    cudaEventRecord(ev_join, s2);

    k_scatter<<<98, 256>>>(el, et);
    k_w<<<RH, 256>>>();
    k_agg<<<dim3(RH, SPLIT), 256>>>(emb);
    k_rel<<<50, 400>>>(Wsrc, rel, wrel, out_rel);

    cudaStreamWaitEvent(0, ev_join, 0);
}

// round 14
// speedup vs baseline: 1.6208x; 1.0388x over previous
#include <cuda_runtime.h>
#include <cuda_fp16.h>
#include <cstdint>

#define E_NUM   100000
#define N_NODES 40000
#define R_NUM   400
#define RH      200
#define DIN     200
#define NH      4
#define CAP     1024
#define SPLIT   8
#define SLICE_MAX 256
#define KPAD    224

// ---------------- device scratch ----------------
__device__ float  g_u[NH][DIN];
__device__ float  g_v[NH][DIN];
__device__ float  g_t[NH][RH];
__device__ float4 g_s[N_NODES];
__device__ int    g_count[RH];
__device__ int    g_offs[RH + 1];
__device__ int    g_cursor[RH];
__device__ int2   g_edges[E_NUM];
__device__ float4 g_w[E_NUM];
__device__ float4 g_sc[RH];
__device__ float  g_agg[NH][RH][DIN];
__device__ __align__(16) __half g_Ah[(size_t)N_NODES * KPAD];
__device__ __align__(16) __half g_Al[(size_t)N_NODES * KPAD];
__device__ __align__(16) __half g_Bh[400 * KPAD];

// ---------------- helpers ----------------
__device__ __forceinline__ float lrelu(float x) { return x >= 0.f ? x : 0.2f * x; }
__device__ __forceinline__ float elu(float x)   { return x > 0.f ? x : expm1f(x); }

__device__ __forceinline__ float warp_sum(float v) {
    #pragma unroll
    for (int o = 16; o; o >>= 1) v += __shfl_down_sync(0xffffffffu, v, o);
    return v;
}

__device__ __forceinline__ uint32_t smem_u32(const void* p) {
    uint32_t a;
    asm("{ .reg .u64 t; cvta.to.shared.u64 t, %1; cvt.u32.u64 %0, t; }" : "=r"(a) : "l"(p));
    return a;
}

__device__ __forceinline__ uint32_t pack_hf2(float a, float b) {
    __half2 t(__float2half_rn(a), __float2half_rn(b));
    return *(uint32_t*)&t;
}

__device__ __forceinline__ void ldm_x4(uint32_t* r, uint32_t addr) {
    asm volatile("ldmatrix.sync.aligned.m8n8.x4.shared.b16 {%0,%1,%2,%3}, [%4];"
                 : "=r"(r[0]), "=r"(r[1]), "=r"(r[2]), "=r"(r[3]) : "r"(addr));
}
__device__ __forceinline__ void ldm_x2(uint32_t* r, uint32_t addr) {
    asm volatile("ldmatrix.sync.aligned.m8n8.x2.shared.b16 {%0,%1}, [%2];"
                 : "=r"(r[0]), "=r"(r[1]) : "r"(addr));
}
__device__ __forceinline__ void mma16816(float* d, const uint32_t* a, const uint32_t* b) {
    asm volatile("mma.sync.aligned.m16n8k16.row.col.f32.f16.f16.f32 "
                 "{%0,%1,%2,%3}, {%4,%5,%6,%7}, {%8,%9}, {%0,%1,%2,%3};"
                 : "+f"(d[0]), "+f"(d[1]), "+f"(d[2]), "+f"(d[3])
                 : "r"(a[0]), "r"(a[1]), "r"(a[2]), "r"(a[3]), "r"(b[0]), "r"(b[1]));
}
__device__ __forceinline__ void cp16(uint32_t dst, const void* src, bool pred) {
    int sz = pred ? 16 : 0;
    asm volatile("cp.async.cg.shared.global [%0], [%1], 16, %2;"
                 :: "r"(dst), "l"(src), "r"(sz));
}
#define CP_COMMIT() asm volatile("cp.async.commit_group;" ::: "memory")
#define CP_WAIT1()  asm volatile("cp.async.wait_group 1;" ::: "memory")
#define CP_WAIT0()  asm volatile("cp.async.wait_group 0;" ::: "memory")

// ---------------- k_init: uv + zero(count,cursor) ----------------
__global__ void k_init(const float* __restrict__ Wsrc, const float* __restrict__ Wdst,
                       const float* __restrict__ avec) {
    int b = blockIdx.x;
    if (b < 200) {
        int w = b * 8 + (threadIdx.x >> 5);
        int lane = threadIdx.x & 31;
        int side = w / 800;
        int h = (w / 200) % 4;
        int i = w % 200;
        const float* W = (side == 0 ? Wsrc : Wdst) + h * DIN * DIN + i * DIN;
        const float* a = avec + h * 400 + side * 200;
        float acc = 0.f;
        for (int j = lane; j < DIN; j += 32) acc += W[j] * a[j];
        acc = warp_sum(acc);
        if (lane == 0) {
            if (side == 0) g_u[h][i] = acc; else g_v[h][i] = acc;
        }
    } else {
        if (threadIdx.x < RH) {
            g_count[threadIdx.x] = 0;
            g_cursor[threadIdx.x] = 0;
        }
    }
}

// ---------------- k_stcvt: s-scores + fp16 cvtA (one emb read) + t + hist + cvtB ----
// blocks [0,5000): s+cvtA ; [5000,5100): t ; [5100,5198): hist ; [5198,5598): cvtB
__global__ void k_stcvt(const float* __restrict__ emb, const float* __restrict__ rel,
                        const int* __restrict__ etype, const float* __restrict__ Wproj) {
    __shared__ float4 su4[NH * 50];
    __shared__ int hh[RH];
    int b = blockIdx.x;
    if (b < 5000) {
        for (int i = threadIdx.x; i < NH * 50; i += 256)
            su4[i] = ((const float4*)g_u)[i];
        __syncthreads();
        int n = b * 8 + (threadIdx.x >> 5);
        int l = threadIdx.x & 31;
        const float4* row4 = (const float4*)(emb + (long)n * DIN);
        float4 x = row4[l];
        float4 u0 = su4[0 * 50 + l], u1 = su4[1 * 50 + l];
        float4 u2 = su4[2 * 50 + l], u3 = su4[3 * 50 + l];
        float a0 = x.x * u0.x + x.y * u0.y + x.z * u0.z + x.w * u0.w;
        float a1 = x.x * u1.x + x.y * u1.y + x.z * u1.z + x.w * u1.w;
        float a2 = x.x * u2.x + x.y * u2.y + x.z * u2.z + x.w * u2.w;
        float a3 = x.x * u3.x + x.y * u3.y + x.z * u3.z + x.w * u3.w;
        {
            uint2 vh, vl;
            vh.x = pack_hf2(x.x, x.y); vh.y = pack_hf2(x.z, x.w);
            float rx = x.x - __half2float(__float2half_rn(x.x));
            float ry = x.y - __half2float(__float2half_rn(x.y));
            float rz = x.z - __half2float(__float2half_rn(x.z));
            float rw = x.w - __half2float(__float2half_rn(x.w));
            vl.x = pack_hf2(rx, ry); vl.y = pack_hf2(rz, rw);
            *(uint2*)&g_Ah[(long)n * KPAD + 4 * l] = vh;
            *(uint2*)&g_Al[(long)n * KPAD + 4 * l] = vl;
        }
        if (l < 18) {
            float4 y = row4[l + 32];
            float4 v0 = su4[0 * 50 + l + 32], v1 = su4[1 * 50 + l + 32];
            float4 v2 = su4[2 * 50 + l + 32], v3 = su4[3 * 50 + l + 32];
            a0 += y.x * v0.x + y.y * v0.y + y.z * v0.z + y.w * v0.w;
            a1 += y.x * v1.x + y.y * v1.y + y.z * v1.z + y.w * v1.w;
            a2 += y.x * v2.x + y.y * v2.y + y.z * v2.z + y.w * v2.w;
            a3 += y.x * v3.x + y.y * v3.y + y.z * v3.z + y.w * v3.w;
            uint2 vh, vl;
            vh.x = pack_hf2(y.x, y.y); vh.y = pack_hf2(y.z, y.w);
            float rx = y.x - __half2float(__float2half_rn(y.x));
            float ry = y.y - __half2float(__float2half_rn(y.y));
            float rz = y.z - __half2float(__float2half_rn(y.z));
            float rw = y.w - __half2float(__float2half_rn(y.w));
            vl.x = pack_hf2(rx, ry); vl.y = pack_hf2(rz, rw);
            *(uint2*)&g_Ah[(long)n * KPAD + 128 + 4 * l] = vh;
            *(uint2*)&g_Al[(long)n * KPAD + 128 + 4 * l] = vl;
        } else if (l < 24) {
            uint2 z = make_uint2(0u, 0u);
            *(uint2*)&g_Ah[(long)n * KPAD + 128 + 4 * l] = z;
            *(uint2*)&g_Al[(long)n * KPAD + 128 + 4 * l] = z;
        }
        a0 = warp_sum(a0); a1 = warp_sum(a1); a2 = warp_sum(a2); a3 = warp_sum(a3);
        if (l == 0) g_s[n] = make_float4(a0, a1, a2, a3);
    } else if (b < 5100) {
        int w = (b - 5000) * 8 + (threadIdx.x >> 5);
        int lane = threadIdx.x & 31;
        int h = w / RH;
        int r = w % RH;
        const float* row = rel + (r + (h < 2 ? RH : 0)) * DIN;
        float acc = 0.f;
        for (int j = lane; j < DIN; j += 32) acc += row[j] * g_v[h][j];
        acc = warp_sum(acc);
        if (lane == 0) g_t[h][r] = acc;
    } else if (b < 5198) {
        for (int i = threadIdx.x; i < RH; i += 256) hh[i] = 0;
        __syncthreads();
        int base = (b - 5100) * 1024;
        for (int i = threadIdx.x; i < 1024; i += 256) {
            int e = base + i;
            if (e < E_NUM) atomicAdd(&hh[etype[e]], 1);
        }
        __syncthreads();
        for (int i = threadIdx.x; i < RH; i += 256)
            if (hh[i]) atomicAdd(&g_count[i], hh[i]);
    } else {
        int n = b - 5198;
        int k = threadIdx.x;
        if (k < KPAD) {
            float x = (k < 200) ? Wproj[k * 400 + n] : 0.f;
            g_Bh[n * KPAD + k] = __float2half_rn(x);
        }
    }
}

// ---------------- k_scatter ----------------
__global__ void k_scatter(const int* __restrict__ el, const int* __restrict__ etype) {
    __shared__ int sc[256];
    __shared__ int hh[RH];
    __shared__ int bb[RH];
    int t = threadIdx.x;
    int c = (t < RH) ? g_count[t] : 0;
    sc[t] = c;
    __syncthreads();
    for (int o = 1; o < 256; o <<= 1) {
        int v = (t >= o) ? sc[t - o] : 0;
        __syncthreads();
        sc[t] += v;
        __syncthreads();
    }
    int offs_t = sc[t] - c;
    if (blockIdx.x == 0 && t < RH) {
        g_offs[t] = offs_t;
        if (t == RH - 1) g_offs[RH] = sc[t];
    }
    if (t < RH) hh[t] = 0;
    __syncthreads();
    int e0 = blockIdx.x * 1024;
    int myrel[4], myrank[4];
    #pragma unroll
    for (int j = 0; j < 4; j++) {
        int e = e0 + t + j * 256;
        if (e < E_NUM) {
            myrel[j] = etype[e];
            myrank[j] = atomicAdd(&hh[myrel[j]], 1);
        } else myrel[j] = -1;
    }
    __syncthreads();
    if (t < RH) {
        int cnt = hh[t];
        if (cnt) bb[t] = offs_t + atomicAdd(&g_cursor[t], cnt);
    }
    __syncthreads();
    #pragma unroll
    for (int j = 0; j < 4; j++) {
        int e = e0 + t + j * 256;
        if (myrel[j] >= 0)
            g_edges[bb[myrel[j]] + myrank[j]] = make_int2(el[e], el[E_NUM + e]);
    }
}

// ---------------- k_w: zero g_agg + softmax stats + per-edge weights ----------------
__global__ void k_w() {
    __shared__ int2   sed[CAP];
    __shared__ float4 s_e[CAP];
    __shared__ float4 red[256];
    int r = blockIdx.x;
    int t = threadIdx.x;
    for (int i = t; i < NH * DIN; i += 256) {
        int h = i / DIN, k = i % DIN;
        g_agg[h][r][k] = 0.f;
    }
    int start = g_offs[r], end = g_offs[r + 1];
    int cnt = end - start;
    if (cnt == 0) return;
    float4 tr = make_float4(g_t[0][r], g_t[1][r], g_t[2][r], g_t[3][r]);

    for (int i = t; i < cnt && i < CAP; i += 256) sed[i] = g_edges[start + i];
    __syncthreads();

    float4 mx = make_float4(-1e30f, -1e30f, -1e30f, -1e30f);
    for (int i = t; i < cnt; i += 256) {
        int2 ed = (i < CAP) ? sed[i] : g_edges[start + i];
        float4 ss = g_s[ed.x], st = g_s[ed.y];
        float4 e;
        e.x = lrelu(ss.x + tr.x);
        e.y = lrelu(ss.y + tr.y);
        e.z = lrelu(st.z + tr.z);
        e.w = lrelu(st.w + tr.w);
        if (i < CAP) s_e[i] = e;
        mx.x = fmaxf(mx.x, e.x); mx.y = fmaxf(mx.y, e.y);
        mx.z = fmaxf(mx.z, e.z); mx.w = fmaxf(mx.w, e.w);
    }
    red[t] = mx; __syncthreads();
    for (int s = 128; s > 0; s >>= 1) {
        if (t < s) {
            float4 o = red[t + s];
            red[t].x = fmaxf(red[t].x, o.x); red[t].y = fmaxf(red[t].y, o.y);
            red[t].z = fmaxf(red[t].z, o.z); red[t].w = fmaxf(red[t].w, o.w);
        }
        __syncthreads();
    }
    float4 m = red[0]; __syncthreads();

    float4 sm = make_float4(0.f, 0.f, 0.f, 0.f);
    for (int i = t; i < cnt; i += 256) {
        float4 e;
        if (i < CAP) e = s_e[i];
        else {
            int2 ed = g_edges[start + i];
            float4 ss = g_s[ed.x], st = g_s[ed.y];
            e.x = lrelu(ss.x + tr.x); e.y = lrelu(ss.y + tr.y);
            e.z = lrelu(st.z + tr.z); e.w = lrelu(st.w + tr.w);
        }
        float4 ex;
        ex.x = expf(e.x - m.x); ex.y = expf(e.y - m.y);
        ex.z = expf(e.z - m.z); ex.w = expf(e.w - m.w);
        g_w[start + i] = ex;
        sm.x += ex.x; sm.y += ex.y; sm.z += ex.z; sm.w += ex.w;
    }
    red[t] = sm; __syncthreads();
    for (int s = 128; s > 0; s >>= 1) {
        if (t < s) {
            float4 o = red[t + s];
            red[t].x += o.x; red[t].y += o.y; red[t].z += o.z; red[t].w += o.w;
        }
        __syncthreads();
    }
    if (t == 0) {
        float4 dn = red[0];
        g_sc[r] = make_float4(1.f / (dn.x + 1e-16f), 1.f / (dn.y + 1e-16f),
                              1.f / (dn.z + 1e-16f), 1.f / (dn.w + 1e-16f));
    }
}

// ---------------- k_agg: fp16 gather (half the traffic), 128 threads, dim-pairs ----
__global__ __launch_bounds__(128) void k_agg() {
    __shared__ int2   sed[SLICE_MAX];
    __shared__ float4 sw[SLICE_MAX];
    int r = blockIdx.x;
    int t = threadIdx.x;      // 0..127; t<100 active (dim pair 2t, 2t+1)
    int start = g_offs[r], end = g_offs[r + 1];
    int cnt = end - start;
    if (cnt == 0) return;
    int chunk = (cnt + SPLIT - 1) / SPLIT;
    int lo = blockIdx.y * chunk;
    int hi = min(lo + chunk, cnt);
    if (lo >= hi) return;
    int len = hi - lo;
    bool fits = (len <= SLICE_MAX);
    if (fits) {
        for (int i = t; i < len; i += 128) {
            sed[i] = g_edges[start + lo + i];
            sw[i]  = g_w[start + lo + i];
        }
        __syncthreads();
    }
    float4 sc = g_sc[r];
    bool act = (t < 100);
    float2 A0 = make_float2(0.f, 0.f), A1 = A0, A2 = A0, A3 = A0;
    #pragma unroll 4
    for (int j = 0; j < len; j++) {
        float4 w = fits ? sw[j] : g_w[start + lo + j];
        int2 ed  = fits ? sed[j] : g_edges[start + lo + j];
        if (act) {
            __half2 hx = *(const __half2*)&g_Ah[(long)ed.x * KPAD + 2 * t];
            __half2 hy = *(const __half2*)&g_Ah[(long)ed.y * KPAD + 2 * t];
            float2 x = __half22float2(hx);
            float2 y = __half22float2(hy);
            A0.x += w.x * x.x; A0.y += w.x * x.y;
            A1.x += w.y * x.x; A1.y += w.y * x.y;
            A2.x += w.z * y.x; A2.y += w.z * y.y;
            A3.x += w.w * y.x; A3.y += w.w * y.y;
        }
    }
    if (act) {
        int d = 2 * t;
        atomicAdd(&g_agg[0][r][d],     A0.x * sc.x);
        atomicAdd(&g_agg[0][r][d + 1], A0.y * sc.x);
        atomicAdd(&g_agg[1][r][d],     A1.x * sc.y);
        atomicAdd(&g_agg[1][r][d + 1], A1.y * sc.y);
        atomicAdd(&g_agg[2][r][d],     A2.x * sc.z);
        atomicAdd(&g_agg[2][r][d + 1], A2.y * sc.z);
        atomicAdd(&g_agg[3][r][d],     A3.x * sc.w);
        atomicAdd(&g_agg[3][r][d + 1], A3.y * sc.w);
    }
}

// ---------------- k_rel: fused relrep + relfinal ----------------
__global__ __launch_bounds__(400) void k_rel(const float* __restrict__ Wsrc,
                                             const float* __restrict__ rel,
                                             const float* __restrict__ wrel,
                                             float* __restrict__ out_rel) {
    __shared__ float sa[8][NH][DIN];
    __shared__ float sin_[8][600];
    int b = blockIdx.x;
    int t = threadIdx.x;
    int r0 = b * 8;
    bool zero = (r0 >= RH);

    if (!zero) {
        for (int i = t; i < 8 * NH * DIN; i += 400) {
            int rr = i / (NH * DIN), rem = i % (NH * DIN);
            sa[rr][rem / DIN][rem % DIN] = g_agg[rem / DIN][r0 + rr][rem % DIN];
        }
        __syncthreads();
        int h = t / DIN, j = t % DIN;
        const float* W1 = Wsrc + h * DIN * DIN + j;
        const float* W2 = Wsrc + (h + 2) * DIN * DIN + j;
        float d1[8], d2[8];
        #pragma unroll
        for (int rr = 0; rr < 8; rr++) { d1[rr] = 0.f; d2[rr] = 0.f; }
        for (int k4 = 0; k4 < DIN; k4 += 4) {
            float w1a = W1[(k4 + 0) * DIN], w1b = W1[(k4 + 1) * DIN];
            float w1c = W1[(k4 + 2) * DIN], w1d = W1[(k4 + 3) * DIN];
            float w2a = W2[(k4 + 0) * DIN], w2b = W2[(k4 + 1) * DIN];
            float w2c = W2[(k4 + 2) * DIN], w2d = W2[(k4 + 3) * DIN];
            #pragma unroll
            for (int rr = 0; rr < 8; rr++) {
                float4 a1v = *(const float4*)&sa[rr][h][k4];
                float4 a2v = *(const float4*)&sa[rr][h + 2][k4];
                d1[rr] += a1v.x * w1a + a1v.y * w1b + a1v.z * w1c + a1v.w * w1d;
                d2[rr] += a2v.x * w2a + a2v.y * w2b + a2v.z * w2c + a2v.w * w2d;
            }
        }
        #pragma unroll
        for (int rr = 0; rr < 8; rr++)
            sin_[rr][t] = elu(d1[rr]) + elu(d2[rr]);
        for (int i = t; i < 8 * DIN; i += 400) {
            int rr = i / DIN, k = i % DIN;
            sin_[rr][400 + k] = rel[(r0 + rr) * DIN + k];
        }
        __syncthreads();
    } else {
        for (int i = t; i < 8 * 400; i += 400) {
            int rr = i / 400, k = i % 400;
            sin_[rr][k] = 0.f;
        }
        for (int i = t; i < 8 * DIN; i += 400) {
            int rr = i / DIN, k = i % DIN;
            sin_[rr][400 + k] = rel[(r0 + rr) * DIN + k];
        }
        __syncthreads();
    }

    float acc[8];
    #pragma unroll
    for (int rr = 0; rr < 8; rr++) acc[rr] = 0.f;
    for (int k4 = 0; k4 < 600; k4 += 4) {
        float wa = wrel[(k4 + 0) * 400 + t];
        float wb = wrel[(k4 + 1) * 400 + t];
        float wc = wrel[(k4 + 2) * 400 + t];
        float wd = wrel[(k4 + 3) * 400 + t];
        #pragma unroll
        for (int rr = 0; rr < 8; rr++) {
            float4 s = *(const float4*)&sin_[rr][k4];
            acc[rr] += s.x * wa + s.y * wb + s.z * wc + s.w * wd;
        }
    }
    #pragma unroll
    for (int rr = 0; rr < 8; rr++)
        out_rel[(r0 + rr) * 400 + t] = acc[rr];
}

// ---------------- k_entmm: cp.async double-buffered split-fp16 HMMA GEMM ----------------
#define BM 128
#define BN 80
#define KC 32
#define AST 40
#define BST 40
#define A_TILE_B (BM * AST * 2)
#define B_TILE_B (BN * BST * 2)
#define STAGE_B  (2 * A_TILE_B + B_TILE_B)
#define NCHUNK   7

__global__ __launch_bounds__(256) void k_entmm(float* __restrict__ C) {
    extern __shared__ __align__(16) unsigned char dynsmem[];
    const int tid = threadIdx.x;
    const int warp = tid >> 5, lane = tid & 31;
    const int wm = warp & 3;
    const int wn = warp >> 2;
    const int bm = blockIdx.y * BM;
    const int bn = blockIdx.x * BN;

    float acc[2][5][4];
    #pragma unroll
    for (int i = 0; i < 2; i++)
        #pragma unroll
        for (int j = 0; j < 5; j++)
            #pragma unroll
            for (int c = 0; c < 4; c++) acc[i][j][c] = 0.f;

    const uint32_t smem0 = smem_u32(dynsmem);
    const int a_row = wm * 32 + (lane & 15);
    const int a_koff = (lane >> 4) * 8;
    const int b_row = wn * 40 + (lane & 7);
    const int b_koff = ((lane >> 3) & 1) * 8;

    auto load_chunk = [&](int kc, int s) {
        uint32_t base = smem0 + s * STAGE_B;
        uint32_t sAh = base;
        uint32_t sAl = base + A_TILE_B;
        uint32_t sBh = base + 2 * A_TILE_B;
        #pragma unroll
        for (int i = 0; i < 2; i++) {
            int idx = tid + i * 256;
            int row = idx >> 2, j = idx & 3;
            int grow = bm + row;
            bool ok = (grow < N_NODES);
            cp16(sAh + (row * AST + j * 8) * 2, g_Ah + (long)grow * KPAD + kc + j * 8, ok);
            cp16(sAl + (row * AST + j * 8) * 2, g_Al + (long)grow * KPAD + kc + j * 8, ok);
        }
        for (int idx = tid; idx < 320; idx += 256) {
            int row = idx >> 2, j = idx & 3;
            cp16(sBh + (row * BST + j * 8) * 2,
                 g_Bh + (long)(bn + row) * KPAD + kc + j * 8, true);
        }
    };

    load_chunk(0, 0);
    CP_COMMIT();

    int cur = 0;
    #pragma unroll 1
    for (int ci = 0; ci < NCHUNK; ci++) {
        if (ci + 1 < NCHUNK) {
            load_chunk((ci + 1) * KC, cur ^ 1);
            CP_COMMIT();
            CP_WAIT1();
        } else {
            CP_WAIT0();
        }
        __syncthreads();

        uint32_t base = smem0 + cur * STAGE_B;
        uint32_t sAh32 = base;
        uint32_t sAl32 = base + A_TILE_B;
        uint32_t sBh32 = base + 2 * A_TILE_B;

        int nks = (ci == NCHUNK - 1) ? 1 : 2;
        for (int ks = 0; ks < nks; ks++) {
            int k0 = ks * 16;
            uint32_t afh[2][4], afl[2][4], bfh[5][2];
            #pragma unroll
            for (int mf = 0; mf < 2; mf++) {
                ldm_x4(afh[mf], sAh32 + ((a_row + mf * 16) * AST + k0 + a_koff) * 2);
                ldm_x4(afl[mf], sAl32 + ((a_row + mf * 16) * AST + k0 + a_koff) * 2);
            }
            #pragma unroll
            for (int nf = 0; nf < 5; nf++)
                ldm_x2(bfh[nf], sBh32 + ((b_row + nf * 8) * BST + k0 + b_koff) * 2);
            #pragma unroll
            for (int mf = 0; mf < 2; mf++)
                #pragma unroll
                for (int nf = 0; nf < 5; nf++) {
                    mma16816(acc[mf][nf], afh[mf], bfh[nf]);
                    mma16816(acc[mf][nf], afl[mf], bfh[nf]);
                }
        }
        __syncthreads();
        cur ^= 1;
    }

    const int m_base = bm + wm * 32 + (lane >> 2);
    const int n_base = bn + wn * 40 + (lane & 3) * 2;
    #pragma unroll
    for (int mf = 0; mf < 2; mf++) {
        #pragma unroll
        for (int nf = 0; nf < 5; nf++) {
            int n = n_base + nf * 8;
            int m0 = m_base + mf * 16;
            if (m0 < N_NODES)
                *(float2*)&C[(long)m0 * 400 + n] = make_float2(acc[mf][nf][0], acc[mf][nf][1]);
            if (m0 + 8 < N_NODES)
                *(float2*)&C[(long)(m0 + 8) * 400 + n] = make_float2(acc[mf][nf][2], acc[mf][nf][3]);
        }
    }
}

// ---------------- launch ----------------
extern "C" void kernel_launch(void* const* d_in, const int* in_sizes, int n_in,
                              void* d_out, int out_size) {
    const int*   el    = (const int*)d_in[0];
    const int*   et    = (const int*)d_in[1];
    const float* emb   = (const float*)d_in[2];
    const float* rel   = (const float*)d_in[3];
    const float* Wsrc  = (const float*)d_in[4];
    const float* Wdst  = (const float*)d_in[5];
    const float* avec  = (const float*)d_in[6];
    const float* wrel  = (const float*)d_in[7];
    const float* Wproj = (const float*)d_in[8];
    float* out     = (float*)d_out;
    float* out_ent = out;
    float* out_rel = out + (long)N_NODES * 400;

    static bool attr_done = false;
    if (!attr_done) {
        cudaFuncSetAttribute(k_entmm, cudaFuncAttributeMaxDynamicSharedMemorySize,
                             2 * STAGE_B);
        attr_done = true;
    }

    cudaStream_t s2;
    cudaEvent_t ev_fork, ev_join;
    cudaStreamCreateWithFlags(&s2, cudaStreamNonBlocking);
    cudaEventCreateWithFlags(&ev_fork, cudaEventDisableTiming);
    cudaEventCreateWithFlags(&ev_join, cudaEventDisableTiming);

    // edge chain (main stream); k_w is the 4th enqueued launch -> profiled
    k_init<<<201, 256>>>(Wsrc, Wdst, avec);
    k_stcvt<<<5598, 256>>>(emb, rel, et, Wproj);
    cudaEventRecord(ev_fork, 0);               // g_Ah/g_Al/g_Bh ready after k_stcvt
    k_scatter<<<98, 256>>>(el, et);
    k_w<<<RH, 256>>>();
    k_agg<<<dim3(RH, SPLIT), 128>>>();
    k_rel<<<50, 400>>>(Wsrc, rel, wrel, out_rel);

    // GEMM chain on side stream (overlaps tail of edge chain)
    cudaStreamWaitEvent(s2, ev_fork, 0);
    k_entmm<<<dim3(5, 313), 256, 2 * STAGE_B, s2>>>(out_ent);
    cudaEventRecord(ev_join, s2);
    cudaStreamWaitEvent(0, ev_join, 0);
}

// round 15
// speedup vs baseline: 1.8839x; 1.1623x over previous
#include <cuda_runtime.h>
#include <cuda_fp16.h>
#include <cstdint>

#define E_NUM   100000
#define N_NODES 40000
#define R_NUM   400
#define RH      200
#define DIN     200
#define NH      4
#define CAP     1024
#define SPLIT   16
#define SLICE_MAX 256
#define KPAD    224

// ---------------- device scratch ----------------
__device__ float  g_u[NH][DIN];
__device__ float  g_v[NH][DIN];
__device__ float  g_t[NH][RH];
__device__ float4 g_s[N_NODES];
__device__ int    g_count[RH];
__device__ int    g_offs[RH + 1];
__device__ int    g_cursor[RH];
__device__ int2   g_edges[E_NUM];
__device__ float4 g_w[E_NUM];
__device__ float4 g_sc[RH];
__device__ float  g_agg[NH][RH][DIN];
__device__ __align__(16) __half g_Ah[(size_t)N_NODES * KPAD];
__device__ __align__(16) __half g_Bh[400 * KPAD];

// ---------------- helpers ----------------
__device__ __forceinline__ float lrelu(float x) { return x >= 0.f ? x : 0.2f * x; }
__device__ __forceinline__ float elu(float x)   { return x > 0.f ? x : expm1f(x); }

__device__ __forceinline__ float warp_sum(float v) {
    #pragma unroll
    for (int o = 16; o; o >>= 1) v += __shfl_down_sync(0xffffffffu, v, o);
    return v;
}

__device__ __forceinline__ uint32_t smem_u32(const void* p) {
    uint32_t a;
    asm("{ .reg .u64 t; cvta.to.shared.u64 t, %1; cvt.u32.u64 %0, t; }" : "=r"(a) : "l"(p));
    return a;
}

__device__ __forceinline__ uint32_t pack_hf2(float a, float b) {
    __half2 t(__float2half_rn(a), __float2half_rn(b));
    return *(uint32_t*)&t;
}

__device__ __forceinline__ void ldm_x4(uint32_t* r, uint32_t addr) {
    asm volatile("ldmatrix.sync.aligned.m8n8.x4.shared.b16 {%0,%1,%2,%3}, [%4];"
                 : "=r"(r[0]), "=r"(r[1]), "=r"(r[2]), "=r"(r[3]) : "r"(addr));
}
__device__ __forceinline__ void ldm_x2(uint32_t* r, uint32_t addr) {
    asm volatile("ldmatrix.sync.aligned.m8n8.x2.shared.b16 {%0,%1}, [%2];"
                 : "=r"(r[0]), "=r"(r[1]) : "r"(addr));
}
__device__ __forceinline__ void mma16816(float* d, const uint32_t* a, const uint32_t* b) {
    asm volatile("mma.sync.aligned.m16n8k16.row.col.f32.f16.f16.f32 "
                 "{%0,%1,%2,%3}, {%4,%5,%6,%7}, {%8,%9}, {%0,%1,%2,%3};"
                 : "+f"(d[0]), "+f"(d[1]), "+f"(d[2]), "+f"(d[3])
                 : "r"(a[0]), "r"(a[1]), "r"(a[2]), "r"(a[3]), "r"(b[0]), "r"(b[1]));
}
__device__ __forceinline__ void cp16(uint32_t dst, const void* src, bool pred) {
    int sz = pred ? 16 : 0;
    asm volatile("cp.async.cg.shared.global [%0], [%1], 16, %2;"
                 :: "r"(dst), "l"(src), "r"(sz));
}
#define CP_COMMIT() asm volatile("cp.async.commit_group;" ::: "memory")
#define CP_WAIT1()  asm volatile("cp.async.wait_group 1;" ::: "memory")
#define CP_WAIT0()  asm volatile("cp.async.wait_group 0;" ::: "memory")

// ---------------- k_init: uv + zero(count,cursor) ----------------
__global__ void k_init(const float* __restrict__ Wsrc, const float* __restrict__ Wdst,
                       const float* __restrict__ avec) {
    int b = blockIdx.x;
    if (b < 200) {
        int w = b * 8 + (threadIdx.x >> 5);
        int lane = threadIdx.x & 31;
        int side = w / 800;
        int h = (w / 200) % 4;
        int i = w % 200;
        const float* W = (side == 0 ? Wsrc : Wdst) + h * DIN * DIN + i * DIN;
        const float* a = avec + h * 400 + side * 200;
        float acc = 0.f;
        for (int j = lane; j < DIN; j += 32) acc += W[j] * a[j];
        acc = warp_sum(acc);
        if (lane == 0) {
            if (side == 0) g_u[h][i] = acc; else g_v[h][i] = acc;
        }
    } else {
        if (threadIdx.x < RH) {
            g_count[threadIdx.x] = 0;
            g_cursor[threadIdx.x] = 0;
        }
    }
}

// ---------------- k_stcvt: s-scores + fp16 cvtA (one emb read) + t + hist + cvtB ----
__global__ void k_stcvt(const float* __restrict__ emb, const float* __restrict__ rel,
                        const int* __restrict__ etype, const float* __restrict__ Wproj) {
    __shared__ float4 su4[NH * 50];
    __shared__ int hh[RH];
    int b = blockIdx.x;
    if (b < 5000) {
        for (int i = threadIdx.x; i < NH * 50; i += 256)
            su4[i] = ((const float4*)g_u)[i];
        __syncthreads();
        int n = b * 8 + (threadIdx.x >> 5);
        int l = threadIdx.x & 31;
        const float4* row4 = (const float4*)(emb + (long)n * DIN);
        float4 x = row4[l];
        float4 u0 = su4[0 * 50 + l], u1 = su4[1 * 50 + l];
        float4 u2 = su4[2 * 50 + l], u3 = su4[3 * 50 + l];
        float a0 = x.x * u0.x + x.y * u0.y + x.z * u0.z + x.w * u0.w;
        float a1 = x.x * u1.x + x.y * u1.y + x.z * u1.z + x.w * u1.w;
        float a2 = x.x * u2.x + x.y * u2.y + x.z * u2.z + x.w * u2.w;
        float a3 = x.x * u3.x + x.y * u3.y + x.z * u3.z + x.w * u3.w;
        {
            uint2 vh;
            vh.x = pack_hf2(x.x, x.y); vh.y = pack_hf2(x.z, x.w);
            *(uint2*)&g_Ah[(long)n * KPAD + 4 * l] = vh;
        }
        if (l < 18) {
            float4 y = row4[l + 32];
            float4 v0 = su4[0 * 50 + l + 32], v1 = su4[1 * 50 + l + 32];
            float4 v2 = su4[2 * 50 + l + 32], v3 = su4[3 * 50 + l + 32];
            a0 += y.x * v0.x + y.y * v0.y + y.z * v0.z + y.w * v0.w;
            a1 += y.x * v1.x + y.y * v1.y + y.z * v1.z + y.w * v1.w;
            a2 += y.x * v2.x + y.y * v2.y + y.z * v2.z + y.w * v2.w;
            a3 += y.x * v3.x + y.y * v3.y + y.z * v3.z + y.w * v3.w;
            uint2 vh;
            vh.x = pack_hf2(y.x, y.y); vh.y = pack_hf2(y.z, y.w);
            *(uint2*)&g_Ah[(long)n * KPAD + 128 + 4 * l] = vh;
        } else if (l < 24) {
            uint2 z = make_uint2(0u, 0u);
            *(uint2*)&g_Ah[(long)n * KPAD + 128 + 4 * l] = z;
        }
        a0 = warp_sum(a0); a1 = warp_sum(a1); a2 = warp_sum(a2); a3 = warp_sum(a3);
        if (l == 0) g_s[n] = make_float4(a0, a1, a2, a3);
    } else if (b < 5100) {
        int w = (b - 5000) * 8 + (threadIdx.x >> 5);
        int lane = threadIdx.x & 31;
        int h = w / RH;
        int r = w % RH;
        const float* row = rel + (r + (h < 2 ? RH : 0)) * DIN;
        float acc = 0.f;
        for (int j = lane; j < DIN; j += 32) acc += row[j] * g_v[h][j];
        acc = warp_sum(acc);
        if (lane == 0) g_t[h][r] = acc;
    } else if (b < 5198) {
        for (int i = threadIdx.x; i < RH; i += 256) hh[i] = 0;
        __syncthreads();
        int base = (b - 5100) * 1024;
        for (int i = threadIdx.x; i < 1024; i += 256) {
            int e = base + i;
            if (e < E_NUM) atomicAdd(&hh[etype[e]], 1);
        }
        __syncthreads();
        for (int i = threadIdx.x; i < RH; i += 256)
            if (hh[i]) atomicAdd(&g_count[i], hh[i]);
    } else {
        int n = b - 5198;
        int k = threadIdx.x;
        if (k < KPAD) {
            float x = (k < 200) ? Wproj[k * 400 + n] : 0.f;
            g_Bh[n * KPAD + k] = __float2half_rn(x);
        }
    }
}

// ---------------- k_scatter ----------------
__global__ void k_scatter(const int* __restrict__ el, const int* __restrict__ etype) {
    __shared__ int sc[256];
    __shared__ int hh[RH];
    __shared__ int bb[RH];
    int t = threadIdx.x;
    int c = (t < RH) ? g_count[t] : 0;
    sc[t] = c;
    __syncthreads();
    for (int o = 1; o < 256; o <<= 1) {
        int v = (t >= o) ? sc[t - o] : 0;
        __syncthreads();
        sc[t] += v;
        __syncthreads();
    }
    int offs_t = sc[t] - c;
    if (blockIdx.x == 0 && t < RH) {
        g_offs[t] = offs_t;
        if (t == RH - 1) g_offs[RH] = sc[t];
    }
    if (t < RH) hh[t] = 0;
    __syncthreads();
    int e0 = blockIdx.x * 1024;
    int myrel[4], myrank[4];
    #pragma unroll
    for (int j = 0; j < 4; j++) {
        int e = e0 + t + j * 256;
        if (e < E_NUM) {
            myrel[j] = etype[e];
            myrank[j] = atomicAdd(&hh[myrel[j]], 1);
        } else myrel[j] = -1;
    }
    __syncthreads();
    if (t < RH) {
        int cnt = hh[t];
        if (cnt) bb[t] = offs_t + atomicAdd(&g_cursor[t], cnt);
    }
    __syncthreads();
    #pragma unroll
    for (int j = 0; j < 4; j++) {
        int e = e0 + t + j * 256;
        if (myrel[j] >= 0)
            g_edges[bb[myrel[j]] + myrank[j]] = make_int2(el[e], el[E_NUM + e]);
    }
}

// ---------------- k_w: zero g_agg + softmax stats + per-edge weights ----------------
__global__ void k_w() {
    __shared__ int2   sed[CAP];
    __shared__ float4 s_e[CAP];
    __shared__ float4 red[256];
    int r = blockIdx.x;
    int t = threadIdx.x;
    for (int i = t; i < NH * DIN; i += 256) {
        int h = i / DIN, k = i % DIN;
        g_agg[h][r][k] = 0.f;
    }
    int start = g_offs[r], end = g_offs[r + 1];
    int cnt = end - start;
    if (cnt == 0) return;
    float4 tr = make_float4(g_t[0][r], g_t[1][r], g_t[2][r], g_t[3][r]);

    for (int i = t; i < cnt && i < CAP; i += 256) sed[i] = g_edges[start + i];
    __syncthreads();

    float4 mx = make_float4(-1e30f, -1e30f, -1e30f, -1e30f);
    for (int i = t; i < cnt; i += 256) {
        int2 ed = (i < CAP) ? sed[i] : g_edges[start + i];
        float4 ss = g_s[ed.x], st = g_s[ed.y];
        float4 e;
        e.x = lrelu(ss.x + tr.x);
        e.y = lrelu(ss.y + tr.y);
        e.z = lrelu(st.z + tr.z);
        e.w = lrelu(st.w + tr.w);
        if (i < CAP) s_e[i] = e;
        mx.x = fmaxf(mx.x, e.x); mx.y = fmaxf(mx.y, e.y);
        mx.z = fmaxf(mx.z, e.z); mx.w = fmaxf(mx.w, e.w);
    }
    red[t] = mx; __syncthreads();
    for (int s = 128; s > 0; s >>= 1) {
        if (t < s) {
            float4 o = red[t + s];
            red[t].x = fmaxf(red[t].x, o.x); red[t].y = fmaxf(red[t].y, o.y);
            red[t].z = fmaxf(red[t].z, o.z); red[t].w = fmaxf(red[t].w, o.w);
        }
        __syncthreads();
    }
    float4 m = red[0]; __syncthreads();

    float4 sm = make_float4(0.f, 0.f, 0.f, 0.f);
    for (int i = t; i < cnt; i += 256) {
        float4 e;
        if (i < CAP) e = s_e[i];
        else {
            int2 ed = g_edges[start + i];
            float4 ss = g_s[ed.x], st = g_s[ed.y];
            e.x = lrelu(ss.x + tr.x); e.y = lrelu(ss.y + tr.y);
            e.z = lrelu(st.z + tr.z); e.w = lrelu(st.w + tr.w);
        }
        float4 ex;
        ex.x = expf(e.x - m.x); ex.y = expf(e.y - m.y);
        ex.z = expf(e.z - m.z); ex.w = expf(e.w - m.w);
        g_w[start + i] = ex;
        sm.x += ex.x; sm.y += ex.y; sm.z += ex.z; sm.w += ex.w;
    }
    red[t] = sm; __syncthreads();
    for (int s = 128; s > 0; s >>= 1) {
        if (t < s) {
            float4 o = red[t + s];
            red[t].x += o.x; red[t].y += o.y; red[t].z += o.z; red[t].w += o.w;
        }
        __syncthreads();
    }
    if (t == 0) {
        float4 dn = red[0];
        g_sc[r] = make_float4(1.f / (dn.x + 1e-16f), 1.f / (dn.y + 1e-16f),
                              1.f / (dn.z + 1e-16f), 1.f / (dn.w + 1e-16f));
    }
}

// ---------------- k_agg: fp16 gather, 128 threads, dim-pairs, SPLIT=16 ----------------
__global__ __launch_bounds__(128) void k_agg() {
    __shared__ int2   sed[SLICE_MAX];
    __shared__ float4 sw[SLICE_MAX];
    int r = blockIdx.x;
    int t = threadIdx.x;
    int start = g_offs[r], end = g_offs[r + 1];
    int cnt = end - start;
    if (cnt == 0) return;
    int chunk = (cnt + SPLIT - 1) / SPLIT;
    int lo = blockIdx.y * chunk;
    int hi = min(lo + chunk, cnt);
    if (lo >= hi) return;
    int len = hi - lo;
    bool fits = (len <= SLICE_MAX);
    if (fits) {
        for (int i = t; i < len; i += 128) {
            sed[i] = g_edges[start + lo + i];
            sw[i]  = g_w[start + lo + i];
        }
        __syncthreads();
    }
    float4 sc = g_sc[r];
    bool act = (t < 100);
    float2 A0 = make_float2(0.f, 0.f), A1 = A0, A2 = A0, A3 = A0;
    #pragma unroll 4
    for (int j = 0; j < len; j++) {
        float4 w = fits ? sw[j] : g_w[start + lo + j];
        int2 ed  = fits ? sed[j] : g_edges[start + lo + j];
        if (act) {
            __half2 hx = *(const __half2*)&g_Ah[(long)ed.x * KPAD + 2 * t];
            __half2 hy = *(const __half2*)&g_Ah[(long)ed.y * KPAD + 2 * t];
            float2 x = __half22float2(hx);
            float2 y = __half22float2(hy);
            A0.x += w.x * x.x; A0.y += w.x * x.y;
            A1.x += w.y * x.x; A1.y += w.y * x.y;
            A2.x += w.z * y.x; A2.y += w.z * y.y;
            A3.x += w.w * y.x; A3.y += w.w * y.y;
        }
    }
    if (act) {
        int d = 2 * t;
        atomicAdd(&g_agg[0][r][d],     A0.x * sc.x);
        atomicAdd(&g_agg[0][r][d + 1], A0.y * sc.x);
        atomicAdd(&g_agg[1][r][d],     A1.x * sc.y);
        atomicAdd(&g_agg[1][r][d + 1], A1.y * sc.y);
        atomicAdd(&g_agg[2][r][d],     A2.x * sc.z);
        atomicAdd(&g_agg[2][r][d + 1], A2.y * sc.z);
        atomicAdd(&g_agg[3][r][d],     A3.x * sc.w);
        atomicAdd(&g_agg[3][r][d + 1], A3.y * sc.w);
    }
}

// ---------------- k_rel: fused relrep + relfinal ----------------
__global__ __launch_bounds__(400) void k_rel(const float* __restrict__ Wsrc,
                                             const float* __restrict__ rel,
                                             const float* __restrict__ wrel,
                                             float* __restrict__ out_rel) {
    __shared__ float sa[8][NH][DIN];
    __shared__ float sin_[8][600];
    int b = blockIdx.x;
    int t = threadIdx.x;
    int r0 = b * 8;
    bool zero = (r0 >= RH);

    if (!zero) {
        for (int i = t; i < 8 * NH * DIN; i += 400) {
            int rr = i / (NH * DIN), rem = i % (NH * DIN);
            sa[rr][rem / DIN][rem % DIN] = g_agg[rem / DIN][r0 + rr][rem % DIN];
        }
        __syncthreads();
        int h = t / DIN, j = t % DIN;
        const float* W1 = Wsrc + h * DIN * DIN + j;
        const float* W2 = Wsrc + (h + 2) * DIN * DIN + j;
        float d1[8], d2[8];
        #pragma unroll
        for (int rr = 0; rr < 8; rr++) { d1[rr] = 0.f; d2[rr] = 0.f; }
        for (int k4 = 0; k4 < DIN; k4 += 4) {
            float w1a = W1[(k4 + 0) * DIN], w1b = W1[(k4 + 1) * DIN];
            float w1c = W1[(k4 + 2) * DIN], w1d = W1[(k4 + 3) * DIN];
            float w2a = W2[(k4 + 0) * DIN], w2b = W2[(k4 + 1) * DIN];
            float w2c = W2[(k4 + 2) * DIN], w2d = W2[(k4 + 3) * DIN];
            #pragma unroll
            for (int rr = 0; rr < 8; rr++) {
                float4 a1v = *(const float4*)&sa[rr][h][k4];
                float4 a2v = *(const float4*)&sa[rr][h + 2][k4];
                d1[rr] += a1v.x * w1a + a1v.y * w1b + a1v.z * w1c + a1v.w * w1d;
                d2[rr] += a2v.x * w2a + a2v.y * w2b + a2v.z * w2c + a2v.w * w2d;
            }
        }
        #pragma unroll
        for (int rr = 0; rr < 8; rr++)
            sin_[rr][t] = elu(d1[rr]) + elu(d2[rr]);
        for (int i = t; i < 8 * DIN; i += 400) {
            int rr = i / DIN, k = i % DIN;
            sin_[rr][400 + k] = rel[(r0 + rr) * DIN + k];
        }
        __syncthreads();
    } else {
        for (int i = t; i < 8 * 400; i += 400) {
            int rr = i / 400, k = i % 400;
            sin_[rr][k] = 0.f;
        }
        for (int i = t; i < 8 * DIN; i += 400) {
            int rr = i / DIN, k = i % DIN;
            sin_[rr][400 + k] = rel[(r0 + rr) * DIN + k];
        }
        __syncthreads();
    }

    float acc[8];
    #pragma unroll
    for (int rr = 0; rr < 8; rr++) acc[rr] = 0.f;
    for (int k4 = 0; k4 < 600; k4 += 4) {
        float wa = wrel[(k4 + 0) * 400 + t];
        float wb = wrel[(k4 + 1) * 400 + t];
        float wc = wrel[(k4 + 2) * 400 + t];
        float wd = wrel[(k4 + 3) * 400 + t];
        #pragma unroll
        for (int rr = 0; rr < 8; rr++) {
            float4 s = *(const float4*)&sin_[rr][k4];
            acc[rr] += s.x * wa + s.y * wb + s.z * wc + s.w * wd;
        }
    }
    #pragma unroll
    for (int rr = 0; rr < 8; rr++)
        out_rel[(r0 + rr) * 400 + t] = acc[rr];
}

// ---------------- k_entmm: cp.async double-buffered plain-fp16 HMMA GEMM ----------------
#define BM 128
#define BN 80
#define KC 32
#define AST 40
#define BST 40
#define A_TILE_B (BM * AST * 2)                 // 10240 bytes
#define B_TILE_B (BN * BST * 2)                 // 6400 bytes
#define STAGE_B  (A_TILE_B + B_TILE_B)          // 16640 bytes
#define NCHUNK   7

__global__ __launch_bounds__(256) void k_entmm(float* __restrict__ C) {
    __shared__ __align__(16) unsigned char smbuf[2 * STAGE_B];   // 33280 B, static
    const int tid = threadIdx.x;
    const int warp = tid >> 5, lane = tid & 31;
    const int wm = warp & 3;
    const int wn = warp >> 2;
    const int bm = blockIdx.y * BM;
    const int bn = blockIdx.x * BN;

    float acc[2][5][4];
    #pragma unroll
    for (int i = 0; i < 2; i++)
        #pragma unroll
        for (int j = 0; j < 5; j++)
            #pragma unroll
            for (int c = 0; c < 4; c++) acc[i][j][c] = 0.f;

    const uint32_t smem0 = smem_u32(smbuf);
    const int a_row = wm * 32 + (lane & 15);
    const int a_koff = (lane >> 4) * 8;
    const int b_row = wn * 40 + (lane & 7);
    const int b_koff = ((lane >> 3) & 1) * 8;

    auto load_chunk = [&](int kc, int s) {
        uint32_t base = smem0 + s * STAGE_B;
        uint32_t sAh = base;
        uint32_t sBh = base + A_TILE_B;
        #pragma unroll
        for (int i = 0; i < 2; i++) {
            int idx = tid + i * 256;
            int row = idx >> 2, j = idx & 3;
            int grow = bm + row;
            cp16(sAh + (row * AST + j * 8) * 2, g_Ah + (long)grow * KPAD + kc + j * 8,
                 grow < N_NODES);
        }
        for (int idx = tid; idx < 320; idx += 256) {
            int row = idx >> 2, j = idx & 3;
            cp16(sBh + (row * BST + j * 8) * 2,
                 g_Bh + (long)(bn + row) * KPAD + kc + j * 8, true);
        }
    };

    load_chunk(0, 0);
    CP_COMMIT();

    int cur = 0;
    #pragma unroll 1
    for (int ci = 0; ci < NCHUNK; ci++) {
        if (ci + 1 < NCHUNK) {
            load_chunk((ci + 1) * KC, cur ^ 1);
            CP_COMMIT();
            CP_WAIT1();
        } else {
            CP_WAIT0();
        }
        __syncthreads();

        uint32_t base = smem0 + cur * STAGE_B;
        uint32_t sAh32 = base;
        uint32_t sBh32 = base + A_TILE_B;

        int nks = (ci == NCHUNK - 1) ? 1 : 2;
        for (int ks = 0; ks < nks; ks++) {
            int k0 = ks * 16;
            uint32_t afh[2][4], bfh[5][2];
            #pragma unroll
            for (int mf = 0; mf < 2; mf++)
                ldm_x4(afh[mf], sAh32 + ((a_row + mf * 16) * AST + k0 + a_koff) * 2);
            #pragma unroll
            for (int nf = 0; nf < 5; nf++)
                ldm_x2(bfh[nf], sBh32 + ((b_row + nf * 8) * BST + k0 + b_koff) * 2);
            #pragma unroll
            for (int mf = 0; mf < 2; mf++)
                #pragma unroll
                for (int nf = 0; nf < 5; nf++)
                    mma16816(acc[mf][nf], afh[mf], bfh[nf]);
        }
        __syncthreads();
        cur ^= 1;
    }

    const int m_base = bm + wm * 32 + (lane >> 2);
    const int n_base = bn + wn * 40 + (lane & 3) * 2;
    #pragma unroll
    for (int mf = 0; mf < 2; mf++) {
        #pragma unroll
        for (int nf = 0; nf < 5; nf++) {
            int n = n_base + nf * 8;
            int m0 = m_base + mf * 16;
            if (m0 < N_NODES)
                *(float2*)&C[(long)m0 * 400 + n] = make_float2(acc[mf][nf][0], acc[mf][nf][1]);
            if (m0 + 8 < N_NODES)
                *(float2*)&C[(long)(m0 + 8) * 400 + n] = make_float2(acc[mf][nf][2], acc[mf][nf][3]);
        }
    }
}

// ---------------- launch ----------------
extern "C" void kernel_launch(void* const* d_in, const int* in_sizes, int n_in,
                              void* d_out, int out_size) {
    const int*   el    = (const int*)d_in[0];
    const int*   et    = (const int*)d_in[1];
    const float* emb   = (const float*)d_in[2];
    const float* rel   = (const float*)d_in[3];
    const float* Wsrc  = (const float*)d_in[4];
    const float* Wdst  = (const float*)d_in[5];
    const float* avec  = (const float*)d_in[6];
    const float* wrel  = (const float*)d_in[7];
    const float* Wproj = (const float*)d_in[8];
    float* out     = (float*)d_out;
    float* out_ent = out;
    float* out_rel = out + (long)N_NODES * 400;

    cudaStream_t s2;
    cudaEvent_t ev_fork, ev_join;
    cudaStreamCreateWithFlags(&s2, cudaStreamNonBlocking);
    cudaEventCreateWithFlags(&ev_fork, cudaEventDisableTiming);
    cudaEventCreateWithFlags(&ev_join, cudaEventDisableTiming);

    // edge chain (main stream); k_w stays 4th enqueued launch
    k_init<<<201, 256>>>(Wsrc, Wdst, avec);
    k_stcvt<<<5598, 256>>>(emb, rel, et, Wproj);
    cudaEventRecord(ev_fork, 0);               // g_Ah/g_Bh ready after k_stcvt
    k_scatter<<<98, 256>>>(el, et);
    k_w<<<RH, 256>>>();
    k_agg<<<dim3(RH, SPLIT), 128>>>();
    k_rel<<<50, 400>>>(Wsrc, rel, wrel, out_rel);

    // GEMM chain on side stream (overlaps tail of edge chain)
    cudaStreamWaitEvent(s2, ev_fork, 0);
    k_entmm<<<dim3(5, 313), 256, 0, s2>>>(out_ent);
    cudaEventRecord(ev_join, s2);
    cudaStreamWaitEvent(0, ev_join, 0);
}